// round 3
// baseline (speedup 1.0000x reference)
#include <cuda_runtime.h>
#include <cuda_bf16.h>
#include <math.h>

// ---------------------------------------------------------------------------
// Problem constants
// ---------------------------------------------------------------------------
#define T_TOK   8192
#define HID     2048
#define NH      16
#define HD      128
#define INNER   2048          // NH*HD
#define QKV_W   6144          // 3*INNER
#define NCHUNK  64            // T/128
#define CHUNK   128
#define EPS     1e-5f
#define QSCALE  0.08838834764831845f   // 128^-0.5

// ---------------------------------------------------------------------------
// Device scratch (static globals: allocation-free rule)
// ---------------------------------------------------------------------------
__device__ float g_qkv [T_TOK * QKV_W];            // 192 MiB: silu(x@Wqkv), q/k rope'd in place
__device__ float g_gate[T_TOK * INNER];            // 64 MiB: x@Wg, then overwritten with gated value
__device__ float g_o   [T_TOK * INNER];            // 64 MiB: attention output
__device__ float g_kvp [NCHUNK * NH * HD * HD];    // 64 MiB: per-chunk KV outer products
__device__ float g_S   [NCHUNK * NH * HD * HD];    // 64 MiB: exclusive prefix state per chunk

// ---------------------------------------------------------------------------
// Generic fp32 SGEMM: C[M,N] = act(A[M,K] @ B[K,N])
// 128x128 block tile, BK=16, 256 threads, 8x8 microtile, prefetched
// ACT: 0 = none, 1 = silu
// ---------------------------------------------------------------------------
template<int ACT>
__global__ __launch_bounds__(256, 2)
void sgemm128(const float* __restrict__ A, const float* __restrict__ B,
              float* __restrict__ C, int M, int N, int K)
{
    __shared__ float As[16][128];   // transposed: As[k][m]
    __shared__ float Bs[16][128];   // natural:    Bs[k][n]

    const int bm = blockIdx.y * 128;
    const int bn = blockIdx.x * 128;
    const int tid = threadIdx.x;
    const int tx = tid & 15;        // 0..15 -> N microtile
    const int ty = tid >> 4;        // 0..15 -> M microtile

    // A tile loader: 128 rows x 16 cols, each thread 2 float4
    const int a_row = tid >> 2;            // 0..63 (and +64)
    const int a_col = (tid & 3) << 2;      // 0,4,8,12
    // B tile loader: 16 rows x 128 cols, each thread 2 float4
    const int b_row = tid >> 5;            // 0..7 (and +8)
    const int b_col = (tid & 31) << 2;

    const float* Ap = A + (long)(bm + a_row) * K + a_col;
    const float* Ap2 = Ap + (long)64 * K;
    const float* Bp = B + (long)b_row * N + bn + b_col;
    const float* Bp2 = Bp + (long)8 * N;

    float4 a0 = *(const float4*)(Ap);
    float4 a1 = *(const float4*)(Ap2);
    float4 b0 = *(const float4*)(Bp);
    float4 b1 = *(const float4*)(Bp2);

    float acc[8][8];
    #pragma unroll
    for (int i = 0; i < 8; i++)
        #pragma unroll
        for (int j = 0; j < 8; j++) acc[i][j] = 0.f;

    for (int k0 = 0; k0 < K; k0 += 16) {
        // store staged tile
        As[a_col+0][a_row]    = a0.x; As[a_col+1][a_row]    = a0.y;
        As[a_col+2][a_row]    = a0.z; As[a_col+3][a_row]    = a0.w;
        As[a_col+0][a_row+64] = a1.x; As[a_col+1][a_row+64] = a1.y;
        As[a_col+2][a_row+64] = a1.z; As[a_col+3][a_row+64] = a1.w;
        *(float4*)&Bs[b_row][b_col]   = b0;
        *(float4*)&Bs[b_row+8][b_col] = b1;
        __syncthreads();

        // prefetch next tile while computing this one
        if (k0 + 16 < K) {
            a0 = *(const float4*)(Ap  + k0 + 16);
            a1 = *(const float4*)(Ap2 + k0 + 16);
            b0 = *(const float4*)(Bp  + (long)(k0 + 16) * N);
            b1 = *(const float4*)(Bp2 + (long)(k0 + 16) * N);
        }

        #pragma unroll
        for (int kk = 0; kk < 16; kk++) {
            float a[8], b[8];
            *(float4*)&a[0] = *(const float4*)&As[kk][ty*8];
            *(float4*)&a[4] = *(const float4*)&As[kk][ty*8+4];
            *(float4*)&b[0] = *(const float4*)&Bs[kk][tx*8];
            *(float4*)&b[4] = *(const float4*)&Bs[kk][tx*8+4];
            #pragma unroll
            for (int i = 0; i < 8; i++)
                #pragma unroll
                for (int j = 0; j < 8; j++)
                    acc[i][j] += a[i] * b[j];
        }
        __syncthreads();
    }

    // epilogue
    #pragma unroll
    for (int i = 0; i < 8; i++) {
        float* Cp = C + (long)(bm + ty*8 + i) * N + bn + tx*8;
        float4 r0, r1;
        float v[8];
        #pragma unroll
        for (int j = 0; j < 8; j++) {
            float x = acc[i][j];
            if (ACT == 1) x = x / (1.f + expf(-x));   // silu
            v[j] = x;
        }
        r0.x = v[0]; r0.y = v[1]; r0.z = v[2]; r0.w = v[3];
        r1.x = v[4]; r1.y = v[5]; r1.z = v[6]; r1.w = v[7];
        *(float4*)(Cp)     = r0;
        *(float4*)(Cp + 4) = r1;
    }
}

// ---------------------------------------------------------------------------
// Per-(token, head) RMSNorm + RoPE (+ q scale), in place on g_qkv
// grid(T, H), 64 threads; thread j handles dims j and j+64 (rope pair)
// ---------------------------------------------------------------------------
__global__ void qk_rope_kernel(float* __restrict__ qkv,
                               const int* __restrict__ pos,
                               const float* __restrict__ qw,
                               const float* __restrict__ kw)
{
    const int t = blockIdx.x, h = blockIdx.y;
    const int j = threadIdx.x;              // 0..63
    float* qp = qkv + (long)t * QKV_W + h * HD;
    float* kp = qp + INNER;

    float q1 = qp[j], q2 = qp[j + 64];
    float k1 = kp[j], k2 = kp[j + 64];

    float sq = q1*q1 + q2*q2;
    float sk = k1*k1 + k2*k2;
    #pragma unroll
    for (int o = 16; o; o >>= 1) {
        sq += __shfl_xor_sync(0xffffffffu, sq, o);
        sk += __shfl_xor_sync(0xffffffffu, sk, o);
    }
    __shared__ float red[4];
    const int w = j >> 5, lane = j & 31;
    if (lane == 0) { red[w] = sq; red[2 + w] = sk; }
    __syncthreads();
    const float rq = rsqrtf((red[0] + red[1]) * (1.f / 128.f) + EPS);
    const float rk = rsqrtf((red[2] + red[3]) * (1.f / 128.f) + EPS);

    q1 = q1 * rq * qw[j]; q2 = q2 * rq * qw[j + 64];
    k1 = k1 * rk * kw[j]; k2 = k2 * rk * kw[j + 64];

    const float inv = powf(600000.0f, -(float)j * (1.0f / 64.0f));
    const float ang = (float)pos[t] * inv;
    float s, c;
    sincosf(ang, &s, &c);

    qp[j]      = (q1 * c - q2 * s) * QSCALE;
    qp[j + 64] = (q2 * c + q1 * s) * QSCALE;
    kp[j]      =  k1 * c - k2 * s;
    kp[j + 64] =  k2 * c + k1 * s;
}

// ---------------------------------------------------------------------------
// Per-(chunk, head) KV outer product: KV[d][e] = sum_j k[j][d] * v[j][e]
// grid(NCHUNK, NH), 256 threads, dyn smem = 2 * 64KB
// ---------------------------------------------------------------------------
__global__ __launch_bounds__(256, 1)
void kv_outer_kernel(const float* __restrict__ qkv, float* __restrict__ KV)
{
    extern __shared__ float sm[];
    float* sK = sm;            // [j][d]
    float* sV = sm + 16384;    // [j][e]

    const int c = blockIdx.x, h = blockIdx.y;
    const int t0 = c * CHUNK;
    const int tid = threadIdx.x, tx = tid & 15, ty = tid >> 4;

    const float* kg = qkv + (long)t0 * QKV_W + h * HD + INNER;
    const float* vg = kg + INNER;

    #pragma unroll
    for (int r = 0; r < 16; r++) {
        int idx = r * 256 + tid;            // 0..4095
        int row = idx >> 5;
        int col = (idx & 31) << 2;
        *(float4*)&sK[row * 128 + col] = *(const float4*)(kg + (long)row * QKV_W + col);
        *(float4*)&sV[row * 128 + col] = *(const float4*)(vg + (long)row * QKV_W + col);
    }
    __syncthreads();

    float acc[8][8];
    #pragma unroll
    for (int i = 0; i < 8; i++)
        #pragma unroll
        for (int j = 0; j < 8; j++) acc[i][j] = 0.f;

    for (int j = 0; j < 128; j++) {
        float a[8], b[8];
        *(float4*)&a[0] = *(const float4*)&sK[j * 128 + ty*8];
        *(float4*)&a[4] = *(const float4*)&sK[j * 128 + ty*8 + 4];
        *(float4*)&b[0] = *(const float4*)&sV[j * 128 + tx*8];
        *(float4*)&b[4] = *(const float4*)&sV[j * 128 + tx*8 + 4];
        #pragma unroll
        for (int i = 0; i < 8; i++)
            #pragma unroll
            for (int e = 0; e < 8; e++)
                acc[i][e] += a[i] * b[e];
    }

    float* out = KV + ((long)c * NH + h) * (HD * HD);
    #pragma unroll
    for (int i = 0; i < 8; i++) {
        float4 r0 = make_float4(acc[i][0], acc[i][1], acc[i][2], acc[i][3]);
        float4 r1 = make_float4(acc[i][4], acc[i][5], acc[i][6], acc[i][7]);
        *(float4*)&out[(ty*8 + i) * 128 + tx*8]     = r0;
        *(float4*)&out[(ty*8 + i) * 128 + tx*8 + 4] = r1;
    }
}

// ---------------------------------------------------------------------------
// Exclusive prefix over chunks: S[c] = sum_{j<c} KV[j]   (per h,d,e element)
// ---------------------------------------------------------------------------
__global__ void prefix_kernel(const float* __restrict__ KV, float* __restrict__ S)
{
    const int idx = blockIdx.x * 256 + threadIdx.x;   // 0 .. 262143 (h*16384 + d*128 + e)
    float acc = 0.f;
    #pragma unroll 4
    for (int c = 0; c < NCHUNK; c++) {
        S[(long)c * (NH * HD * HD) + idx] = acc;
        acc += KV[(long)c * (NH * HD * HD) + idx];
    }
}

// ---------------------------------------------------------------------------
// Per-(chunk, head) attention:
//   scT[j][i] = (i>=j) ? sum_d q[i][d] k[j][d] : 0
//   o[i][e]   = sum_j scT[j][i] v[j][e]  +  sum_d q[i][d] S[d][e]
// grid(NCHUNK, NH), 256 threads, dyn smem = 3 * 64KB
// ---------------------------------------------------------------------------
__global__ __launch_bounds__(256, 1)
void attn_chunk_kernel(const float* __restrict__ qkv, const float* __restrict__ S,
                       float* __restrict__ O)
{
    extern __shared__ float sm[];
    float* sQ = sm;             // qT [d][i]
    float* sB = sm + 16384;     // kT [d][j], then v [j][e]
    float* sC = sm + 32768;     // scoresT [j][i], then S [d][e]

    const int c = blockIdx.x, h = blockIdx.y;
    const int t0 = c * CHUNK;
    const int tid = threadIdx.x, tx = tid & 15, ty = tid >> 4;

    const float* qg = qkv + (long)t0 * QKV_W + h * HD;
    const float* kg = qg + INNER;
    const float* vg = qg + 2 * INNER;

    // load qT, kT (transpose on store)
    #pragma unroll
    for (int r = 0; r < 16; r++) {
        int idx = r * 256 + tid;
        int i  = idx >> 5;
        int dd = (idx & 31) << 2;
        float4 q4 = *(const float4*)(qg + (long)i * QKV_W + dd);
        float4 k4 = *(const float4*)(kg + (long)i * QKV_W + dd);
        sQ[(dd+0)*128 + i] = q4.x; sQ[(dd+1)*128 + i] = q4.y;
        sQ[(dd+2)*128 + i] = q4.z; sQ[(dd+3)*128 + i] = q4.w;
        sB[(dd+0)*128 + i] = k4.x; sB[(dd+1)*128 + i] = k4.y;
        sB[(dd+2)*128 + i] = k4.z; sB[(dd+3)*128 + i] = k4.w;
    }
    __syncthreads();

    // GEMM1: scT[j][i] with causal mask (keep i >= j)
    {
        float acc[8][8];
        #pragma unroll
        for (int a = 0; a < 8; a++)
            #pragma unroll
            for (int b = 0; b < 8; b++) acc[a][b] = 0.f;

        for (int d = 0; d < 128; d++) {
            float a[8], b[8];
            *(float4*)&a[0] = *(const float4*)&sB[d * 128 + ty*8];      // k rows (j)
            *(float4*)&a[4] = *(const float4*)&sB[d * 128 + ty*8 + 4];
            *(float4*)&b[0] = *(const float4*)&sQ[d * 128 + tx*8];      // q rows (i)
            *(float4*)&b[4] = *(const float4*)&sQ[d * 128 + tx*8 + 4];
            #pragma unroll
            for (int jj = 0; jj < 8; jj++)
                #pragma unroll
                for (int ii = 0; ii < 8; ii++)
                    acc[jj][ii] += a[jj] * b[ii];
        }
        __syncthreads();   // kT reads done; sC free to write
        #pragma unroll
        for (int jj = 0; jj < 8; jj++) {
            int j = ty*8 + jj;
            #pragma unroll
            for (int ii = 0; ii < 8; ii++) {
                int i = tx*8 + ii;
                sC[j * 128 + i] = (i >= j) ? acc[jj][ii] : 0.f;
            }
        }
    }
    __syncthreads();

    // overwrite sB with v (natural [j][e])
    #pragma unroll
    for (int r = 0; r < 16; r++) {
        int idx = r * 256 + tid;
        int row = idx >> 5;
        int col = (idx & 31) << 2;
        *(float4*)&sB[row * 128 + col] = *(const float4*)(vg + (long)row * QKV_W + col);
    }
    __syncthreads();

    // GEMM2: o[i][e] = sum_j scT[j][i] * v[j][e]
    float o[8][8];
    #pragma unroll
    for (int a = 0; a < 8; a++)
        #pragma unroll
        for (int b = 0; b < 8; b++) o[a][b] = 0.f;

    for (int j = 0; j < 128; j++) {
        float a[8], b[8];
        *(float4*)&a[0] = *(const float4*)&sC[j * 128 + ty*8];
        *(float4*)&a[4] = *(const float4*)&sC[j * 128 + ty*8 + 4];
        *(float4*)&b[0] = *(const float4*)&sB[j * 128 + tx*8];
        *(float4*)&b[4] = *(const float4*)&sB[j * 128 + tx*8 + 4];
        #pragma unroll
        for (int ii = 0; ii < 8; ii++)
            #pragma unroll
            for (int ee = 0; ee < 8; ee++)
                o[ii][ee] += a[ii] * b[ee];
    }
    __syncthreads();

    // overwrite sC with S (natural [d][e])
    const float* Sg = S + ((long)c * NH + h) * (HD * HD);
    #pragma unroll
    for (int r = 0; r < 16; r++) {
        int idx = r * 256 + tid;
        int row = idx >> 5;
        int col = (idx & 31) << 2;
        *(float4*)&sC[row * 128 + col] = *(const float4*)(Sg + row * 128 + col);
    }
    __syncthreads();

    // GEMM3: o[i][e] += sum_d qT[d][i] * S[d][e]
    for (int d = 0; d < 128; d++) {
        float a[8], b[8];
        *(float4*)&a[0] = *(const float4*)&sQ[d * 128 + ty*8];
        *(float4*)&a[4] = *(const float4*)&sQ[d * 128 + ty*8 + 4];
        *(float4*)&b[0] = *(const float4*)&sC[d * 128 + tx*8];
        *(float4*)&b[4] = *(const float4*)&sC[d * 128 + tx*8 + 4];
        #pragma unroll
        for (int ii = 0; ii < 8; ii++)
            #pragma unroll
            for (int ee = 0; ee < 8; ee++)
                o[ii][ee] += a[ii] * b[ee];
    }

    // write O[t][h*128 + e]
    #pragma unroll
    for (int ii = 0; ii < 8; ii++) {
        float* Op = O + (long)(t0 + ty*8 + ii) * INNER + h * HD + tx*8;
        *(float4*)(Op)     = make_float4(o[ii][0], o[ii][1], o[ii][2], o[ii][3]);
        *(float4*)(Op + 4) = make_float4(o[ii][4], o[ii][5], o[ii][6], o[ii][7]);
    }
}

// ---------------------------------------------------------------------------
// Per-token g-norm + sigmoid gate: G[t] = sigmoid(G[t]) * rmsnorm(O[t]) * gw
// grid(T), 256 threads; in-place over g_gate
// ---------------------------------------------------------------------------
__global__ __launch_bounds__(256)
void gate_norm_kernel(const float* __restrict__ O, float* __restrict__ G,
                      const float* __restrict__ gw)
{
    const int t = blockIdx.x;
    const int tid = threadIdx.x;
    const float* orow = O + (long)t * INNER;
    float* grow = G + (long)t * INNER;

    float4 o0 = *(const float4*)(orow + tid * 4);
    float4 o1 = *(const float4*)(orow + 1024 + tid * 4);

    float s = o0.x*o0.x + o0.y*o0.y + o0.z*o0.z + o0.w*o0.w
            + o1.x*o1.x + o1.y*o1.y + o1.z*o1.z + o1.w*o1.w;
    #pragma unroll
    for (int o = 16; o; o >>= 1) s += __shfl_xor_sync(0xffffffffu, s, o);
    __shared__ float red[8];
    if ((tid & 31) == 0) red[tid >> 5] = s;
    __syncthreads();
    float tot = 0.f;
    #pragma unroll
    for (int w = 0; w < 8; w++) tot += red[w];
    const float rs = rsqrtf(tot * (1.f / 2048.f) + EPS);

    float4 g0 = *(const float4*)(grow + tid * 4);
    float4 g1 = *(const float4*)(grow + 1024 + tid * 4);
    float4 w0 = *(const float4*)(gw + tid * 4);
    float4 w1 = *(const float4*)(gw + 1024 + tid * 4);

    float4 r0, r1;
    r0.x = (1.f / (1.f + expf(-g0.x))) * o0.x * rs * w0.x;
    r0.y = (1.f / (1.f + expf(-g0.y))) * o0.y * rs * w0.y;
    r0.z = (1.f / (1.f + expf(-g0.z))) * o0.z * rs * w0.z;
    r0.w = (1.f / (1.f + expf(-g0.w))) * o0.w * rs * w0.w;
    r1.x = (1.f / (1.f + expf(-g1.x))) * o1.x * rs * w1.x;
    r1.y = (1.f / (1.f + expf(-g1.y))) * o1.y * rs * w1.y;
    r1.z = (1.f / (1.f + expf(-g1.z))) * o1.z * rs * w1.z;
    r1.w = (1.f / (1.f + expf(-g1.w))) * o1.w * rs * w1.w;

    *(float4*)(grow + tid * 4)        = r0;
    *(float4*)(grow + 1024 + tid * 4) = r1;
}

// ---------------------------------------------------------------------------
// Launch
// ---------------------------------------------------------------------------
extern "C" void kernel_launch(void* const* d_in, const int* in_sizes, int n_in,
                              void* d_out, int out_size)
{
    const float* x    = (const float*)d_in[0];   // [8192, 2048]
    const int*   pos  = (const int*)  d_in[1];   // [8192]
    const float* Wqkv = (const float*)d_in[2];   // [2048, 6144]
    const float* qw   = (const float*)d_in[3];   // [128]
    const float* kw   = (const float*)d_in[4];   // [128]
    const float* Wg   = (const float*)d_in[5];   // [2048, 2048]
    const float* gw   = (const float*)d_in[6];   // [2048]
    const float* Wo   = (const float*)d_in[7];   // [2048, 2048]
    float* out = (float*)d_out;                  // [8192, 2048]

    float* qkv;  cudaGetSymbolAddress((void**)&qkv,  g_qkv);
    float* gate; cudaGetSymbolAddress((void**)&gate, g_gate);
    float* o;    cudaGetSymbolAddress((void**)&o,    g_o);
    float* kvp;  cudaGetSymbolAddress((void**)&kvp,  g_kvp);
    float* S;    cudaGetSymbolAddress((void**)&S,    g_S);

    cudaFuncSetAttribute(kv_outer_kernel,
                         cudaFuncAttributeMaxDynamicSharedMemorySize, 2 * 65536);
    cudaFuncSetAttribute(attn_chunk_kernel,
                         cudaFuncAttributeMaxDynamicSharedMemorySize, 3 * 65536);

    // 1. qkv = silu(x @ Wqkv)
    sgemm128<1><<<dim3(QKV_W / 128, T_TOK / 128), 256>>>(x, Wqkv, qkv, T_TOK, QKV_W, HID);
    // 2. gate = x @ Wg
    sgemm128<0><<<dim3(INNER / 128, T_TOK / 128), 256>>>(x, Wg, gate, T_TOK, INNER, HID);
    // 3. per-head rmsnorm + rope (+ q scale), in place
    qk_rope_kernel<<<dim3(T_TOK, NH), 64>>>(qkv, pos, qw, kw);
    // 4. per-chunk KV outer products
    kv_outer_kernel<<<dim3(NCHUNK, NH), 256, 2 * 65536>>>(qkv, kvp);
    // 5. exclusive prefix over chunks -> per-chunk state S
    prefix_kernel<<<(NH * HD * HD) / 256, 256>>>(kvp, S);
    // 6. intra-chunk masked attention + inter-chunk q@S
    attn_chunk_kernel<<<dim3(NCHUNK, NH), 256, 3 * 65536>>>(qkv, S, o);
    // 7. g-norm + sigmoid gating (in place over gate)
    gate_norm_kernel<<<T_TOK, 256>>>(o, gate, gw);
    // 8. out = gated @ Wo
    sgemm128<0><<<dim3(HID / 128, T_TOK / 128), 256>>>(gate, Wo, out, T_TOK, HID, INNER);
}

// round 4
// speedup vs baseline: 1.0002x; 1.0002x over previous
#include <cuda_runtime.h>
#include <cuda_bf16.h>
#include <math.h>

// ---------------------------------------------------------------------------
// Problem constants
// ---------------------------------------------------------------------------
#define T_TOK   8192
#define HID     2048
#define NH      16
#define HD      128
#define INNER   2048          // NH*HD
#define QKV_W   6144          // 3*INNER
#define NCHUNK  64            // T/128
#define CHUNK   128
#define EPS     1e-5f
#define QSCALE  0.08838834764831845f   // 128^-0.5

// ---------------------------------------------------------------------------
// Device scratch (static globals: allocation-free rule)
// ---------------------------------------------------------------------------
__device__ float g_qkv [T_TOK * QKV_W];            // 192 MiB: silu(x@Wqkv), q/k rope'd in place
__device__ float g_gate[T_TOK * INNER];            // 64 MiB: x@Wg, then overwritten with gated value
__device__ float g_o   [T_TOK * INNER];            // 64 MiB: attention output
__device__ float g_kvp [NCHUNK * NH * HD * HD];    // 64 MiB: per-chunk KV outer products
__device__ float g_S   [NCHUNK * NH * HD * HD];    // 64 MiB: exclusive prefix state per chunk

// ---------------------------------------------------------------------------
// Generic fp32 SGEMM: C[M,N] = act(A[M,K] @ B[K,N])
// 128x128 block tile, BK=16, 256 threads, 8x8 microtile, prefetched
// ACT: 0 = none, 1 = silu
// ---------------------------------------------------------------------------
template<int ACT>
__global__ __launch_bounds__(256, 2)
void sgemm128(const float* __restrict__ A, const float* __restrict__ B,
              float* __restrict__ C, int M, int N, int K)
{
    __shared__ float As[16][128];   // transposed: As[k][m]
    __shared__ float Bs[16][128];   // natural:    Bs[k][n]

    const int bm = blockIdx.y * 128;
    const int bn = blockIdx.x * 128;
    const int tid = threadIdx.x;
    const int tx = tid & 15;        // 0..15 -> N microtile
    const int ty = tid >> 4;        // 0..15 -> M microtile

    // A tile loader: 128 rows x 16 cols, each thread 2 float4
    const int a_row = tid >> 2;            // 0..63 (and +64)
    const int a_col = (tid & 3) << 2;      // 0,4,8,12
    // B tile loader: 16 rows x 128 cols, each thread 2 float4
    const int b_row = tid >> 5;            // 0..7 (and +8)
    const int b_col = (tid & 31) << 2;

    const float* Ap = A + (long)(bm + a_row) * K + a_col;
    const float* Ap2 = Ap + (long)64 * K;
    const float* Bp = B + (long)b_row * N + bn + b_col;
    const float* Bp2 = Bp + (long)8 * N;

    float4 a0 = *(const float4*)(Ap);
    float4 a1 = *(const float4*)(Ap2);
    float4 b0 = *(const float4*)(Bp);
    float4 b1 = *(const float4*)(Bp2);

    float acc[8][8];
    #pragma unroll
    for (int i = 0; i < 8; i++)
        #pragma unroll
        for (int j = 0; j < 8; j++) acc[i][j] = 0.f;

    for (int k0 = 0; k0 < K; k0 += 16) {
        // store staged tile
        As[a_col+0][a_row]    = a0.x; As[a_col+1][a_row]    = a0.y;
        As[a_col+2][a_row]    = a0.z; As[a_col+3][a_row]    = a0.w;
        As[a_col+0][a_row+64] = a1.x; As[a_col+1][a_row+64] = a1.y;
        As[a_col+2][a_row+64] = a1.z; As[a_col+3][a_row+64] = a1.w;
        *(float4*)&Bs[b_row][b_col]   = b0;
        *(float4*)&Bs[b_row+8][b_col] = b1;
        __syncthreads();

        // prefetch next tile while computing this one
        if (k0 + 16 < K) {
            a0 = *(const float4*)(Ap  + k0 + 16);
            a1 = *(const float4*)(Ap2 + k0 + 16);
            b0 = *(const float4*)(Bp  + (long)(k0 + 16) * N);
            b1 = *(const float4*)(Bp2 + (long)(k0 + 16) * N);
        }

        #pragma unroll
        for (int kk = 0; kk < 16; kk++) {
            float a[8], b[8];
            *(float4*)&a[0] = *(const float4*)&As[kk][ty*8];
            *(float4*)&a[4] = *(const float4*)&As[kk][ty*8+4];
            *(float4*)&b[0] = *(const float4*)&Bs[kk][tx*8];
            *(float4*)&b[4] = *(const float4*)&Bs[kk][tx*8+4];
            #pragma unroll
            for (int i = 0; i < 8; i++)
                #pragma unroll
                for (int j = 0; j < 8; j++)
                    acc[i][j] += a[i] * b[j];
        }
        __syncthreads();
    }

    // epilogue
    #pragma unroll
    for (int i = 0; i < 8; i++) {
        float* Cp = C + (long)(bm + ty*8 + i) * N + bn + tx*8;
        float4 r0, r1;
        float v[8];
        #pragma unroll
        for (int j = 0; j < 8; j++) {
            float x = acc[i][j];
            if (ACT == 1) x = x / (1.f + expf(-x));   // silu
            v[j] = x;
        }
        r0.x = v[0]; r0.y = v[1]; r0.z = v[2]; r0.w = v[3];
        r1.x = v[4]; r1.y = v[5]; r1.z = v[6]; r1.w = v[7];
        *(float4*)(Cp)     = r0;
        *(float4*)(Cp + 4) = r1;
    }
}

// ---------------------------------------------------------------------------
// Per-(token, head) RMSNorm + RoPE (+ q scale), in place on g_qkv
// grid(T, H), 64 threads; thread j handles dims j and j+64 (rope pair)
// ---------------------------------------------------------------------------
__global__ void qk_rope_kernel(float* __restrict__ qkv,
                               const int* __restrict__ pos,
                               const float* __restrict__ qw,
                               const float* __restrict__ kw)
{
    const int t = blockIdx.x, h = blockIdx.y;
    const int j = threadIdx.x;              // 0..63
    float* qp = qkv + (long)t * QKV_W + h * HD;
    float* kp = qp + INNER;

    float q1 = qp[j], q2 = qp[j + 64];
    float k1 = kp[j], k2 = kp[j + 64];

    float sq = q1*q1 + q2*q2;
    float sk = k1*k1 + k2*k2;
    #pragma unroll
    for (int o = 16; o; o >>= 1) {
        sq += __shfl_xor_sync(0xffffffffu, sq, o);
        sk += __shfl_xor_sync(0xffffffffu, sk, o);
    }
    __shared__ float red[4];
    const int w = j >> 5, lane = j & 31;
    if (lane == 0) { red[w] = sq; red[2 + w] = sk; }
    __syncthreads();
    const float rq = rsqrtf((red[0] + red[1]) * (1.f / 128.f) + EPS);
    const float rk = rsqrtf((red[2] + red[3]) * (1.f / 128.f) + EPS);

    q1 = q1 * rq * qw[j]; q2 = q2 * rq * qw[j + 64];
    k1 = k1 * rk * kw[j]; k2 = k2 * rk * kw[j + 64];

    const float inv = powf(600000.0f, -(float)j * (1.0f / 64.0f));
    const float ang = (float)pos[t] * inv;
    float s, c;
    sincosf(ang, &s, &c);

    qp[j]      = (q1 * c - q2 * s) * QSCALE;
    qp[j + 64] = (q2 * c + q1 * s) * QSCALE;
    kp[j]      =  k1 * c - k2 * s;
    kp[j + 64] =  k2 * c + k1 * s;
}

// ---------------------------------------------------------------------------
// Per-(chunk, head) KV outer product: KV[d][e] = sum_j k[j][d] * v[j][e]
// grid(NCHUNK, NH), 256 threads, dyn smem = 2 * 64KB
// ---------------------------------------------------------------------------
__global__ __launch_bounds__(256, 1)
void kv_outer_kernel(const float* __restrict__ qkv, float* __restrict__ KV)
{
    extern __shared__ float sm[];
    float* sK = sm;            // [j][d]
    float* sV = sm + 16384;    // [j][e]

    const int c = blockIdx.x, h = blockIdx.y;
    const int t0 = c * CHUNK;
    const int tid = threadIdx.x, tx = tid & 15, ty = tid >> 4;

    const float* kg = qkv + (long)t0 * QKV_W + h * HD + INNER;
    const float* vg = kg + INNER;

    #pragma unroll
    for (int r = 0; r < 16; r++) {
        int idx = r * 256 + tid;            // 0..4095
        int row = idx >> 5;
        int col = (idx & 31) << 2;
        *(float4*)&sK[row * 128 + col] = *(const float4*)(kg + (long)row * QKV_W + col);
        *(float4*)&sV[row * 128 + col] = *(const float4*)(vg + (long)row * QKV_W + col);
    }
    __syncthreads();

    float acc[8][8];
    #pragma unroll
    for (int i = 0; i < 8; i++)
        #pragma unroll
        for (int j = 0; j < 8; j++) acc[i][j] = 0.f;

    for (int j = 0; j < 128; j++) {
        float a[8], b[8];
        *(float4*)&a[0] = *(const float4*)&sK[j * 128 + ty*8];
        *(float4*)&a[4] = *(const float4*)&sK[j * 128 + ty*8 + 4];
        *(float4*)&b[0] = *(const float4*)&sV[j * 128 + tx*8];
        *(float4*)&b[4] = *(const float4*)&sV[j * 128 + tx*8 + 4];
        #pragma unroll
        for (int i = 0; i < 8; i++)
            #pragma unroll
            for (int e = 0; e < 8; e++)
                acc[i][e] += a[i] * b[e];
    }

    float* out = KV + ((long)c * NH + h) * (HD * HD);
    #pragma unroll
    for (int i = 0; i < 8; i++) {
        float4 r0 = make_float4(acc[i][0], acc[i][1], acc[i][2], acc[i][3]);
        float4 r1 = make_float4(acc[i][4], acc[i][5], acc[i][6], acc[i][7]);
        *(float4*)&out[(ty*8 + i) * 128 + tx*8]     = r0;
        *(float4*)&out[(ty*8 + i) * 128 + tx*8 + 4] = r1;
    }
}

// ---------------------------------------------------------------------------
// Exclusive prefix over chunks: S[c] = sum_{j<c} KV[j]   (per h,d,e element)
// ---------------------------------------------------------------------------
__global__ void prefix_kernel(const float* __restrict__ KV, float* __restrict__ S)
{
    const int idx = blockIdx.x * 256 + threadIdx.x;   // 0 .. 262143 (h*16384 + d*128 + e)
    float acc = 0.f;
    #pragma unroll 4
    for (int c = 0; c < NCHUNK; c++) {
        S[(long)c * (NH * HD * HD) + idx] = acc;
        acc += KV[(long)c * (NH * HD * HD) + idx];
    }
}

// ---------------------------------------------------------------------------
// Per-(chunk, head) attention:
//   scT[j][i] = (i>=j) ? sum_d q[i][d] k[j][d] : 0
//   o[i][e]   = sum_j scT[j][i] v[j][e]  +  sum_d q[i][d] S[d][e]
// grid(NCHUNK, NH), 256 threads, dyn smem = 3 * 64KB
// ---------------------------------------------------------------------------
__global__ __launch_bounds__(256, 1)
void attn_chunk_kernel(const float* __restrict__ qkv, const float* __restrict__ S,
                       float* __restrict__ O)
{
    extern __shared__ float sm[];
    float* sQ = sm;             // qT [d][i]
    float* sB = sm + 16384;     // kT [d][j], then v [j][e]
    float* sC = sm + 32768;     // scoresT [j][i], then S [d][e]

    const int c = blockIdx.x, h = blockIdx.y;
    const int t0 = c * CHUNK;
    const int tid = threadIdx.x, tx = tid & 15, ty = tid >> 4;

    const float* qg = qkv + (long)t0 * QKV_W + h * HD;
    const float* kg = qg + INNER;
    const float* vg = qg + 2 * INNER;

    // load qT, kT (transpose on store)
    #pragma unroll
    for (int r = 0; r < 16; r++) {
        int idx = r * 256 + tid;
        int i  = idx >> 5;
        int dd = (idx & 31) << 2;
        float4 q4 = *(const float4*)(qg + (long)i * QKV_W + dd);
        float4 k4 = *(const float4*)(kg + (long)i * QKV_W + dd);
        sQ[(dd+0)*128 + i] = q4.x; sQ[(dd+1)*128 + i] = q4.y;
        sQ[(dd+2)*128 + i] = q4.z; sQ[(dd+3)*128 + i] = q4.w;
        sB[(dd+0)*128 + i] = k4.x; sB[(dd+1)*128 + i] = k4.y;
        sB[(dd+2)*128 + i] = k4.z; sB[(dd+3)*128 + i] = k4.w;
    }
    __syncthreads();

    // GEMM1: scT[j][i] with causal mask (keep i >= j)
    {
        float acc[8][8];
        #pragma unroll
        for (int a = 0; a < 8; a++)
            #pragma unroll
            for (int b = 0; b < 8; b++) acc[a][b] = 0.f;

        for (int d = 0; d < 128; d++) {
            float a[8], b[8];
            *(float4*)&a[0] = *(const float4*)&sB[d * 128 + ty*8];      // k rows (j)
            *(float4*)&a[4] = *(const float4*)&sB[d * 128 + ty*8 + 4];
            *(float4*)&b[0] = *(const float4*)&sQ[d * 128 + tx*8];      // q rows (i)
            *(float4*)&b[4] = *(const float4*)&sQ[d * 128 + tx*8 + 4];
            #pragma unroll
            for (int jj = 0; jj < 8; jj++)
                #pragma unroll
                for (int ii = 0; ii < 8; ii++)
                    acc[jj][ii] += a[jj] * b[ii];
        }
        __syncthreads();   // kT reads done; sC free to write
        #pragma unroll
        for (int jj = 0; jj < 8; jj++) {
            int j = ty*8 + jj;
            #pragma unroll
            for (int ii = 0; ii < 8; ii++) {
                int i = tx*8 + ii;
                sC[j * 128 + i] = (i >= j) ? acc[jj][ii] : 0.f;
            }
        }
    }
    __syncthreads();

    // overwrite sB with v (natural [j][e])
    #pragma unroll
    for (int r = 0; r < 16; r++) {
        int idx = r * 256 + tid;
        int row = idx >> 5;
        int col = (idx & 31) << 2;
        *(float4*)&sB[row * 128 + col] = *(const float4*)(vg + (long)row * QKV_W + col);
    }
    __syncthreads();

    // GEMM2: o[i][e] = sum_j scT[j][i] * v[j][e]
    float o[8][8];
    #pragma unroll
    for (int a = 0; a < 8; a++)
        #pragma unroll
        for (int b = 0; b < 8; b++) o[a][b] = 0.f;

    for (int j = 0; j < 128; j++) {
        float a[8], b[8];
        *(float4*)&a[0] = *(const float4*)&sC[j * 128 + ty*8];
        *(float4*)&a[4] = *(const float4*)&sC[j * 128 + ty*8 + 4];
        *(float4*)&b[0] = *(const float4*)&sB[j * 128 + tx*8];
        *(float4*)&b[4] = *(const float4*)&sB[j * 128 + tx*8 + 4];
        #pragma unroll
        for (int ii = 0; ii < 8; ii++)
            #pragma unroll
            for (int ee = 0; ee < 8; ee++)
                o[ii][ee] += a[ii] * b[ee];
    }
    __syncthreads();

    // overwrite sC with S (natural [d][e])
    const float* Sg = S + ((long)c * NH + h) * (HD * HD);
    #pragma unroll
    for (int r = 0; r < 16; r++) {
        int idx = r * 256 + tid;
        int row = idx >> 5;
        int col = (idx & 31) << 2;
        *(float4*)&sC[row * 128 + col] = *(const float4*)(Sg + row * 128 + col);
    }
    __syncthreads();

    // GEMM3: o[i][e] += sum_d qT[d][i] * S[d][e]
    for (int d = 0; d < 128; d++) {
        float a[8], b[8];
        *(float4*)&a[0] = *(const float4*)&sQ[d * 128 + ty*8];
        *(float4*)&a[4] = *(const float4*)&sQ[d * 128 + ty*8 + 4];
        *(float4*)&b[0] = *(const float4*)&sC[d * 128 + tx*8];
        *(float4*)&b[4] = *(const float4*)&sC[d * 128 + tx*8 + 4];
        #pragma unroll
        for (int ii = 0; ii < 8; ii++)
            #pragma unroll
            for (int ee = 0; ee < 8; ee++)
                o[ii][ee] += a[ii] * b[ee];
    }

    // write O[t][h*128 + e]
    #pragma unroll
    for (int ii = 0; ii < 8; ii++) {
        float* Op = O + (long)(t0 + ty*8 + ii) * INNER + h * HD + tx*8;
        *(float4*)(Op)     = make_float4(o[ii][0], o[ii][1], o[ii][2], o[ii][3]);
        *(float4*)(Op + 4) = make_float4(o[ii][4], o[ii][5], o[ii][6], o[ii][7]);
    }
}

// ---------------------------------------------------------------------------
// Per-token g-norm + sigmoid gate: G[t] = sigmoid(G[t]) * rmsnorm(O[t]) * gw
// grid(T), 256 threads; in-place over g_gate
// ---------------------------------------------------------------------------
__global__ __launch_bounds__(256)
void gate_norm_kernel(const float* __restrict__ O, float* __restrict__ G,
                      const float* __restrict__ gw)
{
    const int t = blockIdx.x;
    const int tid = threadIdx.x;
    const float* orow = O + (long)t * INNER;
    float* grow = G + (long)t * INNER;

    float4 o0 = *(const float4*)(orow + tid * 4);
    float4 o1 = *(const float4*)(orow + 1024 + tid * 4);

    float s = o0.x*o0.x + o0.y*o0.y + o0.z*o0.z + o0.w*o0.w
            + o1.x*o1.x + o1.y*o1.y + o1.z*o1.z + o1.w*o1.w;
    #pragma unroll
    for (int o = 16; o; o >>= 1) s += __shfl_xor_sync(0xffffffffu, s, o);
    __shared__ float red[8];
    if ((tid & 31) == 0) red[tid >> 5] = s;
    __syncthreads();
    float tot = 0.f;
    #pragma unroll
    for (int w = 0; w < 8; w++) tot += red[w];
    const float rs = rsqrtf(tot * (1.f / 2048.f) + EPS);

    float4 g0 = *(const float4*)(grow + tid * 4);
    float4 g1 = *(const float4*)(grow + 1024 + tid * 4);
    float4 w0 = *(const float4*)(gw + tid * 4);
    float4 w1 = *(const float4*)(gw + 1024 + tid * 4);

    float4 r0, r1;
    r0.x = (1.f / (1.f + expf(-g0.x))) * o0.x * rs * w0.x;
    r0.y = (1.f / (1.f + expf(-g0.y))) * o0.y * rs * w0.y;
    r0.z = (1.f / (1.f + expf(-g0.z))) * o0.z * rs * w0.z;
    r0.w = (1.f / (1.f + expf(-g0.w))) * o0.w * rs * w0.w;
    r1.x = (1.f / (1.f + expf(-g1.x))) * o1.x * rs * w1.x;
    r1.y = (1.f / (1.f + expf(-g1.y))) * o1.y * rs * w1.y;
    r1.z = (1.f / (1.f + expf(-g1.z))) * o1.z * rs * w1.z;
    r1.w = (1.f / (1.f + expf(-g1.w))) * o1.w * rs * w1.w;

    *(float4*)(grow + tid * 4)        = r0;
    *(float4*)(grow + 1024 + tid * 4) = r1;
}

// ---------------------------------------------------------------------------
// Launch
// ---------------------------------------------------------------------------
extern "C" void kernel_launch(void* const* d_in, const int* in_sizes, int n_in,
                              void* d_out, int out_size)
{
    const float* x    = (const float*)d_in[0];   // [8192, 2048]
    const int*   pos  = (const int*)  d_in[1];   // [8192]
    const float* Wqkv = (const float*)d_in[2];   // [2048, 6144]
    const float* qw   = (const float*)d_in[3];   // [128]
    const float* kw   = (const float*)d_in[4];   // [128]
    const float* Wg   = (const float*)d_in[5];   // [2048, 2048]
    const float* gw   = (const float*)d_in[6];   // [2048]
    const float* Wo   = (const float*)d_in[7];   // [2048, 2048]
    float* out = (float*)d_out;                  // [8192, 2048]

    float* qkv;  cudaGetSymbolAddress((void**)&qkv,  g_qkv);
    float* gate; cudaGetSymbolAddress((void**)&gate, g_gate);
    float* o;    cudaGetSymbolAddress((void**)&o,    g_o);
    float* kvp;  cudaGetSymbolAddress((void**)&kvp,  g_kvp);
    float* S;    cudaGetSymbolAddress((void**)&S,    g_S);

    cudaFuncSetAttribute(kv_outer_kernel,
                         cudaFuncAttributeMaxDynamicSharedMemorySize, 2 * 65536);
    cudaFuncSetAttribute(attn_chunk_kernel,
                         cudaFuncAttributeMaxDynamicSharedMemorySize, 3 * 65536);

    // 1. qkv = silu(x @ Wqkv)
    sgemm128<1><<<dim3(QKV_W / 128, T_TOK / 128), 256>>>(x, Wqkv, qkv, T_TOK, QKV_W, HID);
    // 2. gate = x @ Wg
    sgemm128<0><<<dim3(INNER / 128, T_TOK / 128), 256>>>(x, Wg, gate, T_TOK, INNER, HID);
    // 3. per-head rmsnorm + rope (+ q scale), in place
    qk_rope_kernel<<<dim3(T_TOK, NH), 64>>>(qkv, pos, qw, kw);
    // 4. per-chunk KV outer products
    kv_outer_kernel<<<dim3(NCHUNK, NH), 256, 2 * 65536>>>(qkv, kvp);
    // 5. exclusive prefix over chunks -> per-chunk state S
    prefix_kernel<<<(NH * HD * HD) / 256, 256>>>(kvp, S);
    // 6. intra-chunk masked attention + inter-chunk q@S
    attn_chunk_kernel<<<dim3(NCHUNK, NH), 256, 3 * 65536>>>(qkv, S, o);
    // 7. g-norm + sigmoid gating (in place over gate)
    gate_norm_kernel<<<T_TOK, 256>>>(o, gate, gw);
    // 8. out = gated @ Wo
    sgemm128<0><<<dim3(HID / 128, T_TOK / 128), 256>>>(gate, Wo, out, T_TOK, HID, INNER);
}

// round 5
// speedup vs baseline: 1.0004x; 1.0001x over previous
#include <cuda_runtime.h>
#include <cuda_bf16.h>
#include <math.h>

// ---------------------------------------------------------------------------
// Problem constants
// ---------------------------------------------------------------------------
#define T_TOK   8192
#define HID     2048
#define NH      16
#define HD      128
#define INNER   2048          // NH*HD
#define QKV_W   6144          // 3*INNER
#define NCHUNK  64            // T/128
#define CHUNK   128
#define EPS     1e-5f
#define QSCALE  0.08838834764831845f   // 128^-0.5

// ---------------------------------------------------------------------------
// Device scratch (static globals: allocation-free rule)
// ---------------------------------------------------------------------------
__device__ float g_qkv [T_TOK * QKV_W];            // 192 MiB: silu(x@Wqkv), q/k rope'd in place
__device__ float g_gate[T_TOK * INNER];            // 64 MiB: x@Wg, then overwritten with gated value
__device__ float g_o   [T_TOK * INNER];            // 64 MiB: attention output
__device__ float g_kvp [NCHUNK * NH * HD * HD];    // 64 MiB: per-chunk KV outer products
__device__ float g_S   [NCHUNK * NH * HD * HD];    // 64 MiB: exclusive prefix state per chunk

// ---------------------------------------------------------------------------
// Generic fp32 SGEMM: C[M,N] = act(A[M,K] @ B[K,N])
// 128x128 block tile, BK=16, 256 threads, 8x8 microtile, prefetched
// ACT: 0 = none, 1 = silu
// ---------------------------------------------------------------------------
template<int ACT>
__global__ __launch_bounds__(256, 2)
void sgemm128(const float* __restrict__ A, const float* __restrict__ B,
              float* __restrict__ C, int M, int N, int K)
{
    __shared__ float As[16][128];   // transposed: As[k][m]
    __shared__ float Bs[16][128];   // natural:    Bs[k][n]

    const int bm = blockIdx.y * 128;
    const int bn = blockIdx.x * 128;
    const int tid = threadIdx.x;
    const int tx = tid & 15;        // 0..15 -> N microtile
    const int ty = tid >> 4;        // 0..15 -> M microtile

    // A tile loader: 128 rows x 16 cols, each thread 2 float4
    const int a_row = tid >> 2;            // 0..63 (and +64)
    const int a_col = (tid & 3) << 2;      // 0,4,8,12
    // B tile loader: 16 rows x 128 cols, each thread 2 float4
    const int b_row = tid >> 5;            // 0..7 (and +8)
    const int b_col = (tid & 31) << 2;

    const float* Ap = A + (long)(bm + a_row) * K + a_col;
    const float* Ap2 = Ap + (long)64 * K;
    const float* Bp = B + (long)b_row * N + bn + b_col;
    const float* Bp2 = Bp + (long)8 * N;

    float4 a0 = *(const float4*)(Ap);
    float4 a1 = *(const float4*)(Ap2);
    float4 b0 = *(const float4*)(Bp);
    float4 b1 = *(const float4*)(Bp2);

    float acc[8][8];
    #pragma unroll
    for (int i = 0; i < 8; i++)
        #pragma unroll
        for (int j = 0; j < 8; j++) acc[i][j] = 0.f;

    for (int k0 = 0; k0 < K; k0 += 16) {
        // store staged tile
        As[a_col+0][a_row]    = a0.x; As[a_col+1][a_row]    = a0.y;
        As[a_col+2][a_row]    = a0.z; As[a_col+3][a_row]    = a0.w;
        As[a_col+0][a_row+64] = a1.x; As[a_col+1][a_row+64] = a1.y;
        As[a_col+2][a_row+64] = a1.z; As[a_col+3][a_row+64] = a1.w;
        *(float4*)&Bs[b_row][b_col]   = b0;
        *(float4*)&Bs[b_row+8][b_col] = b1;
        __syncthreads();

        // prefetch next tile while computing this one
        if (k0 + 16 < K) {
            a0 = *(const float4*)(Ap  + k0 + 16);
            a1 = *(const float4*)(Ap2 + k0 + 16);
            b0 = *(const float4*)(Bp  + (long)(k0 + 16) * N);
            b1 = *(const float4*)(Bp2 + (long)(k0 + 16) * N);
        }

        #pragma unroll
        for (int kk = 0; kk < 16; kk++) {
            float a[8], b[8];
            *(float4*)&a[0] = *(const float4*)&As[kk][ty*8];
            *(float4*)&a[4] = *(const float4*)&As[kk][ty*8+4];
            *(float4*)&b[0] = *(const float4*)&Bs[kk][tx*8];
            *(float4*)&b[4] = *(const float4*)&Bs[kk][tx*8+4];
            #pragma unroll
            for (int i = 0; i < 8; i++)
                #pragma unroll
                for (int j = 0; j < 8; j++)
                    acc[i][j] += a[i] * b[j];
        }
        __syncthreads();
    }

    // epilogue
    #pragma unroll
    for (int i = 0; i < 8; i++) {
        float* Cp = C + (long)(bm + ty*8 + i) * N + bn + tx*8;
        float4 r0, r1;
        float v[8];
        #pragma unroll
        for (int j = 0; j < 8; j++) {
            float x = acc[i][j];
            if (ACT == 1) x = x / (1.f + expf(-x));   // silu
            v[j] = x;
        }
        r0.x = v[0]; r0.y = v[1]; r0.z = v[2]; r0.w = v[3];
        r1.x = v[4]; r1.y = v[5]; r1.z = v[6]; r1.w = v[7];
        *(float4*)(Cp)     = r0;
        *(float4*)(Cp + 4) = r1;
    }
}

// ---------------------------------------------------------------------------
// Per-(token, head) RMSNorm + RoPE (+ q scale), in place on g_qkv
// grid(T, H), 64 threads; thread j handles dims j and j+64 (rope pair)
// ---------------------------------------------------------------------------
__global__ void qk_rope_kernel(float* __restrict__ qkv,
                               const int* __restrict__ pos,
                               const float* __restrict__ qw,
                               const float* __restrict__ kw)
{
    const int t = blockIdx.x, h = blockIdx.y;
    const int j = threadIdx.x;              // 0..63
    float* qp = qkv + (long)t * QKV_W + h * HD;
    float* kp = qp + INNER;

    float q1 = qp[j], q2 = qp[j + 64];
    float k1 = kp[j], k2 = kp[j + 64];

    float sq = q1*q1 + q2*q2;
    float sk = k1*k1 + k2*k2;
    #pragma unroll
    for (int o = 16; o; o >>= 1) {
        sq += __shfl_xor_sync(0xffffffffu, sq, o);
        sk += __shfl_xor_sync(0xffffffffu, sk, o);
    }
    __shared__ float red[4];
    const int w = j >> 5, lane = j & 31;
    if (lane == 0) { red[w] = sq; red[2 + w] = sk; }
    __syncthreads();
    const float rq = rsqrtf((red[0] + red[1]) * (1.f / 128.f) + EPS);
    const float rk = rsqrtf((red[2] + red[3]) * (1.f / 128.f) + EPS);

    q1 = q1 * rq * qw[j]; q2 = q2 * rq * qw[j + 64];
    k1 = k1 * rk * kw[j]; k2 = k2 * rk * kw[j + 64];

    const float inv = powf(600000.0f, -(float)j * (1.0f / 64.0f));
    const float ang = (float)pos[t] * inv;
    float s, c;
    sincosf(ang, &s, &c);

    qp[j]      = (q1 * c - q2 * s) * QSCALE;
    qp[j + 64] = (q2 * c + q1 * s) * QSCALE;
    kp[j]      =  k1 * c - k2 * s;
    kp[j + 64] =  k2 * c + k1 * s;
}

// ---------------------------------------------------------------------------
// Per-(chunk, head) KV outer product: KV[d][e] = sum_j k[j][d] * v[j][e]
// grid(NCHUNK, NH), 256 threads, dyn smem = 2 * 64KB
// ---------------------------------------------------------------------------
__global__ __launch_bounds__(256, 1)
void kv_outer_kernel(const float* __restrict__ qkv, float* __restrict__ KV)
{
    extern __shared__ float sm[];
    float* sK = sm;            // [j][d]
    float* sV = sm + 16384;    // [j][e]

    const int c = blockIdx.x, h = blockIdx.y;
    const int t0 = c * CHUNK;
    const int tid = threadIdx.x, tx = tid & 15, ty = tid >> 4;

    const float* kg = qkv + (long)t0 * QKV_W + h * HD + INNER;
    const float* vg = kg + INNER;

    #pragma unroll
    for (int r = 0; r < 16; r++) {
        int idx = r * 256 + tid;            // 0..4095
        int row = idx >> 5;
        int col = (idx & 31) << 2;
        *(float4*)&sK[row * 128 + col] = *(const float4*)(kg + (long)row * QKV_W + col);
        *(float4*)&sV[row * 128 + col] = *(const float4*)(vg + (long)row * QKV_W + col);
    }
    __syncthreads();

    float acc[8][8];
    #pragma unroll
    for (int i = 0; i < 8; i++)
        #pragma unroll
        for (int j = 0; j < 8; j++) acc[i][j] = 0.f;

    for (int j = 0; j < 128; j++) {
        float a[8], b[8];
        *(float4*)&a[0] = *(const float4*)&sK[j * 128 + ty*8];
        *(float4*)&a[4] = *(const float4*)&sK[j * 128 + ty*8 + 4];
        *(float4*)&b[0] = *(const float4*)&sV[j * 128 + tx*8];
        *(float4*)&b[4] = *(const float4*)&sV[j * 128 + tx*8 + 4];
        #pragma unroll
        for (int i = 0; i < 8; i++)
            #pragma unroll
            for (int e = 0; e < 8; e++)
                acc[i][e] += a[i] * b[e];
    }

    float* out = KV + ((long)c * NH + h) * (HD * HD);
    #pragma unroll
    for (int i = 0; i < 8; i++) {
        float4 r0 = make_float4(acc[i][0], acc[i][1], acc[i][2], acc[i][3]);
        float4 r1 = make_float4(acc[i][4], acc[i][5], acc[i][6], acc[i][7]);
        *(float4*)&out[(ty*8 + i) * 128 + tx*8]     = r0;
        *(float4*)&out[(ty*8 + i) * 128 + tx*8 + 4] = r1;
    }
}

// ---------------------------------------------------------------------------
// Exclusive prefix over chunks: S[c] = sum_{j<c} KV[j]   (per h,d,e element)
// ---------------------------------------------------------------------------
__global__ void prefix_kernel(const float* __restrict__ KV, float* __restrict__ S)
{
    const int idx = blockIdx.x * 256 + threadIdx.x;   // 0 .. 262143 (h*16384 + d*128 + e)
    float acc = 0.f;
    #pragma unroll 4
    for (int c = 0; c < NCHUNK; c++) {
        S[(long)c * (NH * HD * HD) + idx] = acc;
        acc += KV[(long)c * (NH * HD * HD) + idx];
    }
}

// ---------------------------------------------------------------------------
// Per-(chunk, head) attention:
//   scT[j][i] = (i>=j) ? sum_d q[i][d] k[j][d] : 0
//   o[i][e]   = sum_j scT[j][i] v[j][e]  +  sum_d q[i][d] S[d][e]
// grid(NCHUNK, NH), 256 threads, dyn smem = 3 * 64KB
// ---------------------------------------------------------------------------
__global__ __launch_bounds__(256, 1)
void attn_chunk_kernel(const float* __restrict__ qkv, const float* __restrict__ S,
                       float* __restrict__ O)
{
    extern __shared__ float sm[];
    float* sQ = sm;             // qT [d][i]
    float* sB = sm + 16384;     // kT [d][j], then v [j][e]
    float* sC = sm + 32768;     // scoresT [j][i], then S [d][e]

    const int c = blockIdx.x, h = blockIdx.y;
    const int t0 = c * CHUNK;
    const int tid = threadIdx.x, tx = tid & 15, ty = tid >> 4;

    const float* qg = qkv + (long)t0 * QKV_W + h * HD;
    const float* kg = qg + INNER;
    const float* vg = qg + 2 * INNER;

    // load qT, kT (transpose on store)
    #pragma unroll
    for (int r = 0; r < 16; r++) {
        int idx = r * 256 + tid;
        int i  = idx >> 5;
        int dd = (idx & 31) << 2;
        float4 q4 = *(const float4*)(qg + (long)i * QKV_W + dd);
        float4 k4 = *(const float4*)(kg + (long)i * QKV_W + dd);
        sQ[(dd+0)*128 + i] = q4.x; sQ[(dd+1)*128 + i] = q4.y;
        sQ[(dd+2)*128 + i] = q4.z; sQ[(dd+3)*128 + i] = q4.w;
        sB[(dd+0)*128 + i] = k4.x; sB[(dd+1)*128 + i] = k4.y;
        sB[(dd+2)*128 + i] = k4.z; sB[(dd+3)*128 + i] = k4.w;
    }
    __syncthreads();

    // GEMM1: scT[j][i] with causal mask (keep i >= j)
    {
        float acc[8][8];
        #pragma unroll
        for (int a = 0; a < 8; a++)
            #pragma unroll
            for (int b = 0; b < 8; b++) acc[a][b] = 0.f;

        for (int d = 0; d < 128; d++) {
            float a[8], b[8];
            *(float4*)&a[0] = *(const float4*)&sB[d * 128 + ty*8];      // k rows (j)
            *(float4*)&a[4] = *(const float4*)&sB[d * 128 + ty*8 + 4];
            *(float4*)&b[0] = *(const float4*)&sQ[d * 128 + tx*8];      // q rows (i)
            *(float4*)&b[4] = *(const float4*)&sQ[d * 128 + tx*8 + 4];
            #pragma unroll
            for (int jj = 0; jj < 8; jj++)
                #pragma unroll
                for (int ii = 0; ii < 8; ii++)
                    acc[jj][ii] += a[jj] * b[ii];
        }
        __syncthreads();   // kT reads done; sC free to write
        #pragma unroll
        for (int jj = 0; jj < 8; jj++) {
            int j = ty*8 + jj;
            #pragma unroll
            for (int ii = 0; ii < 8; ii++) {
                int i = tx*8 + ii;
                sC[j * 128 + i] = (i >= j) ? acc[jj][ii] : 0.f;
            }
        }
    }
    __syncthreads();

    // overwrite sB with v (natural [j][e])
    #pragma unroll
    for (int r = 0; r < 16; r++) {
        int idx = r * 256 + tid;
        int row = idx >> 5;
        int col = (idx & 31) << 2;
        *(float4*)&sB[row * 128 + col] = *(const float4*)(vg + (long)row * QKV_W + col);
    }
    __syncthreads();

    // GEMM2: o[i][e] = sum_j scT[j][i] * v[j][e]
    float o[8][8];
    #pragma unroll
    for (int a = 0; a < 8; a++)
        #pragma unroll
        for (int b = 0; b < 8; b++) o[a][b] = 0.f;

    for (int j = 0; j < 128; j++) {
        float a[8], b[8];
        *(float4*)&a[0] = *(const float4*)&sC[j * 128 + ty*8];
        *(float4*)&a[4] = *(const float4*)&sC[j * 128 + ty*8 + 4];
        *(float4*)&b[0] = *(const float4*)&sB[j * 128 + tx*8];
        *(float4*)&b[4] = *(const float4*)&sB[j * 128 + tx*8 + 4];
        #pragma unroll
        for (int ii = 0; ii < 8; ii++)
            #pragma unroll
            for (int ee = 0; ee < 8; ee++)
                o[ii][ee] += a[ii] * b[ee];
    }
    __syncthreads();

    // overwrite sC with S (natural [d][e])
    const float* Sg = S + ((long)c * NH + h) * (HD * HD);
    #pragma unroll
    for (int r = 0; r < 16; r++) {
        int idx = r * 256 + tid;
        int row = idx >> 5;
        int col = (idx & 31) << 2;
        *(float4*)&sC[row * 128 + col] = *(const float4*)(Sg + row * 128 + col);
    }
    __syncthreads();

    // GEMM3: o[i][e] += sum_d qT[d][i] * S[d][e]
    for (int d = 0; d < 128; d++) {
        float a[8], b[8];
        *(float4*)&a[0] = *(const float4*)&sQ[d * 128 + ty*8];
        *(float4*)&a[4] = *(const float4*)&sQ[d * 128 + ty*8 + 4];
        *(float4*)&b[0] = *(const float4*)&sC[d * 128 + tx*8];
        *(float4*)&b[4] = *(const float4*)&sC[d * 128 + tx*8 + 4];
        #pragma unroll
        for (int ii = 0; ii < 8; ii++)
            #pragma unroll
            for (int ee = 0; ee < 8; ee++)
                o[ii][ee] += a[ii] * b[ee];
    }

    // write O[t][h*128 + e]
    #pragma unroll
    for (int ii = 0; ii < 8; ii++) {
        float* Op = O + (long)(t0 + ty*8 + ii) * INNER + h * HD + tx*8;
        *(float4*)(Op)     = make_float4(o[ii][0], o[ii][1], o[ii][2], o[ii][3]);
        *(float4*)(Op + 4) = make_float4(o[ii][4], o[ii][5], o[ii][6], o[ii][7]);
    }
}

// ---------------------------------------------------------------------------
// Per-token g-norm + sigmoid gate: G[t] = sigmoid(G[t]) * rmsnorm(O[t]) * gw
// grid(T), 256 threads; in-place over g_gate
// ---------------------------------------------------------------------------
__global__ __launch_bounds__(256)
void gate_norm_kernel(const float* __restrict__ O, float* __restrict__ G,
                      const float* __restrict__ gw)
{
    const int t = blockIdx.x;
    const int tid = threadIdx.x;
    const float* orow = O + (long)t * INNER;
    float* grow = G + (long)t * INNER;

    float4 o0 = *(const float4*)(orow + tid * 4);
    float4 o1 = *(const float4*)(orow + 1024 + tid * 4);

    float s = o0.x*o0.x + o0.y*o0.y + o0.z*o0.z + o0.w*o0.w
            + o1.x*o1.x + o1.y*o1.y + o1.z*o1.z + o1.w*o1.w;
    #pragma unroll
    for (int o = 16; o; o >>= 1) s += __shfl_xor_sync(0xffffffffu, s, o);
    __shared__ float red[8];
    if ((tid & 31) == 0) red[tid >> 5] = s;
    __syncthreads();
    float tot = 0.f;
    #pragma unroll
    for (int w = 0; w < 8; w++) tot += red[w];
    const float rs = rsqrtf(tot * (1.f / 2048.f) + EPS);

    float4 g0 = *(const float4*)(grow + tid * 4);
    float4 g1 = *(const float4*)(grow + 1024 + tid * 4);
    float4 w0 = *(const float4*)(gw + tid * 4);
    float4 w1 = *(const float4*)(gw + 1024 + tid * 4);

    float4 r0, r1;
    r0.x = (1.f / (1.f + expf(-g0.x))) * o0.x * rs * w0.x;
    r0.y = (1.f / (1.f + expf(-g0.y))) * o0.y * rs * w0.y;
    r0.z = (1.f / (1.f + expf(-g0.z))) * o0.z * rs * w0.z;
    r0.w = (1.f / (1.f + expf(-g0.w))) * o0.w * rs * w0.w;
    r1.x = (1.f / (1.f + expf(-g1.x))) * o1.x * rs * w1.x;
    r1.y = (1.f / (1.f + expf(-g1.y))) * o1.y * rs * w1.y;
    r1.z = (1.f / (1.f + expf(-g1.z))) * o1.z * rs * w1.z;
    r1.w = (1.f / (1.f + expf(-g1.w))) * o1.w * rs * w1.w;

    *(float4*)(grow + tid * 4)        = r0;
    *(float4*)(grow + 1024 + tid * 4) = r1;
}

// ---------------------------------------------------------------------------
// Launch
// ---------------------------------------------------------------------------
extern "C" void kernel_launch(void* const* d_in, const int* in_sizes, int n_in,
                              void* d_out, int out_size)
{
    const float* x    = (const float*)d_in[0];   // [8192, 2048]
    const int*   pos  = (const int*)  d_in[1];   // [8192]
    const float* Wqkv = (const float*)d_in[2];   // [2048, 6144]
    const float* qw   = (const float*)d_in[3];   // [128]
    const float* kw   = (const float*)d_in[4];   // [128]
    const float* Wg   = (const float*)d_in[5];   // [2048, 2048]
    const float* gw   = (const float*)d_in[6];   // [2048]
    const float* Wo   = (const float*)d_in[7];   // [2048, 2048]
    float* out = (float*)d_out;                  // [8192, 2048]

    float* qkv;  cudaGetSymbolAddress((void**)&qkv,  g_qkv);
    float* gate; cudaGetSymbolAddress((void**)&gate, g_gate);
    float* o;    cudaGetSymbolAddress((void**)&o,    g_o);
    float* kvp;  cudaGetSymbolAddress((void**)&kvp,  g_kvp);
    float* S;    cudaGetSymbolAddress((void**)&S,    g_S);

    cudaFuncSetAttribute(kv_outer_kernel,
                         cudaFuncAttributeMaxDynamicSharedMemorySize, 2 * 65536);
    cudaFuncSetAttribute(attn_chunk_kernel,
                         cudaFuncAttributeMaxDynamicSharedMemorySize, 3 * 65536);

    // 1. qkv = silu(x @ Wqkv)
    sgemm128<1><<<dim3(QKV_W / 128, T_TOK / 128), 256>>>(x, Wqkv, qkv, T_TOK, QKV_W, HID);
    // 2. gate = x @ Wg
    sgemm128<0><<<dim3(INNER / 128, T_TOK / 128), 256>>>(x, Wg, gate, T_TOK, INNER, HID);
    // 3. per-head rmsnorm + rope (+ q scale), in place
    qk_rope_kernel<<<dim3(T_TOK, NH), 64>>>(qkv, pos, qw, kw);
    // 4. per-chunk KV outer products
    kv_outer_kernel<<<dim3(NCHUNK, NH), 256, 2 * 65536>>>(qkv, kvp);
    // 5. exclusive prefix over chunks -> per-chunk state S
    prefix_kernel<<<(NH * HD * HD) / 256, 256>>>(kvp, S);
    // 6. intra-chunk masked attention + inter-chunk q@S
    attn_chunk_kernel<<<dim3(NCHUNK, NH), 256, 3 * 65536>>>(qkv, S, o);
    // 7. g-norm + sigmoid gating (in place over gate)
    gate_norm_kernel<<<T_TOK, 256>>>(o, gate, gw);
    // 8. out = gated @ Wo
    sgemm128<0><<<dim3(HID / 128, T_TOK / 128), 256>>>(gate, Wo, out, T_TOK, HID, INNER);
}

// round 13
// speedup vs baseline: 1.4902x; 1.4896x over previous
#include <cuda_runtime.h>
#include <cuda_bf16.h>
#include <mma.h>
#include <cstdint>
#include <math.h>

using namespace nvcuda;

// ---------------------------------------------------------------------------
// Problem constants
// ---------------------------------------------------------------------------
#define T_TOK   8192
#define HID     2048
#define NH      16
#define HD      128
#define INNER   2048          // NH*HD
#define QKV_W   6144          // 3*INNER
#define NCHUNK  64            // T/128
#define CHUNK   128
#define EPS     1e-5f
#define QSCALE  0.08838834764831845f   // 128^-0.5

// ---------------------------------------------------------------------------
// Device scratch (static globals: allocation-free rule)
// ---------------------------------------------------------------------------
__device__ float g_qkv [T_TOK * QKV_W];            // silu(x@Wqkv), q/k rope'd in place
__device__ float g_gate[T_TOK * INNER];            // x@Wg, then gated value
__device__ float g_o   [T_TOK * INNER];            // attention output
__device__ float g_kvp [NCHUNK * NH * HD * HD];    // per-chunk KV outer products
__device__ float g_S   [NCHUNK * NH * HD * HD];    // exclusive prefix state

// ---------------------------------------------------------------------------
// cp.async helpers (Ampere+, no arch-specific feature gating)
// ---------------------------------------------------------------------------
__device__ __forceinline__ uint32_t smem_u32(const void* p) {
    uint32_t a;
    asm("{ .reg .u64 t; cvta.to.shared.u64 t, %1; cvt.u32.u64 %0, t; }" : "=r"(a) : "l"(p));
    return a;
}
#define CP_ASYNC16(sdst, gsrc) \
    asm volatile("cp.async.cg.shared.global [%0], [%1], 16;" :: "r"(sdst), "l"(gsrc) : "memory")
#define CP_COMMIT() asm volatile("cp.async.commit_group;" ::: "memory")
#define CP_WAIT1()  asm volatile("cp.async.wait_group 1;" ::: "memory")

// ---------------------------------------------------------------------------
// WMMA TF32 GEMM: C[M,N] = act(A[M,K] @ B[K,N]),  B in natural [K,N] layout
// 128x128 block tile, BK=32, 8 warps (4x2), warp tile 32x64 (2x4 wmma frags)
// double-buffered cp.async pipeline. ACT: 0 = none, 1 = silu
// ---------------------------------------------------------------------------
#define BM 128
#define BN 128
#define BK 32
#define AS_LDM 40                 // 32 + 8 skew  (row = 160B, 16B aligned)
#define BS_LDM 136                // 128 + 8 skew (row = 544B, 16B aligned)
#define CS_LDM 132
#define STAGE_A (BM * AS_LDM)     // 5120 floats
#define STAGE_B (BK * BS_LDM)     // 4352 floats
#define OFF_A0  0
#define OFF_A1  STAGE_A
#define OFF_B0  (2 * STAGE_A)
#define OFF_B1  (2 * STAGE_A + STAGE_B)
#define GSM_FLOATS (2 * STAGE_A + 2 * STAGE_B)   // 18944 floats = 75776 B
#define GSM_BYTES  (GSM_FLOATS * 4)

__device__ __forceinline__ void g_load_stage(float* sm, int slot, int tid,
                                             const float* __restrict__ ag, int K,
                                             const float* __restrict__ bg, int N)
{
    // A tile: BM x BK, 1024 float4, 4 per thread
    uint32_t sa = smem_u32(sm + (slot ? OFF_A1 : OFF_A0));
    #pragma unroll
    for (int r = 0; r < 4; r++) {
        int idx = r * 256 + tid;            // 0..1023
        int row = idx >> 3;                 // 0..127
        int c   = (idx & 7) << 2;           // 0,4,..,28
        CP_ASYNC16(sa + (uint32_t)(row * AS_LDM + c) * 4, ag + (long)row * K + c);
    }
    // B tile: BK x BN, 1024 float4, 4 per thread
    uint32_t sb = smem_u32(sm + (slot ? OFF_B1 : OFF_B0));
    #pragma unroll
    for (int r = 0; r < 4; r++) {
        int idx = r * 256 + tid;
        int row = idx >> 5;                 // 0..31 (k)
        int c   = (idx & 31) << 2;          // 0..124 (n)
        CP_ASYNC16(sb + (uint32_t)(row * BS_LDM + c) * 4, bg + (long)row * N + c);
    }
}

template<int ACT>
__global__ __launch_bounds__(256, 2)
void wmma_gemm(const float* __restrict__ A, const float* __restrict__ B,
               float* __restrict__ C, int M, int N, int K)
{
    extern __shared__ float sm[];
    const int tid = threadIdx.x;
    const int wid = tid >> 5;
    const int wr  = wid >> 1;       // 0..3  -> warp row block (32 rows)
    const int wc  = wid & 1;        // 0..1  -> warp col block (64 cols)
    const long bm = (long)blockIdx.y * BM;
    const long bn = (long)blockIdx.x * BN;

    const float* Ab = A + bm * K;
    const float* Bb = B + bn;
    const int nk = K / BK;

    wmma::fragment<wmma::accumulator, 16, 16, 8, float> acc[2][4];
    #pragma unroll
    for (int i = 0; i < 2; i++)
        #pragma unroll
        for (int j = 0; j < 4; j++)
            wmma::fill_fragment(acc[i][j], 0.0f);

    g_load_stage(sm, 0, tid, Ab, K, Bb, N);            CP_COMMIT();
    g_load_stage(sm, 1, tid, Ab + BK, K, Bb + (long)BK * N, N);  CP_COMMIT();

    for (int ks = 0; ks < nk; ks++) {
        const int slot = ks & 1;
        CP_WAIT1();
        __syncthreads();

        const float* As = sm + (slot ? OFF_A1 : OFF_A0);
        const float* Bs = sm + (slot ? OFF_B1 : OFF_B0);

        #pragma unroll
        for (int kk = 0; kk < BK / 8; kk++) {
            wmma::fragment<wmma::matrix_a, 16, 16, 8, wmma::precision::tf32, wmma::row_major> af[2];
            wmma::fragment<wmma::matrix_b, 16, 16, 8, wmma::precision::tf32, wmma::row_major> bf[4];
            #pragma unroll
            for (int i = 0; i < 2; i++) {
                wmma::load_matrix_sync(af[i], As + (wr * 32 + i * 16) * AS_LDM + kk * 8, AS_LDM);
                #pragma unroll
                for (int t = 0; t < af[i].num_elements; t++)
                    af[i].x[t] = wmma::__float_to_tf32(af[i].x[t]);
            }
            #pragma unroll
            for (int j = 0; j < 4; j++) {
                wmma::load_matrix_sync(bf[j], Bs + (kk * 8) * BS_LDM + wc * 64 + j * 16, BS_LDM);
                #pragma unroll
                for (int t = 0; t < bf[j].num_elements; t++)
                    bf[j].x[t] = wmma::__float_to_tf32(bf[j].x[t]);
            }
            #pragma unroll
            for (int i = 0; i < 2; i++)
                #pragma unroll
                for (int j = 0; j < 4; j++)
                    wmma::mma_sync(acc[i][j], af[i], bf[j], acc[i][j]);
        }
        __syncthreads();
        if (ks + 2 < nk)
            g_load_stage(sm, slot, tid, Ab + (long)(ks + 2) * BK, K,
                         Bb + (long)(ks + 2) * BK * N, N);
        CP_COMMIT();
    }

    // epilogue: frags -> smem -> act -> coalesced global float4
    __syncthreads();
    #pragma unroll
    for (int i = 0; i < 2; i++)
        #pragma unroll
        for (int j = 0; j < 4; j++)
            wmma::store_matrix_sync(sm + (wr * 32 + i * 16) * CS_LDM + wc * 64 + j * 16,
                                    acc[i][j], CS_LDM, wmma::mem_row_major);
    __syncthreads();

    #pragma unroll
    for (int p = 0; p < 16; p++) {
        int fid = p * 256 + tid;            // 0..4095
        int row = fid >> 5;
        int col = (fid & 31) << 2;
        float4 v = *(const float4*)&sm[row * CS_LDM + col];
        if (ACT == 1) {
            v.x = v.x / (1.f + expf(-v.x));
            v.y = v.y / (1.f + expf(-v.y));
            v.z = v.z / (1.f + expf(-v.z));
            v.w = v.w / (1.f + expf(-v.w));
        }
        *(float4*)(C + (bm + row) * N + bn + col) = v;
    }
}

// ---------------------------------------------------------------------------
// Per-(token, head) RMSNorm + RoPE (+ q scale), in place on g_qkv
// ---------------------------------------------------------------------------
__global__ void qk_rope_kernel(float* __restrict__ qkv,
                               const int* __restrict__ pos,
                               const float* __restrict__ qw,
                               const float* __restrict__ kw)
{
    const int t = blockIdx.x, h = blockIdx.y;
    const int j = threadIdx.x;              // 0..63
    float* qp = qkv + (long)t * QKV_W + h * HD;
    float* kp = qp + INNER;

    float q1 = qp[j], q2 = qp[j + 64];
    float k1 = kp[j], k2 = kp[j + 64];

    float sq = q1*q1 + q2*q2;
    float sk = k1*k1 + k2*k2;
    #pragma unroll
    for (int o = 16; o; o >>= 1) {
        sq += __shfl_xor_sync(0xffffffffu, sq, o);
        sk += __shfl_xor_sync(0xffffffffu, sk, o);
    }
    __shared__ float red[4];
    const int w = j >> 5, lane = j & 31;
    if (lane == 0) { red[w] = sq; red[2 + w] = sk; }
    __syncthreads();
    const float rq = rsqrtf((red[0] + red[1]) * (1.f / 128.f) + EPS);
    const float rk = rsqrtf((red[2] + red[3]) * (1.f / 128.f) + EPS);

    q1 = q1 * rq * qw[j]; q2 = q2 * rq * qw[j + 64];
    k1 = k1 * rk * kw[j]; k2 = k2 * rk * kw[j + 64];

    const float inv = powf(600000.0f, -(float)j * (1.0f / 64.0f));
    const float ang = (float)pos[t] * inv;
    float s, c;
    sincosf(ang, &s, &c);

    qp[j]      = (q1 * c - q2 * s) * QSCALE;
    qp[j + 64] = (q2 * c + q1 * s) * QSCALE;
    kp[j]      =  k1 * c - k2 * s;
    kp[j + 64] =  k2 * c + k1 * s;
}

// ---------------------------------------------------------------------------
// Per-(chunk, head) KV outer product
// ---------------------------------------------------------------------------
__global__ __launch_bounds__(256, 1)
void kv_outer_kernel(const float* __restrict__ qkv, float* __restrict__ KV)
{
    extern __shared__ float sm[];
    float* sK = sm;            // [j][d]
    float* sV = sm + 16384;    // [j][e]

    const int c = blockIdx.x, h = blockIdx.y;
    const int t0 = c * CHUNK;
    const int tid = threadIdx.x, tx = tid & 15, ty = tid >> 4;

    const float* kg = qkv + (long)t0 * QKV_W + h * HD + INNER;
    const float* vg = kg + INNER;

    #pragma unroll
    for (int r = 0; r < 16; r++) {
        int idx = r * 256 + tid;
        int row = idx >> 5;
        int col = (idx & 31) << 2;
        *(float4*)&sK[row * 128 + col] = *(const float4*)(kg + (long)row * QKV_W + col);
        *(float4*)&sV[row * 128 + col] = *(const float4*)(vg + (long)row * QKV_W + col);
    }
    __syncthreads();

    float acc[8][8];
    #pragma unroll
    for (int i = 0; i < 8; i++)
        #pragma unroll
        for (int j = 0; j < 8; j++) acc[i][j] = 0.f;

    for (int j = 0; j < 128; j++) {
        float a[8], b[8];
        *(float4*)&a[0] = *(const float4*)&sK[j * 128 + ty*8];
        *(float4*)&a[4] = *(const float4*)&sK[j * 128 + ty*8 + 4];
        *(float4*)&b[0] = *(const float4*)&sV[j * 128 + tx*8];
        *(float4*)&b[4] = *(const float4*)&sV[j * 128 + tx*8 + 4];
        #pragma unroll
        for (int i = 0; i < 8; i++)
            #pragma unroll
            for (int e = 0; e < 8; e++)
                acc[i][e] += a[i] * b[e];
    }

    float* out = KV + ((long)c * NH + h) * (HD * HD);
    #pragma unroll
    for (int i = 0; i < 8; i++) {
        float4 r0 = make_float4(acc[i][0], acc[i][1], acc[i][2], acc[i][3]);
        float4 r1 = make_float4(acc[i][4], acc[i][5], acc[i][6], acc[i][7]);
        *(float4*)&out[(ty*8 + i) * 128 + tx*8]     = r0;
        *(float4*)&out[(ty*8 + i) * 128 + tx*8 + 4] = r1;
    }
}

// ---------------------------------------------------------------------------
// Exclusive prefix over chunks
// ---------------------------------------------------------------------------
__global__ void prefix_kernel(const float* __restrict__ KV, float* __restrict__ S)
{
    const int idx = blockIdx.x * 256 + threadIdx.x;
    float acc = 0.f;
    #pragma unroll 4
    for (int c = 0; c < NCHUNK; c++) {
        S[(long)c * (NH * HD * HD) + idx] = acc;
        acc += KV[(long)c * (NH * HD * HD) + idx];
    }
}

// ---------------------------------------------------------------------------
// Per-(chunk, head) attention (intra + inter-chunk)
// ---------------------------------------------------------------------------
__global__ __launch_bounds__(256, 1)
void attn_chunk_kernel(const float* __restrict__ qkv, const float* __restrict__ S,
                       float* __restrict__ O)
{
    extern __shared__ float sm[];
    float* sQ = sm;             // qT [d][i]
    float* sB = sm + 16384;     // kT [d][j], then v [j][e]
    float* sC = sm + 32768;     // scoresT [j][i], then S [d][e]

    const int c = blockIdx.x, h = blockIdx.y;
    const int t0 = c * CHUNK;
    const int tid = threadIdx.x, tx = tid & 15, ty = tid >> 4;

    const float* qg = qkv + (long)t0 * QKV_W + h * HD;
    const float* kg = qg + INNER;
    const float* vg = qg + 2 * INNER;

    #pragma unroll
    for (int r = 0; r < 16; r++) {
        int idx = r * 256 + tid;
        int i  = idx >> 5;
        int dd = (idx & 31) << 2;
        float4 q4 = *(const float4*)(qg + (long)i * QKV_W + dd);
        float4 k4 = *(const float4*)(kg + (long)i * QKV_W + dd);
        sQ[(dd+0)*128 + i] = q4.x; sQ[(dd+1)*128 + i] = q4.y;
        sQ[(dd+2)*128 + i] = q4.z; sQ[(dd+3)*128 + i] = q4.w;
        sB[(dd+0)*128 + i] = k4.x; sB[(dd+1)*128 + i] = k4.y;
        sB[(dd+2)*128 + i] = k4.z; sB[(dd+3)*128 + i] = k4.w;
    }
    __syncthreads();

    {
        float acc[8][8];
        #pragma unroll
        for (int a = 0; a < 8; a++)
            #pragma unroll
            for (int b = 0; b < 8; b++) acc[a][b] = 0.f;

        for (int d = 0; d < 128; d++) {
            float a[8], b[8];
            *(float4*)&a[0] = *(const float4*)&sB[d * 128 + ty*8];
            *(float4*)&a[4] = *(const float4*)&sB[d * 128 + ty*8 + 4];
            *(float4*)&b[0] = *(const float4*)&sQ[d * 128 + tx*8];
            *(float4*)&b[4] = *(const float4*)&sQ[d * 128 + tx*8 + 4];
            #pragma unroll
            for (int jj = 0; jj < 8; jj++)
                #pragma unroll
                for (int ii = 0; ii < 8; ii++)
                    acc[jj][ii] += a[jj] * b[ii];
        }
        __syncthreads();
        #pragma unroll
        for (int jj = 0; jj < 8; jj++) {
            int j = ty*8 + jj;
            #pragma unroll
            for (int ii = 0; ii < 8; ii++) {
                int i = tx*8 + ii;
                sC[j * 128 + i] = (i >= j) ? acc[jj][ii] : 0.f;
            }
        }
    }
    __syncthreads();

    #pragma unroll
    for (int r = 0; r < 16; r++) {
        int idx = r * 256 + tid;
        int row = idx >> 5;
        int col = (idx & 31) << 2;
        *(float4*)&sB[row * 128 + col] = *(const float4*)(vg + (long)row * QKV_W + col);
    }
    __syncthreads();

    float o[8][8];
    #pragma unroll
    for (int a = 0; a < 8; a++)
        #pragma unroll
        for (int b = 0; b < 8; b++) o[a][b] = 0.f;

    for (int j = 0; j < 128; j++) {
        float a[8], b[8];
        *(float4*)&a[0] = *(const float4*)&sC[j * 128 + ty*8];
        *(float4*)&a[4] = *(const float4*)&sC[j * 128 + ty*8 + 4];
        *(float4*)&b[0] = *(const float4*)&sB[j * 128 + tx*8];
        *(float4*)&b[4] = *(const float4*)&sB[j * 128 + tx*8 + 4];
        #pragma unroll
        for (int ii = 0; ii < 8; ii++)
            #pragma unroll
            for (int ee = 0; ee < 8; ee++)
                o[ii][ee] += a[ii] * b[ee];
    }
    __syncthreads();

    const float* Sg = S + ((long)c * NH + h) * (HD * HD);
    #pragma unroll
    for (int r = 0; r < 16; r++) {
        int idx = r * 256 + tid;
        int row = idx >> 5;
        int col = (idx & 31) << 2;
        *(float4*)&sC[row * 128 + col] = *(const float4*)(Sg + row * 128 + col);
    }
    __syncthreads();

    for (int d = 0; d < 128; d++) {
        float a[8], b[8];
        *(float4*)&a[0] = *(const float4*)&sQ[d * 128 + ty*8];
        *(float4*)&a[4] = *(const float4*)&sQ[d * 128 + ty*8 + 4];
        *(float4*)&b[0] = *(const float4*)&sC[d * 128 + tx*8];
        *(float4*)&b[4] = *(const float4*)&sC[d * 128 + tx*8 + 4];
        #pragma unroll
        for (int ii = 0; ii < 8; ii++)
            #pragma unroll
            for (int ee = 0; ee < 8; ee++)
                o[ii][ee] += a[ii] * b[ee];
    }

    #pragma unroll
    for (int ii = 0; ii < 8; ii++) {
        float* Op = O + (long)(t0 + ty*8 + ii) * INNER + h * HD + tx*8;
        *(float4*)(Op)     = make_float4(o[ii][0], o[ii][1], o[ii][2], o[ii][3]);
        *(float4*)(Op + 4) = make_float4(o[ii][4], o[ii][5], o[ii][6], o[ii][7]);
    }
}

// ---------------------------------------------------------------------------
// Per-token g-norm + sigmoid gate (in place over g_gate)
// ---------------------------------------------------------------------------
__global__ __launch_bounds__(256)
void gate_norm_kernel(const float* __restrict__ O, float* __restrict__ G,
                      const float* __restrict__ gw)
{
    const int t = blockIdx.x;
    const int tid = threadIdx.x;
    const float* orow = O + (long)t * INNER;
    float* grow = G + (long)t * INNER;

    float4 o0 = *(const float4*)(orow + tid * 4);
    float4 o1 = *(const float4*)(orow + 1024 + tid * 4);

    float s = o0.x*o0.x + o0.y*o0.y + o0.z*o0.z + o0.w*o0.w
            + o1.x*o1.x + o1.y*o1.y + o1.z*o1.z + o1.w*o1.w;
    #pragma unroll
    for (int o = 16; o; o >>= 1) s += __shfl_xor_sync(0xffffffffu, s, o);
    __shared__ float red[8];
    if ((tid & 31) == 0) red[tid >> 5] = s;
    __syncthreads();
    float tot = 0.f;
    #pragma unroll
    for (int w = 0; w < 8; w++) tot += red[w];
    const float rs = rsqrtf(tot * (1.f / 2048.f) + EPS);

    float4 g0 = *(const float4*)(grow + tid * 4);
    float4 g1 = *(const float4*)(grow + 1024 + tid * 4);
    float4 w0 = *(const float4*)(gw + tid * 4);
    float4 w1 = *(const float4*)(gw + 1024 + tid * 4);

    float4 r0, r1;
    r0.x = (1.f / (1.f + expf(-g0.x))) * o0.x * rs * w0.x;
    r0.y = (1.f / (1.f + expf(-g0.y))) * o0.y * rs * w0.y;
    r0.z = (1.f / (1.f + expf(-g0.z))) * o0.z * rs * w0.z;
    r0.w = (1.f / (1.f + expf(-g0.w))) * o0.w * rs * w0.w;
    r1.x = (1.f / (1.f + expf(-g1.x))) * o1.x * rs * w1.x;
    r1.y = (1.f / (1.f + expf(-g1.y))) * o1.y * rs * w1.y;
    r1.z = (1.f / (1.f + expf(-g1.z))) * o1.z * rs * w1.z;
    r1.w = (1.f / (1.f + expf(-g1.w))) * o1.w * rs * w1.w;

    *(float4*)(grow + tid * 4)        = r0;
    *(float4*)(grow + 1024 + tid * 4) = r1;
}

// ---------------------------------------------------------------------------
// Launch
// ---------------------------------------------------------------------------
extern "C" void kernel_launch(void* const* d_in, const int* in_sizes, int n_in,
                              void* d_out, int out_size)
{
    const float* x    = (const float*)d_in[0];   // [8192, 2048]
    const int*   pos  = (const int*)  d_in[1];   // [8192]
    const float* Wqkv = (const float*)d_in[2];   // [2048, 6144]
    const float* qw   = (const float*)d_in[3];   // [128]
    const float* kw   = (const float*)d_in[4];   // [128]
    const float* Wg   = (const float*)d_in[5];   // [2048, 2048]
    const float* gw   = (const float*)d_in[6];   // [2048]
    const float* Wo   = (const float*)d_in[7];   // [2048, 2048]
    float* out = (float*)d_out;                  // [8192, 2048]

    float* qkv;  cudaGetSymbolAddress((void**)&qkv,  g_qkv);
    float* gate; cudaGetSymbolAddress((void**)&gate, g_gate);
    float* o;    cudaGetSymbolAddress((void**)&o,    g_o);
    float* kvp;  cudaGetSymbolAddress((void**)&kvp,  g_kvp);
    float* S;    cudaGetSymbolAddress((void**)&S,    g_S);

    cudaFuncSetAttribute(kv_outer_kernel,
                         cudaFuncAttributeMaxDynamicSharedMemorySize, 2 * 65536);
    cudaFuncSetAttribute(attn_chunk_kernel,
                         cudaFuncAttributeMaxDynamicSharedMemorySize, 3 * 65536);
    cudaFuncSetAttribute(wmma_gemm<0>,
                         cudaFuncAttributeMaxDynamicSharedMemorySize, GSM_BYTES);
    cudaFuncSetAttribute(wmma_gemm<1>,
                         cudaFuncAttributeMaxDynamicSharedMemorySize, GSM_BYTES);

    // 1. qkv = silu(x @ Wqkv)          [HMMA tf32]
    wmma_gemm<1><<<dim3(QKV_W / BN, T_TOK / BM), 256, GSM_BYTES>>>(x, Wqkv, qkv, T_TOK, QKV_W, HID);
    // 2. gate = x @ Wg                 [HMMA tf32]
    wmma_gemm<0><<<dim3(INNER / BN, T_TOK / BM), 256, GSM_BYTES>>>(x, Wg, gate, T_TOK, INNER, HID);
    // 3. per-head rmsnorm + rope (+ q scale), in place
    qk_rope_kernel<<<dim3(T_TOK, NH), 64>>>(qkv, pos, qw, kw);
    // 4. per-chunk KV outer products
    kv_outer_kernel<<<dim3(NCHUNK, NH), 256, 2 * 65536>>>(qkv, kvp);
    // 5. exclusive prefix over chunks -> per-chunk state S
    prefix_kernel<<<(NH * HD * HD) / 256, 256>>>(kvp, S);
    // 6. intra-chunk masked attention + inter-chunk q@S
    attn_chunk_kernel<<<dim3(NCHUNK, NH), 256, 3 * 65536>>>(qkv, S, o);
    // 7. g-norm + sigmoid gating (in place over gate)
    gate_norm_kernel<<<T_TOK, 256>>>(o, gate, gw);
    // 8. out = gated @ Wo              [HMMA tf32]
    wmma_gemm<0><<<dim3(HID / BN, T_TOK / BM), 256, GSM_BYTES>>>(gate, Wo, out, T_TOK, HID, INNER);
}

// round 14
// speedup vs baseline: 1.5066x; 1.0110x over previous
#include <cuda_runtime.h>
#include <cuda_bf16.h>
#include <mma.h>
#include <cstdint>
#include <math.h>

using namespace nvcuda;

// ---------------------------------------------------------------------------
// Problem constants
// ---------------------------------------------------------------------------
#define T_TOK   8192
#define HID     2048
#define NH      16
#define HD      128
#define INNER   2048          // NH*HD
#define QKV_W   6144          // 3*INNER
#define NCHUNK  64            // T/128
#define CHUNK   128
#define EPS     1e-5f
#define QSCALE  0.08838834764831845f   // 128^-0.5

// ---------------------------------------------------------------------------
// Device scratch (static globals: allocation-free rule)
// ---------------------------------------------------------------------------
__device__ float g_qkv [T_TOK * QKV_W];            // silu(x@Wqkv), q/k rope'd in place
__device__ float g_gate[T_TOK * INNER];            // x@Wg, then gated (tf32-rounded) value
__device__ float g_o   [T_TOK * INNER];            // attention output
__device__ float g_kvp [NCHUNK * NH * HD * HD];    // per-chunk KV outer products
__device__ float g_S   [NCHUNK * NH * HD * HD];    // exclusive prefix state
__device__ float g_xr    [T_TOK * HID];            // tf32-rounded x
__device__ float g_Wqkvr [HID * QKV_W];            // tf32-rounded weights
__device__ float g_Wgr   [HID * INNER];
__device__ float g_Wor   [INNER * HID];

// ---------------------------------------------------------------------------
// cp.async helpers (Ampere+, no arch-specific feature gating)
// ---------------------------------------------------------------------------
__device__ __forceinline__ uint32_t smem_u32(const void* p) {
    uint32_t a;
    asm("{ .reg .u64 t; cvta.to.shared.u64 t, %1; cvt.u32.u64 %0, t; }" : "=r"(a) : "l"(p));
    return a;
}
#define CP_ASYNC16(sdst, gsrc) \
    asm volatile("cp.async.cg.shared.global [%0], [%1], 16;" :: "r"(sdst), "l"(gsrc) : "memory")
#define CP_COMMIT() asm volatile("cp.async.commit_group;" ::: "memory")
#define CP_WAIT2()  asm volatile("cp.async.wait_group 2;" ::: "memory")

// ---------------------------------------------------------------------------
// Elementwise tf32 rounding pass: out[i] = round_tf32(in[i])
// ---------------------------------------------------------------------------
__global__ __launch_bounds__(256)
void tf32_round_kernel(const float* __restrict__ in, float* __restrict__ out)
{
    const long i = ((long)blockIdx.x * 256 + threadIdx.x) * 4;
    float4 v = *(const float4*)(in + i);
    v.x = wmma::__float_to_tf32(v.x);
    v.y = wmma::__float_to_tf32(v.y);
    v.z = wmma::__float_to_tf32(v.z);
    v.w = wmma::__float_to_tf32(v.w);
    *(float4*)(out + i) = v;
}

// ---------------------------------------------------------------------------
// WMMA TF32 GEMM: C[M,N] = act(A[M,K] @ B[K,N]),  B in natural [K,N] layout.
// Operands MUST be pre-rounded to tf32 (no per-fragment converts).
// 128x256 block tile, BK=32, 8 warps (2x4), warp tile 64x64 (4x4 wmma frags)
// 3-stage cp.async pipeline. ACT: 0 = none, 1 = silu
// ---------------------------------------------------------------------------
#define BM 128
#define BN 256
#define BK 32
#define AS_LDM 40                  // 32 + 8 skew
#define BS_LDM 264                 // 256 + 8 skew
#define CS_LDM 264
#define STAGE_A (BM * AS_LDM)      // 5120 floats
#define STAGE_B (BK * BS_LDM)      // 8448 floats
#define OFF_A(s) ((s) * STAGE_A)
#define OFF_B(s) (3 * STAGE_A + (s) * STAGE_B)
#define GSM_FLOATS (3 * STAGE_A + 3 * STAGE_B)   // 40704 floats
#define GSM_BYTES  (GSM_FLOATS * 4)              // 162816 B

__device__ __forceinline__ void g_load_stage(float* sm, int slot, int tid,
                                             const float* __restrict__ ag, int K,
                                             const float* __restrict__ bg, int N)
{
    // A tile: BM x BK = 1024 float4, 4 per thread
    uint32_t sa = smem_u32(sm + OFF_A(slot));
    #pragma unroll
    for (int r = 0; r < 4; r++) {
        int idx = r * 256 + tid;            // 0..1023
        int row = idx >> 3;                 // 0..127
        int c   = (idx & 7) << 2;           // 0,4,..,28
        CP_ASYNC16(sa + (uint32_t)(row * AS_LDM + c) * 4, ag + (long)row * K + c);
    }
    // B tile: BK x BN = 2048 float4, 8 per thread
    uint32_t sb = smem_u32(sm + OFF_B(slot));
    #pragma unroll
    for (int r = 0; r < 8; r++) {
        int idx = r * 256 + tid;            // 0..2047
        int row = idx >> 6;                 // 0..31 (k)
        int c   = (idx & 63) << 2;          // 0..252 (n)
        CP_ASYNC16(sb + (uint32_t)(row * BS_LDM + c) * 4, bg + (long)row * N + c);
    }
}

template<int ACT>
__global__ __launch_bounds__(256)
void wmma_gemm(const float* __restrict__ A, const float* __restrict__ B,
               float* __restrict__ C, int M, int N, int K)
{
    extern __shared__ float sm[];
    const int tid = threadIdx.x;
    const int wid = tid >> 5;
    const int wr  = wid >> 2;       // 0..1 -> warp row block (64 rows)
    const int wc  = wid & 3;        // 0..3 -> warp col block (64 cols)
    const long bm = (long)blockIdx.y * BM;
    const long bn = (long)blockIdx.x * BN;

    const float* Ab = A + bm * K;
    const float* Bb = B + bn;
    const int nk = K / BK;

    wmma::fragment<wmma::accumulator, 16, 16, 8, float> acc[4][4];
    #pragma unroll
    for (int i = 0; i < 4; i++)
        #pragma unroll
        for (int j = 0; j < 4; j++)
            wmma::fill_fragment(acc[i][j], 0.0f);

    g_load_stage(sm, 0, tid, Ab, K, Bb, N);                       CP_COMMIT();
    g_load_stage(sm, 1, tid, Ab + BK, K, Bb + (long)BK * N, N);   CP_COMMIT();
    g_load_stage(sm, 2, tid, Ab + 2 * BK, K, Bb + (long)(2 * BK) * N, N); CP_COMMIT();

    for (int ks = 0; ks < nk; ks++) {
        const int slot = ks % 3;
        CP_WAIT2();
        __syncthreads();

        const float* As = sm + OFF_A(slot);
        const float* Bs = sm + OFF_B(slot);

        #pragma unroll
        for (int kk = 0; kk < BK / 8; kk++) {
            wmma::fragment<wmma::matrix_a, 16, 16, 8, wmma::precision::tf32, wmma::row_major> af[4];
            wmma::fragment<wmma::matrix_b, 16, 16, 8, wmma::precision::tf32, wmma::row_major> bf[4];
            #pragma unroll
            for (int i = 0; i < 4; i++)
                wmma::load_matrix_sync(af[i], As + (wr * 64 + i * 16) * AS_LDM + kk * 8, AS_LDM);
            #pragma unroll
            for (int j = 0; j < 4; j++)
                wmma::load_matrix_sync(bf[j], Bs + (kk * 8) * BS_LDM + wc * 64 + j * 16, BS_LDM);
            #pragma unroll
            for (int i = 0; i < 4; i++)
                #pragma unroll
                for (int j = 0; j < 4; j++)
                    wmma::mma_sync(acc[i][j], af[i], bf[j], acc[i][j]);
        }
        __syncthreads();
        if (ks + 3 < nk)
            g_load_stage(sm, slot, tid, Ab + (long)(ks + 3) * BK, K,
                         Bb + (long)(ks + 3) * BK * N, N);
        CP_COMMIT();
    }

    // epilogue: frags -> smem -> act -> coalesced global float4
    __syncthreads();
    #pragma unroll
    for (int i = 0; i < 4; i++)
        #pragma unroll
        for (int j = 0; j < 4; j++)
            wmma::store_matrix_sync(sm + (wr * 64 + i * 16) * CS_LDM + wc * 64 + j * 16,
                                    acc[i][j], CS_LDM, wmma::mem_row_major);
    __syncthreads();

    #pragma unroll
    for (int p = 0; p < 32; p++) {
        int fid = p * 256 + tid;            // 0..8191 float4s
        int row = fid >> 6;
        int col = (fid & 63) << 2;
        float4 v = *(const float4*)&sm[row * CS_LDM + col];
        if (ACT == 1) {
            v.x = v.x / (1.f + expf(-v.x));
            v.y = v.y / (1.f + expf(-v.y));
            v.z = v.z / (1.f + expf(-v.z));
            v.w = v.w / (1.f + expf(-v.w));
        }
        *(float4*)(C + (bm + row) * N + bn + col) = v;
    }
}

// ---------------------------------------------------------------------------
// Per-(token, head) RMSNorm + RoPE (+ q scale), in place on g_qkv
// ---------------------------------------------------------------------------
__global__ void qk_rope_kernel(float* __restrict__ qkv,
                               const int* __restrict__ pos,
                               const float* __restrict__ qw,
                               const float* __restrict__ kw)
{
    const int t = blockIdx.x, h = blockIdx.y;
    const int j = threadIdx.x;              // 0..63
    float* qp = qkv + (long)t * QKV_W + h * HD;
    float* kp = qp + INNER;

    float q1 = qp[j], q2 = qp[j + 64];
    float k1 = kp[j], k2 = kp[j + 64];

    float sq = q1*q1 + q2*q2;
    float sk = k1*k1 + k2*k2;
    #pragma unroll
    for (int o = 16; o; o >>= 1) {
        sq += __shfl_xor_sync(0xffffffffu, sq, o);
        sk += __shfl_xor_sync(0xffffffffu, sk, o);
    }
    __shared__ float red[4];
    const int w = j >> 5, lane = j & 31;
    if (lane == 0) { red[w] = sq; red[2 + w] = sk; }
    __syncthreads();
    const float rq = rsqrtf((red[0] + red[1]) * (1.f / 128.f) + EPS);
    const float rk = rsqrtf((red[2] + red[3]) * (1.f / 128.f) + EPS);

    q1 = q1 * rq * qw[j]; q2 = q2 * rq * qw[j + 64];
    k1 = k1 * rk * kw[j]; k2 = k2 * rk * kw[j + 64];

    const float inv = powf(600000.0f, -(float)j * (1.0f / 64.0f));
    const float ang = (float)pos[t] * inv;
    float s, c;
    sincosf(ang, &s, &c);

    qp[j]      = (q1 * c - q2 * s) * QSCALE;
    qp[j + 64] = (q2 * c + q1 * s) * QSCALE;
    kp[j]      =  k1 * c - k2 * s;
    kp[j + 64] =  k2 * c + k1 * s;
}

// ---------------------------------------------------------------------------
// Per-(chunk, head) KV outer product
// ---------------------------------------------------------------------------
__global__ __launch_bounds__(256, 1)
void kv_outer_kernel(const float* __restrict__ qkv, float* __restrict__ KV)
{
    extern __shared__ float sm[];
    float* sK = sm;            // [j][d]
    float* sV = sm + 16384;    // [j][e]

    const int c = blockIdx.x, h = blockIdx.y;
    const int t0 = c * CHUNK;
    const int tid = threadIdx.x, tx = tid & 15, ty = tid >> 4;

    const float* kg = qkv + (long)t0 * QKV_W + h * HD + INNER;
    const float* vg = kg + INNER;

    #pragma unroll
    for (int r = 0; r < 16; r++) {
        int idx = r * 256 + tid;
        int row = idx >> 5;
        int col = (idx & 31) << 2;
        *(float4*)&sK[row * 128 + col] = *(const float4*)(kg + (long)row * QKV_W + col);
        *(float4*)&sV[row * 128 + col] = *(const float4*)(vg + (long)row * QKV_W + col);
    }
    __syncthreads();

    float acc[8][8];
    #pragma unroll
    for (int i = 0; i < 8; i++)
        #pragma unroll
        for (int j = 0; j < 8; j++) acc[i][j] = 0.f;

    for (int j = 0; j < 128; j++) {
        float a[8], b[8];
        *(float4*)&a[0] = *(const float4*)&sK[j * 128 + ty*8];
        *(float4*)&a[4] = *(const float4*)&sK[j * 128 + ty*8 + 4];
        *(float4*)&b[0] = *(const float4*)&sV[j * 128 + tx*8];
        *(float4*)&b[4] = *(const float4*)&sV[j * 128 + tx*8 + 4];
        #pragma unroll
        for (int i = 0; i < 8; i++)
            #pragma unroll
            for (int e = 0; e < 8; e++)
                acc[i][e] += a[i] * b[e];
    }

    float* out = KV + ((long)c * NH + h) * (HD * HD);
    #pragma unroll
    for (int i = 0; i < 8; i++) {
        float4 r0 = make_float4(acc[i][0], acc[i][1], acc[i][2], acc[i][3]);
        float4 r1 = make_float4(acc[i][4], acc[i][5], acc[i][6], acc[i][7]);
        *(float4*)&out[(ty*8 + i) * 128 + tx*8]     = r0;
        *(float4*)&out[(ty*8 + i) * 128 + tx*8 + 4] = r1;
    }
}

// ---------------------------------------------------------------------------
// Exclusive prefix over chunks
// ---------------------------------------------------------------------------
__global__ void prefix_kernel(const float* __restrict__ KV, float* __restrict__ S)
{
    const int idx = blockIdx.x * 256 + threadIdx.x;
    float acc = 0.f;
    #pragma unroll 4
    for (int c = 0; c < NCHUNK; c++) {
        S[(long)c * (NH * HD * HD) + idx] = acc;
        acc += KV[(long)c * (NH * HD * HD) + idx];
    }
}

// ---------------------------------------------------------------------------
// Per-(chunk, head) attention (intra + inter-chunk)
// ---------------------------------------------------------------------------
__global__ __launch_bounds__(256, 1)
void attn_chunk_kernel(const float* __restrict__ qkv, const float* __restrict__ S,
                       float* __restrict__ O)
{
    extern __shared__ float sm[];
    float* sQ = sm;             // qT [d][i]
    float* sB = sm + 16384;     // kT [d][j], then v [j][e]
    float* sC = sm + 32768;     // scoresT [j][i], then S [d][e]

    const int c = blockIdx.x, h = blockIdx.y;
    const int t0 = c * CHUNK;
    const int tid = threadIdx.x, tx = tid & 15, ty = tid >> 4;

    const float* qg = qkv + (long)t0 * QKV_W + h * HD;
    const float* kg = qg + INNER;
    const float* vg = qg + 2 * INNER;

    #pragma unroll
    for (int r = 0; r < 16; r++) {
        int idx = r * 256 + tid;
        int i  = idx >> 5;
        int dd = (idx & 31) << 2;
        float4 q4 = *(const float4*)(qg + (long)i * QKV_W + dd);
        float4 k4 = *(const float4*)(kg + (long)i * QKV_W + dd);
        sQ[(dd+0)*128 + i] = q4.x; sQ[(dd+1)*128 + i] = q4.y;
        sQ[(dd+2)*128 + i] = q4.z; sQ[(dd+3)*128 + i] = q4.w;
        sB[(dd+0)*128 + i] = k4.x; sB[(dd+1)*128 + i] = k4.y;
        sB[(dd+2)*128 + i] = k4.z; sB[(dd+3)*128 + i] = k4.w;
    }
    __syncthreads();

    {
        float acc[8][8];
        #pragma unroll
        for (int a = 0; a < 8; a++)
            #pragma unroll
            for (int b = 0; b < 8; b++) acc[a][b] = 0.f;

        for (int d = 0; d < 128; d++) {
            float a[8], b[8];
            *(float4*)&a[0] = *(const float4*)&sB[d * 128 + ty*8];
            *(float4*)&a[4] = *(const float4*)&sB[d * 128 + ty*8 + 4];
            *(float4*)&b[0] = *(const float4*)&sQ[d * 128 + tx*8];
            *(float4*)&b[4] = *(const float4*)&sQ[d * 128 + tx*8 + 4];
            #pragma unroll
            for (int jj = 0; jj < 8; jj++)
                #pragma unroll
                for (int ii = 0; ii < 8; ii++)
                    acc[jj][ii] += a[jj] * b[ii];
        }
        __syncthreads();
        #pragma unroll
        for (int jj = 0; jj < 8; jj++) {
            int j = ty*8 + jj;
            #pragma unroll
            for (int ii = 0; ii < 8; ii++) {
                int i = tx*8 + ii;
                sC[j * 128 + i] = (i >= j) ? acc[jj][ii] : 0.f;
            }
        }
    }
    __syncthreads();

    #pragma unroll
    for (int r = 0; r < 16; r++) {
        int idx = r * 256 + tid;
        int row = idx >> 5;
        int col = (idx & 31) << 2;
        *(float4*)&sB[row * 128 + col] = *(const float4*)(vg + (long)row * QKV_W + col);
    }
    __syncthreads();

    float o[8][8];
    #pragma unroll
    for (int a = 0; a < 8; a++)
        #pragma unroll
        for (int b = 0; b < 8; b++) o[a][b] = 0.f;

    for (int j = 0; j < 128; j++) {
        float a[8], b[8];
        *(float4*)&a[0] = *(const float4*)&sC[j * 128 + ty*8];
        *(float4*)&a[4] = *(const float4*)&sC[j * 128 + ty*8 + 4];
        *(float4*)&b[0] = *(const float4*)&sB[j * 128 + tx*8];
        *(float4*)&b[4] = *(const float4*)&sB[j * 128 + tx*8 + 4];
        #pragma unroll
        for (int ii = 0; ii < 8; ii++)
            #pragma unroll
            for (int ee = 0; ee < 8; ee++)
                o[ii][ee] += a[ii] * b[ee];
    }
    __syncthreads();

    const float* Sg = S + ((long)c * NH + h) * (HD * HD);
    #pragma unroll
    for (int r = 0; r < 16; r++) {
        int idx = r * 256 + tid;
        int row = idx >> 5;
        int col = (idx & 31) << 2;
        *(float4*)&sC[row * 128 + col] = *(const float4*)(Sg + row * 128 + col);
    }
    __syncthreads();

    for (int d = 0; d < 128; d++) {
        float a[8], b[8];
        *(float4*)&a[0] = *(const float4*)&sQ[d * 128 + ty*8];
        *(float4*)&a[4] = *(const float4*)&sQ[d * 128 + ty*8 + 4];
        *(float4*)&b[0] = *(const float4*)&sC[d * 128 + tx*8];
        *(float4*)&b[4] = *(const float4*)&sC[d * 128 + tx*8 + 4];
        #pragma unroll
        for (int ii = 0; ii < 8; ii++)
            #pragma unroll
            for (int ee = 0; ee < 8; ee++)
                o[ii][ee] += a[ii] * b[ee];
    }

    #pragma unroll
    for (int ii = 0; ii < 8; ii++) {
        float* Op = O + (long)(t0 + ty*8 + ii) * INNER + h * HD + tx*8;
        *(float4*)(Op)     = make_float4(o[ii][0], o[ii][1], o[ii][2], o[ii][3]);
        *(float4*)(Op + 4) = make_float4(o[ii][4], o[ii][5], o[ii][6], o[ii][7]);
    }
}

// ---------------------------------------------------------------------------
// Per-token g-norm + sigmoid gate (in place over g_gate)
// Output is tf32-rounded: it feeds the final GEMM's A operand.
// ---------------------------------------------------------------------------
__global__ __launch_bounds__(256)
void gate_norm_kernel(const float* __restrict__ O, float* __restrict__ G,
                      const float* __restrict__ gw)
{
    const int t = blockIdx.x;
    const int tid = threadIdx.x;
    const float* orow = O + (long)t * INNER;
    float* grow = G + (long)t * INNER;

    float4 o0 = *(const float4*)(orow + tid * 4);
    float4 o1 = *(const float4*)(orow + 1024 + tid * 4);

    float s = o0.x*o0.x + o0.y*o0.y + o0.z*o0.z + o0.w*o0.w
            + o1.x*o1.x + o1.y*o1.y + o1.z*o1.z + o1.w*o1.w;
    #pragma unroll
    for (int o = 16; o; o >>= 1) s += __shfl_xor_sync(0xffffffffu, s, o);
    __shared__ float red[8];
    if ((tid & 31) == 0) red[tid >> 5] = s;
    __syncthreads();
    float tot = 0.f;
    #pragma unroll
    for (int w = 0; w < 8; w++) tot += red[w];
    const float rs = rsqrtf(tot * (1.f / 2048.f) + EPS);

    float4 g0 = *(const float4*)(grow + tid * 4);
    float4 g1 = *(const float4*)(grow + 1024 + tid * 4);
    float4 w0 = *(const float4*)(gw + tid * 4);
    float4 w1 = *(const float4*)(gw + 1024 + tid * 4);

    float4 r0, r1;
    r0.x = wmma::__float_to_tf32((1.f / (1.f + expf(-g0.x))) * o0.x * rs * w0.x);
    r0.y = wmma::__float_to_tf32((1.f / (1.f + expf(-g0.y))) * o0.y * rs * w0.y);
    r0.z = wmma::__float_to_tf32((1.f / (1.f + expf(-g0.z))) * o0.z * rs * w0.z);
    r0.w = wmma::__float_to_tf32((1.f / (1.f + expf(-g0.w))) * o0.w * rs * w0.w);
    r1.x = wmma::__float_to_tf32((1.f / (1.f + expf(-g1.x))) * o1.x * rs * w1.x);
    r1.y = wmma::__float_to_tf32((1.f / (1.f + expf(-g1.y))) * o1.y * rs * w1.y);
    r1.z = wmma::__float_to_tf32((1.f / (1.f + expf(-g1.z))) * o1.z * rs * w1.z);
    r1.w = wmma::__float_to_tf32((1.f / (1.f + expf(-g1.w))) * o1.w * rs * w1.w);

    *(float4*)(grow + tid * 4)        = r0;
    *(float4*)(grow + 1024 + tid * 4) = r1;
}

// ---------------------------------------------------------------------------
// Launch
// ---------------------------------------------------------------------------
extern "C" void kernel_launch(void* const* d_in, const int* in_sizes, int n_in,
                              void* d_out, int out_size)
{
    const float* x    = (const float*)d_in[0];   // [8192, 2048]
    const int*   pos  = (const int*)  d_in[1];   // [8192]
    const float* Wqkv = (const float*)d_in[2];   // [2048, 6144]
    const float* qw   = (const float*)d_in[3];   // [128]
    const float* kw   = (const float*)d_in[4];   // [128]
    const float* Wg   = (const float*)d_in[5];   // [2048, 2048]
    const float* gw   = (const float*)d_in[6];   // [2048]
    const float* Wo   = (const float*)d_in[7];   // [2048, 2048]
    float* out = (float*)d_out;                  // [8192, 2048]

    float* qkv;  cudaGetSymbolAddress((void**)&qkv,  g_qkv);
    float* gate; cudaGetSymbolAddress((void**)&gate, g_gate);
    float* o;    cudaGetSymbolAddress((void**)&o,    g_o);
    float* kvp;  cudaGetSymbolAddress((void**)&kvp,  g_kvp);
    float* S;    cudaGetSymbolAddress((void**)&S,    g_S);
    float* xr;    cudaGetSymbolAddress((void**)&xr,    g_xr);
    float* Wqkvr; cudaGetSymbolAddress((void**)&Wqkvr, g_Wqkvr);
    float* Wgr;   cudaGetSymbolAddress((void**)&Wgr,   g_Wgr);
    float* Wor;   cudaGetSymbolAddress((void**)&Wor,   g_Wor);

    cudaFuncSetAttribute(kv_outer_kernel,
                         cudaFuncAttributeMaxDynamicSharedMemorySize, 2 * 65536);
    cudaFuncSetAttribute(attn_chunk_kernel,
                         cudaFuncAttributeMaxDynamicSharedMemorySize, 3 * 65536);
    cudaFuncSetAttribute(wmma_gemm<0>,
                         cudaFuncAttributeMaxDynamicSharedMemorySize, GSM_BYTES);
    cudaFuncSetAttribute(wmma_gemm<1>,
                         cudaFuncAttributeMaxDynamicSharedMemorySize, GSM_BYTES);

    // 0. pre-round GEMM operands to tf32 (removes all in-loop converts)
    tf32_round_kernel<<<(T_TOK * (long)HID) / 1024, 256>>>(x, xr);
    tf32_round_kernel<<<(HID * (long)QKV_W) / 1024, 256>>>(Wqkv, Wqkvr);
    tf32_round_kernel<<<(HID * (long)INNER) / 1024, 256>>>(Wg, Wgr);
    tf32_round_kernel<<<(INNER * (long)HID) / 1024, 256>>>(Wo, Wor);

    // 1. qkv = silu(x @ Wqkv)          [HMMA tf32]
    wmma_gemm<1><<<dim3(QKV_W / BN, T_TOK / BM), 256, GSM_BYTES>>>(xr, Wqkvr, qkv, T_TOK, QKV_W, HID);
    // 2. gate = x @ Wg                 [HMMA tf32]
    wmma_gemm<0><<<dim3(INNER / BN, T_TOK / BM), 256, GSM_BYTES>>>(xr, Wgr, gate, T_TOK, INNER, HID);
    // 3. per-head rmsnorm + rope (+ q scale), in place
    qk_rope_kernel<<<dim3(T_TOK, NH), 64>>>(qkv, pos, qw, kw);
    // 4. per-chunk KV outer products
    kv_outer_kernel<<<dim3(NCHUNK, NH), 256, 2 * 65536>>>(qkv, kvp);
    // 5. exclusive prefix over chunks -> per-chunk state S
    prefix_kernel<<<(NH * HD * HD) / 256, 256>>>(kvp, S);
    // 6. intra-chunk masked attention + inter-chunk q@S
    attn_chunk_kernel<<<dim3(NCHUNK, NH), 256, 3 * 65536>>>(qkv, S, o);
    // 7. g-norm + sigmoid gating (in place over gate, tf32-rounded output)
    gate_norm_kernel<<<T_TOK, 256>>>(o, gate, gw);
    // 8. out = gated @ Wo              [HMMA tf32]
    wmma_gemm<0><<<dim3(HID / BN, T_TOK / BM), 256, GSM_BYTES>>>(gate, Wor, out, T_TOK, HID, INNER);
}

// round 15
// speedup vs baseline: 3.0175x; 2.0028x over previous
#include <cuda_runtime.h>
#include <cuda_bf16.h>
#include <mma.h>
#include <cstdint>
#include <math.h>

// ---------------------------------------------------------------------------
// Problem constants
// ---------------------------------------------------------------------------
#define T_TOK   8192
#define HID     2048
#define NH      16
#define HD      128
#define INNER   2048          // NH*HD
#define QKV_W   6144          // 3*INNER
#define NCHUNK  64            // T/128
#define CHUNK   128
#define EPS     1e-5f
#define QSCALE  0.08838834764831845f   // 128^-0.5

// ---------------------------------------------------------------------------
// Device scratch (static globals: allocation-free rule)
// ---------------------------------------------------------------------------
__device__ float g_qkv [T_TOK * QKV_W];            // silu(x@Wqkv), q/k rope'd in place
__device__ float g_gate[T_TOK * INNER];            // x@Wg, then gated (tf32-rounded) value
__device__ float g_o   [T_TOK * INNER];            // attention output
__device__ float g_kvp [NCHUNK * NH * HD * HD];    // per-chunk KV outer products
__device__ float g_S   [NCHUNK * NH * HD * HD];    // exclusive prefix state
__device__ float g_xr    [T_TOK * HID];            // tf32-rounded x
__device__ float g_WqkvT [QKV_W * HID];            // tf32-rounded, transposed [N,K]
__device__ float g_WgT   [INNER * HID];
__device__ float g_WoT   [HID * INNER];

// ---------------------------------------------------------------------------
// PTX helpers (all non-arch-gated: sm_75+/sm_80+ instructions)
// ---------------------------------------------------------------------------
__device__ __forceinline__ uint32_t smem_u32(const void* p) {
    uint32_t a;
    asm("{ .reg .u64 t; cvta.to.shared.u64 t, %1; cvt.u32.u64 %0, t; }" : "=r"(a) : "l"(p));
    return a;
}
#define CP_ASYNC16(sdst, gsrc) \
    asm volatile("cp.async.cg.shared.global [%0], [%1], 16;" :: "r"(sdst), "l"(gsrc) : "memory")
#define CP_COMMIT() asm volatile("cp.async.commit_group;" ::: "memory")
#define CP_WAIT2()  asm volatile("cp.async.wait_group 2;" ::: "memory")

__device__ __forceinline__ void ldsm4(uint32_t* d, uint32_t addr) {
    asm volatile("ldmatrix.sync.aligned.m8n8.x4.shared.b16 {%0,%1,%2,%3}, [%4];"
                 : "=r"(d[0]), "=r"(d[1]), "=r"(d[2]), "=r"(d[3]) : "r"(addr));
}
__device__ __forceinline__ void mma_tf32(float* c, const uint32_t* a, const uint32_t* b) {
    asm volatile(
        "mma.sync.aligned.m16n8k8.row.col.f32.tf32.tf32.f32 "
        "{%0,%1,%2,%3}, {%4,%5,%6,%7}, {%8,%9}, {%0,%1,%2,%3};"
        : "+f"(c[0]), "+f"(c[1]), "+f"(c[2]), "+f"(c[3])
        : "r"(a[0]), "r"(a[1]), "r"(a[2]), "r"(a[3]), "r"(b[0]), "r"(b[1]));
}
__device__ __forceinline__ float tf32r(float x) {
    float y;
    asm("cvt.rna.tf32.f32 %0, %1;" : "=f"(y) : "f"(x));
    return y;
}

// ---------------------------------------------------------------------------
// Prep kernels: tf32 rounding (x) and transpose+round (weights -> [N,K])
// ---------------------------------------------------------------------------
__global__ __launch_bounds__(256)
void tf32_round_kernel(const float* __restrict__ in, float* __restrict__ out)
{
    const long i = ((long)blockIdx.x * 256 + threadIdx.x) * 4;
    float4 v = *(const float4*)(in + i);
    v.x = tf32r(v.x); v.y = tf32r(v.y); v.z = tf32r(v.z); v.w = tf32r(v.w);
    *(float4*)(out + i) = v;
}

__global__ void transpose_round_kernel(const float* __restrict__ W, float* __restrict__ Wt,
                                       int K, int N)
{
    __shared__ float tile[32][33];
    const int bx = blockIdx.x * 32;   // n
    const int by = blockIdx.y * 32;   // k
    const int x = threadIdx.x, y = threadIdx.y;   // (32, 8)
    #pragma unroll
    for (int i = 0; i < 32; i += 8)
        tile[y + i][x] = tf32r(W[(long)(by + y + i) * N + bx + x]);
    __syncthreads();
    #pragma unroll
    for (int i = 0; i < 32; i += 8)
        Wt[(long)(bx + y + i) * K + by + x] = tile[x][y + i];
}

// ---------------------------------------------------------------------------
// TF32 GEMM via raw mma.m16n8k8 + ldmatrix (swizzled smem).
// C[M,N] = act(A[M,K] @ Bt[N,K]^T).  Operands pre-rounded to tf32.
// 128x256 tile, BK=32, 256 threads (8 warps 2x4), warp tile 64x64.
// 3-stage cp.async pipeline.  ACT: 0 = none, 1 = silu
// Smem tile layout: rows of 32 f32 = 8 chunks of 16B; chunk' = chunk ^ (row&7)
// ---------------------------------------------------------------------------
#define BM 128
#define BN 256
#define BK 32
#define STAGE_A_B 16384               // 128 rows * 128 B
#define STAGE_B_B 32768               // 256 rows * 128 B
#define OFF_SA(s) ((s) * STAGE_A_B)
#define OFF_SB(s) (3 * STAGE_A_B + (s) * STAGE_B_B)
#define GSM_BYTES (3 * STAGE_A_B + 3 * STAGE_B_B)   // 147456
#define CS_LDM 264

__device__ __forceinline__ void g_load_stage(uint32_t sbase, int slot, int tid,
                                             const float* __restrict__ ag,
                                             const float* __restrict__ bg)
{
    // A tile: 128 rows x 8 chunks = 1024, 4/thread
    uint32_t sa = sbase + OFF_SA(slot);
    #pragma unroll
    for (int r = 0; r < 4; r++) {
        int idx = r * 256 + tid;
        int row = idx >> 3, ch = idx & 7;
        CP_ASYNC16(sa + (uint32_t)(row * 128 + ((ch ^ (row & 7)) << 4)),
                   ag + (long)row * HID + ch * 4);
    }
    // B tile: 256 rows x 8 chunks = 2048, 8/thread
    uint32_t sb = sbase + OFF_SB(slot);
    #pragma unroll
    for (int r = 0; r < 8; r++) {
        int idx = r * 256 + tid;
        int row = idx >> 3, ch = idx & 7;
        CP_ASYNC16(sb + (uint32_t)(row * 128 + ((ch ^ (row & 7)) << 4)),
                   bg + (long)row * HID + ch * 4);
    }
}

template<int ACT>
__global__ __launch_bounds__(256, 1)
void mma_gemm(const float* __restrict__ A, const float* __restrict__ Bt,
              float* __restrict__ C, int M, int N)
{
    extern __shared__ float sm[];
    const uint32_t sbase = smem_u32(sm);
    const int tid  = threadIdx.x;
    const int wid  = tid >> 5, lane = tid & 31;
    const int wr   = wid >> 2;        // 0..1: 64-row block
    const int wc   = wid & 3;         // 0..3: 64-col block
    // blockIdx.x = bm tile (fast) so concurrent CTAs share the B stripe in L2
    const long bm = (long)blockIdx.x * BM;
    const long bn = (long)blockIdx.y * BN;

    const float* Ab = A  + bm * HID;
    const float* Bb = Bt + bn * HID;

    // ldmatrix per-lane addressing (tile = lane>>3, r = lane&7)
    const int r    = lane & 7;
    const int tile = lane >> 3;
    // A frag: row = wr*64 + mi*16 + (tile&1)*8 + r ; chunk = kk*2 + (tile>>1)
    const int rowA = wr * 64 + ((tile & 1) << 3) + r;
    const int cA   = tile >> 1;
    // B frag: row = wc*64 + nj2*16 + (tile>>1)*8 + r ; chunk = kk*2 + (tile&1)
    const int rowB = wc * 64 + ((tile >> 1) << 3) + r;
    const int cB   = tile & 1;

    float acc[4][8][4];
    #pragma unroll
    for (int i = 0; i < 4; i++)
        #pragma unroll
        for (int j = 0; j < 8; j++)
            #pragma unroll
            for (int e = 0; e < 4; e++) acc[i][j][e] = 0.f;

    g_load_stage(sbase, 0, tid, Ab, Bb);                 CP_COMMIT();
    g_load_stage(sbase, 1, tid, Ab + BK, Bb + BK);       CP_COMMIT();
    g_load_stage(sbase, 2, tid, Ab + 2 * BK, Bb + 2 * BK); CP_COMMIT();

    const int nk = HID / BK;          // 64
    for (int ks = 0; ks < nk; ks++) {
        const int slot = ks % 3;
        CP_WAIT2();
        __syncthreads();

        const uint32_t sa = sbase + OFF_SA(slot);
        const uint32_t sb = sbase + OFF_SB(slot);

        #pragma unroll
        for (int kk = 0; kk < 4; kk++) {
            uint32_t af[4][4], bf[4][4];
            #pragma unroll
            for (int mi = 0; mi < 4; mi++)
                ldsm4(af[mi], sa + (uint32_t)((rowA + mi * 16) * 128
                                  + (((kk * 2 + cA) ^ r) << 4)));
            #pragma unroll
            for (int nj2 = 0; nj2 < 4; nj2++)
                ldsm4(bf[nj2], sb + (uint32_t)((rowB + nj2 * 16) * 128
                                  + (((kk * 2 + cB) ^ r) << 4)));
            #pragma unroll
            for (int mi = 0; mi < 4; mi++)
                #pragma unroll
                for (int nj = 0; nj < 8; nj++)
                    mma_tf32(acc[mi][nj], af[mi], &bf[nj >> 1][(nj & 1) * 2]);
        }
        __syncthreads();
        if (ks + 3 < nk)
            g_load_stage(sbase, slot, tid, Ab + (long)(ks + 3) * BK,
                         Bb + (long)(ks + 3) * BK);
        CP_COMMIT();
    }

    // epilogue: acc -> smem -> act -> coalesced global float4
    __syncthreads();
    const int er = lane >> 2, ec = (lane & 3) * 2;
    #pragma unroll
    for (int mi = 0; mi < 4; mi++)
        #pragma unroll
        for (int nj = 0; nj < 8; nj++) {
            int row0 = wr * 64 + mi * 16 + er;
            int col0 = wc * 64 + nj * 8 + ec;
            sm[row0 * CS_LDM + col0]       = acc[mi][nj][0];
            sm[row0 * CS_LDM + col0 + 1]   = acc[mi][nj][1];
            sm[(row0 + 8) * CS_LDM + col0]     = acc[mi][nj][2];
            sm[(row0 + 8) * CS_LDM + col0 + 1] = acc[mi][nj][3];
        }
    __syncthreads();

    #pragma unroll
    for (int p = 0; p < 32; p++) {
        int fid = p * 256 + tid;           // 0..8191
        int row = fid >> 6;
        int col = (fid & 63) << 2;
        float4 v = *(const float4*)&sm[row * CS_LDM + col];
        if (ACT == 1) {
            v.x = v.x / (1.f + expf(-v.x));
            v.y = v.y / (1.f + expf(-v.y));
            v.z = v.z / (1.f + expf(-v.z));
            v.w = v.w / (1.f + expf(-v.w));
        }
        *(float4*)(C + (bm + row) * N + bn + col) = v;
    }
}

// ---------------------------------------------------------------------------
// Per-(token, head) RMSNorm + RoPE (+ q scale), in place on g_qkv
// ---------------------------------------------------------------------------
__global__ void qk_rope_kernel(float* __restrict__ qkv,
                               const int* __restrict__ pos,
                               const float* __restrict__ qw,
                               const float* __restrict__ kw)
{
    const int t = blockIdx.x, h = blockIdx.y;
    const int j = threadIdx.x;              // 0..63
    float* qp = qkv + (long)t * QKV_W + h * HD;
    float* kp = qp + INNER;

    float q1 = qp[j], q2 = qp[j + 64];
    float k1 = kp[j], k2 = kp[j + 64];

    float sq = q1*q1 + q2*q2;
    float sk = k1*k1 + k2*k2;
    #pragma unroll
    for (int o = 16; o; o >>= 1) {
        sq += __shfl_xor_sync(0xffffffffu, sq, o);
        sk += __shfl_xor_sync(0xffffffffu, sk, o);
    }
    __shared__ float red[4];
    const int w = j >> 5, lane = j & 31;
    if (lane == 0) { red[w] = sq; red[2 + w] = sk; }
    __syncthreads();
    const float rq = rsqrtf((red[0] + red[1]) * (1.f / 128.f) + EPS);
    const float rk = rsqrtf((red[2] + red[3]) * (1.f / 128.f) + EPS);

    q1 = q1 * rq * qw[j]; q2 = q2 * rq * qw[j + 64];
    k1 = k1 * rk * kw[j]; k2 = k2 * rk * kw[j + 64];

    const float inv = powf(600000.0f, -(float)j * (1.0f / 64.0f));
    const float ang = (float)pos[t] * inv;
    float s, c;
    sincosf(ang, &s, &c);

    qp[j]      = (q1 * c - q2 * s) * QSCALE;
    qp[j + 64] = (q2 * c + q1 * s) * QSCALE;
    kp[j]      =  k1 * c - k2 * s;
    kp[j + 64] =  k2 * c + k1 * s;
}

// ---------------------------------------------------------------------------
// Per-(chunk, head) KV outer product
// ---------------------------------------------------------------------------
__global__ __launch_bounds__(256, 1)
void kv_outer_kernel(const float* __restrict__ qkv, float* __restrict__ KV)
{
    extern __shared__ float sm[];
    float* sK = sm;            // [j][d]
    float* sV = sm + 16384;    // [j][e]

    const int c = blockIdx.x, h = blockIdx.y;
    const int t0 = c * CHUNK;
    const int tid = threadIdx.x, tx = tid & 15, ty = tid >> 4;

    const float* kg = qkv + (long)t0 * QKV_W + h * HD + INNER;
    const float* vg = kg + INNER;

    #pragma unroll
    for (int r = 0; r < 16; r++) {
        int idx = r * 256 + tid;
        int row = idx >> 5;
        int col = (idx & 31) << 2;
        *(float4*)&sK[row * 128 + col] = *(const float4*)(kg + (long)row * QKV_W + col);
        *(float4*)&sV[row * 128 + col] = *(const float4*)(vg + (long)row * QKV_W + col);
    }
    __syncthreads();

    float acc[8][8];
    #pragma unroll
    for (int i = 0; i < 8; i++)
        #pragma unroll
        for (int j = 0; j < 8; j++) acc[i][j] = 0.f;

    for (int j = 0; j < 128; j++) {
        float a[8], b[8];
        *(float4*)&a[0] = *(const float4*)&sK[j * 128 + ty*8];
        *(float4*)&a[4] = *(const float4*)&sK[j * 128 + ty*8 + 4];
        *(float4*)&b[0] = *(const float4*)&sV[j * 128 + tx*8];
        *(float4*)&b[4] = *(const float4*)&sV[j * 128 + tx*8 + 4];
        #pragma unroll
        for (int i = 0; i < 8; i++)
            #pragma unroll
            for (int e = 0; e < 8; e++)
                acc[i][e] += a[i] * b[e];
    }

    float* out = KV + ((long)c * NH + h) * (HD * HD);
    #pragma unroll
    for (int i = 0; i < 8; i++) {
        float4 r0 = make_float4(acc[i][0], acc[i][1], acc[i][2], acc[i][3]);
        float4 r1 = make_float4(acc[i][4], acc[i][5], acc[i][6], acc[i][7]);
        *(float4*)&out[(ty*8 + i) * 128 + tx*8]     = r0;
        *(float4*)&out[(ty*8 + i) * 128 + tx*8 + 4] = r1;
    }
}

// ---------------------------------------------------------------------------
// Exclusive prefix over chunks
// ---------------------------------------------------------------------------
__global__ void prefix_kernel(const float* __restrict__ KV, float* __restrict__ S)
{
    const int idx = blockIdx.x * 256 + threadIdx.x;
    float acc = 0.f;
    #pragma unroll 4
    for (int c = 0; c < NCHUNK; c++) {
        S[(long)c * (NH * HD * HD) + idx] = acc;
        acc += KV[(long)c * (NH * HD * HD) + idx];
    }
}

// ---------------------------------------------------------------------------
// Per-(chunk, head) attention (intra + inter-chunk)
// ---------------------------------------------------------------------------
__global__ __launch_bounds__(256, 1)
void attn_chunk_kernel(const float* __restrict__ qkv, const float* __restrict__ S,
                       float* __restrict__ O)
{
    extern __shared__ float sm[];
    float* sQ = sm;             // qT [d][i]
    float* sB = sm + 16384;     // kT [d][j], then v [j][e]
    float* sC = sm + 32768;     // scoresT [j][i], then S [d][e]

    const int c = blockIdx.x, h = blockIdx.y;
    const int t0 = c * CHUNK;
    const int tid = threadIdx.x, tx = tid & 15, ty = tid >> 4;

    const float* qg = qkv + (long)t0 * QKV_W + h * HD;
    const float* kg = qg + INNER;
    const float* vg = qg + 2 * INNER;

    #pragma unroll
    for (int r = 0; r < 16; r++) {
        int idx = r * 256 + tid;
        int i  = idx >> 5;
        int dd = (idx & 31) << 2;
        float4 q4 = *(const float4*)(qg + (long)i * QKV_W + dd);
        float4 k4 = *(const float4*)(kg + (long)i * QKV_W + dd);
        sQ[(dd+0)*128 + i] = q4.x; sQ[(dd+1)*128 + i] = q4.y;
        sQ[(dd+2)*128 + i] = q4.z; sQ[(dd+3)*128 + i] = q4.w;
        sB[(dd+0)*128 + i] = k4.x; sB[(dd+1)*128 + i] = k4.y;
        sB[(dd+2)*128 + i] = k4.z; sB[(dd+3)*128 + i] = k4.w;
    }
    __syncthreads();

    {
        float acc[8][8];
        #pragma unroll
        for (int a = 0; a < 8; a++)
            #pragma unroll
            for (int b = 0; b < 8; b++) acc[a][b] = 0.f;

        for (int d = 0; d < 128; d++) {
            float a[8], b[8];
            *(float4*)&a[0] = *(const float4*)&sB[d * 128 + ty*8];
            *(float4*)&a[4] = *(const float4*)&sB[d * 128 + ty*8 + 4];
            *(float4*)&b[0] = *(const float4*)&sQ[d * 128 + tx*8];
            *(float4*)&b[4] = *(const float4*)&sQ[d * 128 + tx*8 + 4];
            #pragma unroll
            for (int jj = 0; jj < 8; jj++)
                #pragma unroll
                for (int ii = 0; ii < 8; ii++)
                    acc[jj][ii] += a[jj] * b[ii];
        }
        __syncthreads();
        #pragma unroll
        for (int jj = 0; jj < 8; jj++) {
            int j = ty*8 + jj;
            #pragma unroll
            for (int ii = 0; ii < 8; ii++) {
                int i = tx*8 + ii;
                sC[j * 128 + i] = (i >= j) ? acc[jj][ii] : 0.f;
            }
        }
    }
    __syncthreads();

    #pragma unroll
    for (int r = 0; r < 16; r++) {
        int idx = r * 256 + tid;
        int row = idx >> 5;
        int col = (idx & 31) << 2;
        *(float4*)&sB[row * 128 + col] = *(const float4*)(vg + (long)row * QKV_W + col);
    }
    __syncthreads();

    float o[8][8];
    #pragma unroll
    for (int a = 0; a < 8; a++)
        #pragma unroll
        for (int b = 0; b < 8; b++) o[a][b] = 0.f;

    for (int j = 0; j < 128; j++) {
        float a[8], b[8];
        *(float4*)&a[0] = *(const float4*)&sC[j * 128 + ty*8];
        *(float4*)&a[4] = *(const float4*)&sC[j * 128 + ty*8 + 4];
        *(float4*)&b[0] = *(const float4*)&sB[j * 128 + tx*8];
        *(float4*)&b[4] = *(const float4*)&sB[j * 128 + tx*8 + 4];
        #pragma unroll
        for (int ii = 0; ii < 8; ii++)
            #pragma unroll
            for (int ee = 0; ee < 8; ee++)
                o[ii][ee] += a[ii] * b[ee];
    }
    __syncthreads();

    const float* Sg = S + ((long)c * NH + h) * (HD * HD);
    #pragma unroll
    for (int r = 0; r < 16; r++) {
        int idx = r * 256 + tid;
        int row = idx >> 5;
        int col = (idx & 31) << 2;
        *(float4*)&sC[row * 128 + col] = *(const float4*)(Sg + row * 128 + col);
    }
    __syncthreads();

    for (int d = 0; d < 128; d++) {
        float a[8], b[8];
        *(float4*)&a[0] = *(const float4*)&sQ[d * 128 + ty*8];
        *(float4*)&a[4] = *(const float4*)&sQ[d * 128 + ty*8 + 4];
        *(float4*)&b[0] = *(const float4*)&sC[d * 128 + tx*8];
        *(float4*)&b[4] = *(const float4*)&sC[d * 128 + tx*8 + 4];
        #pragma unroll
        for (int ii = 0; ii < 8; ii++)
            #pragma unroll
            for (int ee = 0; ee < 8; ee++)
                o[ii][ee] += a[ii] * b[ee];
    }

    #pragma unroll
    for (int ii = 0; ii < 8; ii++) {
        float* Op = O + (long)(t0 + ty*8 + ii) * INNER + h * HD + tx*8;
        *(float4*)(Op)     = make_float4(o[ii][0], o[ii][1], o[ii][2], o[ii][3]);
        *(float4*)(Op + 4) = make_float4(o[ii][4], o[ii][5], o[ii][6], o[ii][7]);
    }
}

// ---------------------------------------------------------------------------
// Per-token g-norm + sigmoid gate (in place over g_gate)
// Output tf32-rounded: it is the A operand of the final GEMM.
// ---------------------------------------------------------------------------
__global__ __launch_bounds__(256)
void gate_norm_kernel(const float* __restrict__ O, float* __restrict__ G,
                      const float* __restrict__ gw)
{
    const int t = blockIdx.x;
    const int tid = threadIdx.x;
    const float* orow = O + (long)t * INNER;
    float* grow = G + (long)t * INNER;

    float4 o0 = *(const float4*)(orow + tid * 4);
    float4 o1 = *(const float4*)(orow + 1024 + tid * 4);

    float s = o0.x*o0.x + o0.y*o0.y + o0.z*o0.z + o0.w*o0.w
            + o1.x*o1.x + o1.y*o1.y + o1.z*o1.z + o1.w*o1.w;
    #pragma unroll
    for (int o = 16; o; o >>= 1) s += __shfl_xor_sync(0xffffffffu, s, o);
    __shared__ float red[8];
    if ((tid & 31) == 0) red[tid >> 5] = s;
    __syncthreads();
    float tot = 0.f;
    #pragma unroll
    for (int w = 0; w < 8; w++) tot += red[w];
    const float rs = rsqrtf(tot * (1.f / 2048.f) + EPS);

    float4 g0 = *(const float4*)(grow + tid * 4);
    float4 g1 = *(const float4*)(grow + 1024 + tid * 4);
    float4 w0 = *(const float4*)(gw + tid * 4);
    float4 w1 = *(const float4*)(gw + 1024 + tid * 4);

    float4 r0, r1;
    r0.x = tf32r((1.f / (1.f + expf(-g0.x))) * o0.x * rs * w0.x);
    r0.y = tf32r((1.f / (1.f + expf(-g0.y))) * o0.y * rs * w0.y);
    r0.z = tf32r((1.f / (1.f + expf(-g0.z))) * o0.z * rs * w0.z);
    r0.w = tf32r((1.f / (1.f + expf(-g0.w))) * o0.w * rs * w0.w);
    r1.x = tf32r((1.f / (1.f + expf(-g1.x))) * o1.x * rs * w1.x);
    r1.y = tf32r((1.f / (1.f + expf(-g1.y))) * o1.y * rs * w1.y);
    r1.z = tf32r((1.f / (1.f + expf(-g1.z))) * o1.z * rs * w1.z);
    r1.w = tf32r((1.f / (1.f + expf(-g1.w))) * o1.w * rs * w1.w);

    *(float4*)(grow + tid * 4)        = r0;
    *(float4*)(grow + 1024 + tid * 4) = r1;
}

// ---------------------------------------------------------------------------
// Launch
// ---------------------------------------------------------------------------
extern "C" void kernel_launch(void* const* d_in, const int* in_sizes, int n_in,
                              void* d_out, int out_size)
{
    const float* x    = (const float*)d_in[0];   // [8192, 2048]
    const int*   pos  = (const int*)  d_in[1];   // [8192]
    const float* Wqkv = (const float*)d_in[2];   // [2048, 6144]
    const float* qw   = (const float*)d_in[3];   // [128]
    const float* kw   = (const float*)d_in[4];   // [128]
    const float* Wg   = (const float*)d_in[5];   // [2048, 2048]
    const float* gw   = (const float*)d_in[6];   // [2048]
    const float* Wo   = (const float*)d_in[7];   // [2048, 2048]
    float* out = (float*)d_out;                  // [8192, 2048]

    float* qkv;  cudaGetSymbolAddress((void**)&qkv,  g_qkv);
    float* gate; cudaGetSymbolAddress((void**)&gate, g_gate);
    float* o;    cudaGetSymbolAddress((void**)&o,    g_o);
    float* kvp;  cudaGetSymbolAddress((void**)&kvp,  g_kvp);
    float* S;    cudaGetSymbolAddress((void**)&S,    g_S);
    float* xr;    cudaGetSymbolAddress((void**)&xr,    g_xr);
    float* WqkvT; cudaGetSymbolAddress((void**)&WqkvT, g_WqkvT);
    float* WgT;   cudaGetSymbolAddress((void**)&WgT,   g_WgT);
    float* WoT;   cudaGetSymbolAddress((void**)&WoT,   g_WoT);

    cudaFuncSetAttribute(kv_outer_kernel,
                         cudaFuncAttributeMaxDynamicSharedMemorySize, 2 * 65536);
    cudaFuncSetAttribute(attn_chunk_kernel,
                         cudaFuncAttributeMaxDynamicSharedMemorySize, 3 * 65536);
    cudaFuncSetAttribute(mma_gemm<0>,
                         cudaFuncAttributeMaxDynamicSharedMemorySize, GSM_BYTES);
    cudaFuncSetAttribute(mma_gemm<1>,
                         cudaFuncAttributeMaxDynamicSharedMemorySize, GSM_BYTES);

    // 0. prep: round x to tf32; transpose+round weights to [N,K]
    tf32_round_kernel<<<(T_TOK * (long)HID) / 1024, 256>>>(x, xr);
    transpose_round_kernel<<<dim3(QKV_W / 32, HID / 32), dim3(32, 8)>>>(Wqkv, WqkvT, HID, QKV_W);
    transpose_round_kernel<<<dim3(INNER / 32, HID / 32), dim3(32, 8)>>>(Wg, WgT, HID, INNER);
    transpose_round_kernel<<<dim3(HID / 32, INNER / 32), dim3(32, 8)>>>(Wo, WoT, INNER, HID);

    // 1. qkv = silu(x @ Wqkv)
    mma_gemm<1><<<dim3(T_TOK / BM, QKV_W / BN), 256, GSM_BYTES>>>(xr, WqkvT, qkv, T_TOK, QKV_W);
    // 2. gate = x @ Wg
    mma_gemm<0><<<dim3(T_TOK / BM, INNER / BN), 256, GSM_BYTES>>>(xr, WgT, gate, T_TOK, INNER);
    // 3. per-head rmsnorm + rope (+ q scale), in place
    qk_rope_kernel<<<dim3(T_TOK, NH), 64>>>(qkv, pos, qw, kw);
    // 4. per-chunk KV outer products
    kv_outer_kernel<<<dim3(NCHUNK, NH), 256, 2 * 65536>>>(qkv, kvp);
    // 5. exclusive prefix over chunks -> per-chunk state S
    prefix_kernel<<<(NH * HD * HD) / 256, 256>>>(kvp, S);
    // 6. intra-chunk masked attention + inter-chunk q@S
    attn_chunk_kernel<<<dim3(NCHUNK, NH), 256, 3 * 65536>>>(qkv, S, o);
    // 7. g-norm + sigmoid gating (in place, tf32-rounded output)
    gate_norm_kernel<<<T_TOK, 256>>>(o, gate, gw);
    // 8. out = gated @ Wo
    mma_gemm<0><<<dim3(T_TOK / BM, HID / BN), 256, GSM_BYTES>>>(gate, WoT, out, T_TOK, HID);
}

// round 16
// speedup vs baseline: 3.3455x; 1.1087x over previous
#include <cuda_runtime.h>
#include <cuda_bf16.h>
#include <cstdint>
#include <math.h>

// ---------------------------------------------------------------------------
// Problem constants
// ---------------------------------------------------------------------------
#define T_TOK   8192
#define HID     2048
#define NH      16
#define HD      128
#define INNER   2048          // NH*HD
#define QKV_W   6144          // 3*INNER
#define NCHUNK  64            // T/128
#define CHUNK   128
#define EPS     1e-5f
#define QSCALE  0.08838834764831845f   // 128^-0.5

// ---------------------------------------------------------------------------
// Device scratch (static globals: allocation-free rule)
// ---------------------------------------------------------------------------
__device__ float g_qkv [T_TOK * QKV_W];            // silu(x@Wqkv), q/k rope'd in place
__device__ float g_gate[T_TOK * INNER];            // x@Wg, then gated (tf32-rounded) value
__device__ float g_o   [T_TOK * INNER];            // attention output
__device__ float g_kvp [NCHUNK * NH * HD * HD];    // per-chunk KVt outer products [e][d]
__device__ float g_S   [NCHUNK * NH * HD * HD];    // exclusive prefix state St [e][d]
__device__ float g_xr    [T_TOK * HID];            // tf32-rounded x
__device__ float g_WqkvT [QKV_W * HID];            // tf32-rounded, transposed [N,K]
__device__ float g_WgT   [INNER * HID];
__device__ float g_WoT   [HID * INNER];

// ---------------------------------------------------------------------------
// PTX helpers (all non-arch-gated: sm_75+/sm_80+ instructions)
// ---------------------------------------------------------------------------
__device__ __forceinline__ uint32_t smem_u32(const void* p) {
    uint32_t a;
    asm("{ .reg .u64 t; cvta.to.shared.u64 t, %1; cvt.u32.u64 %0, t; }" : "=r"(a) : "l"(p));
    return a;
}
#define CP_ASYNC16(sdst, gsrc) \
    asm volatile("cp.async.cg.shared.global [%0], [%1], 16;" :: "r"(sdst), "l"(gsrc) : "memory")
#define CP_COMMIT() asm volatile("cp.async.commit_group;" ::: "memory")
#define CP_WAIT2()  asm volatile("cp.async.wait_group 2;" ::: "memory")
#define CP_WAIT0()  asm volatile("cp.async.wait_group 0;" ::: "memory")

__device__ __forceinline__ void ldsm4(uint32_t* d, uint32_t addr) {
    asm volatile("ldmatrix.sync.aligned.m8n8.x4.shared.b16 {%0,%1,%2,%3}, [%4];"
                 : "=r"(d[0]), "=r"(d[1]), "=r"(d[2]), "=r"(d[3]) : "r"(addr));
}
__device__ __forceinline__ void mma_tf32(float* c, const uint32_t* a, const uint32_t* b) {
    asm volatile(
        "mma.sync.aligned.m16n8k8.row.col.f32.tf32.tf32.f32 "
        "{%0,%1,%2,%3}, {%4,%5,%6,%7}, {%8,%9}, {%0,%1,%2,%3};"
        : "+f"(c[0]), "+f"(c[1]), "+f"(c[2]), "+f"(c[3])
        : "r"(a[0]), "r"(a[1]), "r"(a[2]), "r"(a[3]), "r"(b[0]), "r"(b[1]));
}
__device__ __forceinline__ float tf32r(float x) {
    float y;
    asm("cvt.rna.tf32.f32 %0, %1;" : "=f"(y) : "f"(x));
    return y;
}

// ---------------------------------------------------------------------------
// Prep kernels: tf32 rounding (x) and transpose+round (weights -> [N,K])
// ---------------------------------------------------------------------------
__global__ __launch_bounds__(256)
void tf32_round_kernel(const float* __restrict__ in, float* __restrict__ out)
{
    const long i = ((long)blockIdx.x * 256 + threadIdx.x) * 4;
    float4 v = *(const float4*)(in + i);
    v.x = tf32r(v.x); v.y = tf32r(v.y); v.z = tf32r(v.z); v.w = tf32r(v.w);
    *(float4*)(out + i) = v;
}

__global__ void transpose_round_kernel(const float* __restrict__ W, float* __restrict__ Wt,
                                       int K, int N)
{
    __shared__ float tile[32][33];
    const int bx = blockIdx.x * 32;   // n
    const int by = blockIdx.y * 32;   // k
    const int x = threadIdx.x, y = threadIdx.y;   // (32, 8)
    #pragma unroll
    for (int i = 0; i < 32; i += 8)
        tile[y + i][x] = tf32r(W[(long)(by + y + i) * N + bx + x]);
    __syncthreads();
    #pragma unroll
    for (int i = 0; i < 32; i += 8)
        Wt[(long)(bx + y + i) * K + by + x] = tile[x][y + i];
}

// ---------------------------------------------------------------------------
// TF32 GEMM via raw mma.m16n8k8 + ldmatrix (swizzled smem).
// C[M,N] = act(A[M,K] @ Bt[N,K]^T).  Operands pre-rounded to tf32.
// 128x256 tile, BK=32, 256 threads (8 warps 2x4), warp tile 64x64.
// 4-stage cp.async pipeline, ONE barrier per k-step.  ACT: 0=none, 1=silu
// Smem tile rows = 32 f32 = 8 chunks of 16B; chunk' = chunk ^ (row&7)
// ---------------------------------------------------------------------------
#define BM 128
#define BN 256
#define BK 32
#define STAGE_A_B 16384               // 128 rows * 128 B
#define STAGE_B_B 32768               // 256 rows * 128 B
#define OFF_SA(s) ((s) * STAGE_A_B)
#define OFF_SB(s) (4 * STAGE_A_B + (s) * STAGE_B_B)
#define GSM_BYTES (4 * STAGE_A_B + 4 * STAGE_B_B)   // 196608
#define CS_LDM 264

__device__ __forceinline__ void g_load_stage(uint32_t sbase, int slot, int tid,
                                             const float* __restrict__ ag,
                                             const float* __restrict__ bg)
{
    uint32_t sa = sbase + OFF_SA(slot);
    #pragma unroll
    for (int r = 0; r < 4; r++) {
        int idx = r * 256 + tid;
        int row = idx >> 3, ch = idx & 7;
        CP_ASYNC16(sa + (uint32_t)(row * 128 + ((ch ^ (row & 7)) << 4)),
                   ag + (long)row * HID + ch * 4);
    }
    uint32_t sb = sbase + OFF_SB(slot);
    #pragma unroll
    for (int r = 0; r < 8; r++) {
        int idx = r * 256 + tid;
        int row = idx >> 3, ch = idx & 7;
        CP_ASYNC16(sb + (uint32_t)(row * 128 + ((ch ^ (row & 7)) << 4)),
                   bg + (long)row * HID + ch * 4);
    }
}

template<int ACT>
__global__ __launch_bounds__(256, 1)
void mma_gemm(const float* __restrict__ A, const float* __restrict__ Bt,
              float* __restrict__ C, int M, int N)
{
    extern __shared__ float sm[];
    const uint32_t sbase = smem_u32(sm);
    const int tid  = threadIdx.x;
    const int wid  = tid >> 5, lane = tid & 31;
    const int wr   = wid >> 2;        // 0..1: 64-row block
    const int wc   = wid & 3;         // 0..3: 64-col block
    const long bm = (long)blockIdx.x * BM;
    const long bn = (long)blockIdx.y * BN;

    const float* Ab = A  + bm * HID;
    const float* Bb = Bt + bn * HID;

    const int r    = lane & 7;
    const int tile = lane >> 3;
    const int rowA = wr * 64 + ((tile & 1) << 3) + r;
    const int cA   = tile >> 1;
    const int rowB = wc * 64 + ((tile >> 1) << 3) + r;
    const int cB   = tile & 1;

    float acc[4][8][4];
    #pragma unroll
    for (int i = 0; i < 4; i++)
        #pragma unroll
        for (int j = 0; j < 8; j++)
            #pragma unroll
            for (int e = 0; e < 4; e++) acc[i][j][e] = 0.f;

    g_load_stage(sbase, 0, tid, Ab, Bb);                   CP_COMMIT();
    g_load_stage(sbase, 1, tid, Ab + BK, Bb + BK);         CP_COMMIT();
    g_load_stage(sbase, 2, tid, Ab + 2 * BK, Bb + 2 * BK); CP_COMMIT();

    const int nk = HID / BK;          // 64
    for (int ks = 0; ks < nk; ks++) {
        const int slot = ks & 3;
        CP_WAIT2();
        __syncthreads();
        if (ks + 3 < nk)
            g_load_stage(sbase, (ks + 3) & 3, tid, Ab + (long)(ks + 3) * BK,
                         Bb + (long)(ks + 3) * BK);
        CP_COMMIT();

        const uint32_t sa = sbase + OFF_SA(slot);
        const uint32_t sb = sbase + OFF_SB(slot);

        #pragma unroll
        for (int kk = 0; kk < 4; kk++) {
            uint32_t af[4][4], bf[4][4];
            #pragma unroll
            for (int mi = 0; mi < 4; mi++)
                ldsm4(af[mi], sa + (uint32_t)((rowA + mi * 16) * 128
                                  + (((kk * 2 + cA) ^ r) << 4)));
            #pragma unroll
            for (int nj2 = 0; nj2 < 4; nj2++)
                ldsm4(bf[nj2], sb + (uint32_t)((rowB + nj2 * 16) * 128
                                  + (((kk * 2 + cB) ^ r) << 4)));
            #pragma unroll
            for (int mi = 0; mi < 4; mi++)
                #pragma unroll
                for (int nj = 0; nj < 8; nj++)
                    mma_tf32(acc[mi][nj], af[mi], &bf[nj >> 1][(nj & 1) * 2]);
        }
    }

    // epilogue: acc -> smem -> act -> coalesced global float4
    __syncthreads();
    const int er = lane >> 2, ec = (lane & 3) * 2;
    #pragma unroll
    for (int mi = 0; mi < 4; mi++)
        #pragma unroll
        for (int nj = 0; nj < 8; nj++) {
            int row0 = wr * 64 + mi * 16 + er;
            int col0 = wc * 64 + nj * 8 + ec;
            sm[row0 * CS_LDM + col0]       = acc[mi][nj][0];
            sm[row0 * CS_LDM + col0 + 1]   = acc[mi][nj][1];
            sm[(row0 + 8) * CS_LDM + col0]     = acc[mi][nj][2];
            sm[(row0 + 8) * CS_LDM + col0 + 1] = acc[mi][nj][3];
        }
    __syncthreads();

    #pragma unroll
    for (int p = 0; p < 32; p++) {
        int fid = p * 256 + tid;
        int row = fid >> 6;
        int col = (fid & 63) << 2;
        float4 v = *(const float4*)&sm[row * CS_LDM + col];
        if (ACT == 1) {
            v.x = v.x / (1.f + expf(-v.x));
            v.y = v.y / (1.f + expf(-v.y));
            v.z = v.z / (1.f + expf(-v.z));
            v.w = v.w / (1.f + expf(-v.w));
        }
        *(float4*)(C + (bm + row) * N + bn + col) = v;
    }
}

// ---------------------------------------------------------------------------
// Per-(token, head) RMSNorm + RoPE (+ q scale), in place on g_qkv.
// Outputs rna-rounded to tf32 (they feed tensor-core attention).
// ---------------------------------------------------------------------------
__global__ void qk_rope_kernel(float* __restrict__ qkv,
                               const int* __restrict__ pos,
                               const float* __restrict__ qw,
                               const float* __restrict__ kw)
{
    const int t = blockIdx.x, h = blockIdx.y;
    const int j = threadIdx.x;              // 0..63
    float* qp = qkv + (long)t * QKV_W + h * HD;
    float* kp = qp + INNER;

    float q1 = qp[j], q2 = qp[j + 64];
    float k1 = kp[j], k2 = kp[j + 64];

    float sq = q1*q1 + q2*q2;
    float sk = k1*k1 + k2*k2;
    #pragma unroll
    for (int o = 16; o; o >>= 1) {
        sq += __shfl_xor_sync(0xffffffffu, sq, o);
        sk += __shfl_xor_sync(0xffffffffu, sk, o);
    }
    __shared__ float red[4];
    const int w = j >> 5, lane = j & 31;
    if (lane == 0) { red[w] = sq; red[2 + w] = sk; }
    __syncthreads();
    const float rq = rsqrtf((red[0] + red[1]) * (1.f / 128.f) + EPS);
    const float rk = rsqrtf((red[2] + red[3]) * (1.f / 128.f) + EPS);

    q1 = q1 * rq * qw[j]; q2 = q2 * rq * qw[j + 64];
    k1 = k1 * rk * kw[j]; k2 = k2 * rk * kw[j + 64];

    const float inv = powf(600000.0f, -(float)j * (1.0f / 64.0f));
    const float ang = (float)pos[t] * inv;
    float s, c;
    sincosf(ang, &s, &c);

    qp[j]      = tf32r((q1 * c - q2 * s) * QSCALE);
    qp[j + 64] = tf32r((q2 * c + q1 * s) * QSCALE);
    kp[j]      = tf32r( k1 * c - k2 * s);
    kp[j + 64] = tf32r( k2 * c + k1 * s);
}

// ---------------------------------------------------------------------------
// Tensor-core per-(chunk,head) KV outer product (transposed output):
//   KVt[e][d] = sum_j v[j][e] * k[j][d]
// A = v^T [e][j], B = k^T [d][j] (both scalar-transposed into swizzled smem).
// 8 warps (4x2), warp tile 32x64, K=128.
// Smem tile rows = 128 f32 = 32 chunks of 16B; chunk' = chunk ^ (row&7)
// ---------------------------------------------------------------------------
#define TILE_B 65536   // 128*128*4

__global__ __launch_bounds__(256, 1)
void kv_outer_mma(const float* __restrict__ qkv, float* __restrict__ KVt)
{
    extern __shared__ char smc[];
    const uint32_t sbase = smem_u32(smc);
    const uint32_t sVT = sbase, sKT = sbase + TILE_B;

    const int c = blockIdx.x, h = blockIdx.y;
    const int t0 = c * CHUNK;
    const int tid = threadIdx.x, wid = tid >> 5, lane = tid & 31;
    const int wr = wid >> 1, wc = wid & 1;
    const int r = lane & 7, tl = lane >> 3;
    const int er = lane >> 2, ec = (lane & 3) * 2;

    const float* kg = qkv + (long)t0 * QKV_W + h * HD + INNER;
    const float* vg = kg + INNER;

    // transposed loads: v[j][e] -> sVT[e][j], k[j][d] -> sKT[d][j] (tf32-rounded)
    #pragma unroll
    for (int it = 0; it < 16; it++) {
        int idx = it * 256 + tid;
        int j = idx >> 5, e0 = (idx & 31) << 2;
        float4 v4 = *(const float4*)(vg + (long)j * QKV_W + e0);
        float4 k4 = *(const float4*)(kg + (long)j * QKV_W + e0);
        int chj = j >> 2, cj = (j & 3) * 4;
        float vv[4] = {v4.x, v4.y, v4.z, v4.w};
        float kk4[4] = {k4.x, k4.y, k4.z, k4.w};
        #pragma unroll
        for (int u = 0; u < 4; u++) {
            int row = e0 + u;
            uint32_t off = (uint32_t)(row * 512 + ((chj ^ (row & 7)) << 4) + cj);
            *(float*)(smc + off)          = tf32r(vv[u]);
            *(float*)(smc + TILE_B + off) = tf32r(kk4[u]);
        }
    }
    __syncthreads();

    float acc[2][8][4];
    #pragma unroll
    for (int i = 0; i < 2; i++)
        #pragma unroll
        for (int j = 0; j < 8; j++)
            #pragma unroll
            for (int e = 0; e < 4; e++) acc[i][j][e] = 0.f;

    #pragma unroll
    for (int kb = 0; kb < 16; kb++) {
        uint32_t af[2][4], bf[4][4];
        #pragma unroll
        for (int mi = 0; mi < 2; mi++) {
            int row = wr * 32 + mi * 16 + ((tl & 1) << 3) + r;
            int ch  = kb * 2 + (tl >> 1);
            ldsm4(af[mi], sVT + (uint32_t)(row * 512 + ((ch ^ (row & 7)) << 4)));
        }
        #pragma unroll
        for (int b = 0; b < 4; b++) {
            int row = wc * 64 + b * 16 + ((tl >> 1) << 3) + r;
            int ch  = kb * 2 + (tl & 1);
            ldsm4(bf[b], sKT + (uint32_t)(row * 512 + ((ch ^ (row & 7)) << 4)));
        }
        #pragma unroll
        for (int mi = 0; mi < 2; mi++)
            #pragma unroll
            for (int nj = 0; nj < 8; nj++)
                mma_tf32(acc[mi][nj], af[mi], &bf[nj >> 1][(nj & 1) * 2]);
    }

    float* out = KVt + ((long)c * NH + h) * (HD * HD);
    #pragma unroll
    for (int mi = 0; mi < 2; mi++)
        #pragma unroll
        for (int nj = 0; nj < 8; nj++) {
            int e0 = wr * 32 + mi * 16 + er;
            int d0 = wc * 64 + nj * 8 + ec;
            *(float2*)(out + e0 * 128 + d0)       = make_float2(acc[mi][nj][0], acc[mi][nj][1]);
            *(float2*)(out + (e0 + 8) * 128 + d0) = make_float2(acc[mi][nj][2], acc[mi][nj][3]);
        }
}

// ---------------------------------------------------------------------------
// Exclusive prefix over chunks (elementwise; layout-agnostic)
// ---------------------------------------------------------------------------
__global__ void prefix_kernel(const float* __restrict__ KV, float* __restrict__ S)
{
    const int idx = blockIdx.x * 256 + threadIdx.x;
    float acc = 0.f;
    #pragma unroll 4
    for (int c = 0; c < NCHUNK; c++) {
        S[(long)c * (NH * HD * HD) + idx] = acc;
        acc += KV[(long)c * (NH * HD * HD) + idx];
    }
}

// ---------------------------------------------------------------------------
// Tensor-core per-(chunk,head) attention:
//   GEMM1: sc[i][j] = sum_d q[i][d] k[j][d]        (mask i>=j)  [A=q, B=k nat.]
//   GEMM2: o[i][e]  = sum_j sc[i][j] v[j][e]                    [B = v^T]
//   GEMM3: o[i][e] += sum_d q[i][d] St[e][d]                    [B = St nat.]
// 8 warps (4x2), warp tile 32x64.  Smem: sQ | sB(k->vT->St) | sC(scores)
// ---------------------------------------------------------------------------
__global__ __launch_bounds__(256, 1)
void attn_chunk_mma(const float* __restrict__ qkv, const float* __restrict__ St,
                    float* __restrict__ O)
{
    extern __shared__ char smc[];
    const uint32_t sbase = smem_u32(smc);
    const uint32_t sQ = sbase, sB = sbase + TILE_B, sC = sbase + 2 * TILE_B;

    const int c = blockIdx.x, h = blockIdx.y;
    const int t0 = c * CHUNK;
    const int tid = threadIdx.x, wid = tid >> 5, lane = tid & 31;
    const int wr = wid >> 1, wc = wid & 1;
    const int r = lane & 7, tl = lane >> 3;
    const int er = lane >> 2, ec = (lane & 3) * 2;

    const float* qg = qkv + (long)t0 * QKV_W + h * HD;
    const float* kg = qg + INNER;
    const float* vg = kg + INNER;

    // q -> sQ, k -> sB (natural layout, swizzled)
    #pragma unroll
    for (int it = 0; it < 16; it++) {
        int idx = it * 256 + tid;
        int row = idx >> 5, cc = idx & 31;
        uint32_t off = (uint32_t)(row * 512 + ((cc ^ (row & 7)) << 4));
        CP_ASYNC16(sQ + off, qg + (long)row * QKV_W + cc * 4);
        CP_ASYNC16(sB + off, kg + (long)row * QKV_W + cc * 4);
    }
    CP_COMMIT();
    CP_WAIT0();
    __syncthreads();

    // GEMM1: scores = q @ k^T
    float sc[2][8][4];
    #pragma unroll
    for (int i = 0; i < 2; i++)
        #pragma unroll
        for (int j = 0; j < 8; j++)
            #pragma unroll
            for (int e = 0; e < 4; e++) sc[i][j][e] = 0.f;

    #pragma unroll
    for (int kb = 0; kb < 16; kb++) {
        uint32_t af[2][4], bf[4][4];
        #pragma unroll
        for (int mi = 0; mi < 2; mi++) {
            int row = wr * 32 + mi * 16 + ((tl & 1) << 3) + r;
            int ch  = kb * 2 + (tl >> 1);
            ldsm4(af[mi], sQ + (uint32_t)(row * 512 + ((ch ^ (row & 7)) << 4)));
        }
        #pragma unroll
        for (int b = 0; b < 4; b++) {
            int row = wc * 64 + b * 16 + ((tl >> 1) << 3) + r;
            int ch  = kb * 2 + (tl & 1);
            ldsm4(bf[b], sB + (uint32_t)(row * 512 + ((ch ^ (row & 7)) << 4)));
        }
        #pragma unroll
        for (int mi = 0; mi < 2; mi++)
            #pragma unroll
            for (int nj = 0; nj < 8; nj++)
                mma_tf32(sc[mi][nj], af[mi], &bf[nj >> 1][(nj & 1) * 2]);
    }
    __syncthreads();   // GEMM1 reads of sB done -> sB reusable; sC writes below

    // masked scores -> sC (swizzled natural [i][j])
    #pragma unroll
    for (int mi = 0; mi < 2; mi++)
        #pragma unroll
        for (int nj = 0; nj < 8; nj++) {
            int i0 = wr * 32 + mi * 16 + er;
            int j0 = wc * 64 + nj * 8 + ec;
            float2 lo, hi;
            lo.x = (i0     >= j0    ) ? sc[mi][nj][0] : 0.f;
            lo.y = (i0     >= j0 + 1) ? sc[mi][nj][1] : 0.f;
            hi.x = (i0 + 8 >= j0    ) ? sc[mi][nj][2] : 0.f;
            hi.y = (i0 + 8 >= j0 + 1) ? sc[mi][nj][3] : 0.f;
            int chj = j0 >> 2, cj = (j0 & 3) * 4;
            *(float2*)(smc + 2 * TILE_B + i0 * 512 + ((chj ^ (i0 & 7)) << 4) + cj) = lo;
            *(float2*)(smc + 2 * TILE_B + (i0 + 8) * 512 + ((chj ^ ((i0 + 8) & 7)) << 4) + cj) = hi;
        }

    // v^T -> sB (scalar transpose, tf32-rounded)
    #pragma unroll
    for (int it = 0; it < 16; it++) {
        int idx = it * 256 + tid;
        int j = idx >> 5, e0 = (idx & 31) << 2;
        float4 v4 = *(const float4*)(vg + (long)j * QKV_W + e0);
        int chj = j >> 2, cj = (j & 3) * 4;
        float vv[4] = {v4.x, v4.y, v4.z, v4.w};
        #pragma unroll
        for (int u = 0; u < 4; u++) {
            int row = e0 + u;
            *(float*)(smc + TILE_B + row * 512 + ((chj ^ (row & 7)) << 4) + cj) = tf32r(vv[u]);
        }
    }
    __syncthreads();

    // GEMM2: o = scores @ v^T
    float o[2][8][4];
    #pragma unroll
    for (int i = 0; i < 2; i++)
        #pragma unroll
        for (int j = 0; j < 8; j++)
            #pragma unroll
            for (int e = 0; e < 4; e++) o[i][j][e] = 0.f;

    #pragma unroll
    for (int kb = 0; kb < 16; kb++) {
        uint32_t af[2][4], bf[4][4];
        #pragma unroll
        for (int mi = 0; mi < 2; mi++) {
            int row = wr * 32 + mi * 16 + ((tl & 1) << 3) + r;
            int ch  = kb * 2 + (tl >> 1);
            ldsm4(af[mi], sC + (uint32_t)(row * 512 + ((ch ^ (row & 7)) << 4)));
        }
        #pragma unroll
        for (int b = 0; b < 4; b++) {
            int row = wc * 64 + b * 16 + ((tl >> 1) << 3) + r;
            int ch  = kb * 2 + (tl & 1);
            ldsm4(bf[b], sB + (uint32_t)(row * 512 + ((ch ^ (row & 7)) << 4)));
        }
        #pragma unroll
        for (int mi = 0; mi < 2; mi++)
            #pragma unroll
            for (int nj = 0; nj < 8; nj++)
                mma_tf32(o[mi][nj], af[mi], &bf[nj >> 1][(nj & 1) * 2]);
    }
    __syncthreads();   // GEMM2 reads of sB done

    // St -> sB (natural [e][d], swizzled)
    const float* Sg = St + ((long)c * NH + h) * (HD * HD);
    #pragma unroll
    for (int it = 0; it < 16; it++) {
        int idx = it * 256 + tid;
        int row = idx >> 5, cc = idx & 31;
        CP_ASYNC16(sB + (uint32_t)(row * 512 + ((cc ^ (row & 7)) << 4)),
                   Sg + row * 128 + cc * 4);
    }
    CP_COMMIT();
    CP_WAIT0();
    __syncthreads();

    // GEMM3: o += q @ St^T(B)
    #pragma unroll
    for (int kb = 0; kb < 16; kb++) {
        uint32_t af[2][4], bf[4][4];
        #pragma unroll
        for (int mi = 0; mi < 2; mi++) {
            int row = wr * 32 + mi * 16 + ((tl & 1) << 3) + r;
            int ch  = kb * 2 + (tl >> 1);
            ldsm4(af[mi], sQ + (uint32_t)(row * 512 + ((ch ^ (row & 7)) << 4)));
        }
        #pragma unroll
        for (int b = 0; b < 4; b++) {
            int row = wc * 64 + b * 16 + ((tl >> 1) << 3) + r;
            int ch  = kb * 2 + (tl & 1);
            ldsm4(bf[b], sB + (uint32_t)(row * 512 + ((ch ^ (row & 7)) << 4)));
        }
        #pragma unroll
        for (int mi = 0; mi < 2; mi++)
            #pragma unroll
            for (int nj = 0; nj < 8; nj++)
                mma_tf32(o[mi][nj], af[mi], &bf[nj >> 1][(nj & 1) * 2]);
    }

    // write O[t][h*128 + e]
    #pragma unroll
    for (int mi = 0; mi < 2; mi++)
        #pragma unroll
        for (int nj = 0; nj < 8; nj++) {
            int i0 = wr * 32 + mi * 16 + er;
            int j0 = wc * 64 + nj * 8 + ec;
            *(float2*)(O + (long)(t0 + i0) * INNER + h * HD + j0)
                = make_float2(o[mi][nj][0], o[mi][nj][1]);
            *(float2*)(O + (long)(t0 + i0 + 8) * INNER + h * HD + j0)
                = make_float2(o[mi][nj][2], o[mi][nj][3]);
        }
}

// ---------------------------------------------------------------------------
// Per-token g-norm + sigmoid gate (in place over g_gate)
// Output tf32-rounded: it is the A operand of the final GEMM.
// ---------------------------------------------------------------------------
__global__ __launch_bounds__(256)
void gate_norm_kernel(const float* __restrict__ O, float* __restrict__ G,
                      const float* __restrict__ gw)
{
    const int t = blockIdx.x;
    const int tid = threadIdx.x;
    const float* orow = O + (long)t * INNER;
    float* grow = G + (long)t * INNER;

    float4 o0 = *(const float4*)(orow + tid * 4);
    float4 o1 = *(const float4*)(orow + 1024 + tid * 4);

    float s = o0.x*o0.x + o0.y*o0.y + o0.z*o0.z + o0.w*o0.w
            + o1.x*o1.x + o1.y*o1.y + o1.z*o1.z + o1.w*o1.w;
    #pragma unroll
    for (int o = 16; o; o >>= 1) s += __shfl_xor_sync(0xffffffffu, s, o);
    __shared__ float red[8];
    if ((tid & 31) == 0) red[tid >> 5] = s;
    __syncthreads();
    float tot = 0.f;
    #pragma unroll
    for (int w = 0; w < 8; w++) tot += red[w];
    const float rs = rsqrtf(tot * (1.f / 2048.f) + EPS);

    float4 g0 = *(const float4*)(grow + tid * 4);
    float4 g1 = *(const float4*)(grow + 1024 + tid * 4);
    float4 w0 = *(const float4*)(gw + tid * 4);
    float4 w1 = *(const float4*)(gw + 1024 + tid * 4);

    float4 r0, r1;
    r0.x = tf32r((1.f / (1.f + expf(-g0.x))) * o0.x * rs * w0.x);
    r0.y = tf32r((1.f / (1.f + expf(-g0.y))) * o0.y * rs * w0.y);
    r0.z = tf32r((1.f / (1.f + expf(-g0.z))) * o0.z * rs * w0.z);
    r0.w = tf32r((1.f / (1.f + expf(-g0.w))) * o0.w * rs * w0.w);
    r1.x = tf32r((1.f / (1.f + expf(-g1.x))) * o1.x * rs * w1.x);
    r1.y = tf32r((1.f / (1.f + expf(-g1.y))) * o1.y * rs * w1.y);
    r1.z = tf32r((1.f / (1.f + expf(-g1.z))) * o1.z * rs * w1.z);
    r1.w = tf32r((1.f / (1.f + expf(-g1.w))) * o1.w * rs * w1.w);

    *(float4*)(grow + tid * 4)        = r0;
    *(float4*)(grow + 1024 + tid * 4) = r1;
}

// ---------------------------------------------------------------------------
// Launch
// ---------------------------------------------------------------------------
extern "C" void kernel_launch(void* const* d_in, const int* in_sizes, int n_in,
                              void* d_out, int out_size)
{
    const float* x    = (const float*)d_in[0];   // [8192, 2048]
    const int*   pos  = (const int*)  d_in[1];   // [8192]
    const float* Wqkv = (const float*)d_in[2];   // [2048, 6144]
    const float* qw   = (const float*)d_in[3];   // [128]
    const float* kw   = (const float*)d_in[4];   // [128]
    const float* Wg   = (const float*)d_in[5];   // [2048, 2048]
    const float* gw   = (const float*)d_in[6];   // [2048]
    const float* Wo   = (const float*)d_in[7];   // [2048, 2048]
    float* out = (float*)d_out;                  // [8192, 2048]

    float* qkv;  cudaGetSymbolAddress((void**)&qkv,  g_qkv);
    float* gate; cudaGetSymbolAddress((void**)&gate, g_gate);
    float* o;    cudaGetSymbolAddress((void**)&o,    g_o);
    float* kvp;  cudaGetSymbolAddress((void**)&kvp,  g_kvp);
    float* S;    cudaGetSymbolAddress((void**)&S,    g_S);
    float* xr;    cudaGetSymbolAddress((void**)&xr,    g_xr);
    float* WqkvT; cudaGetSymbolAddress((void**)&WqkvT, g_WqkvT);
    float* WgT;   cudaGetSymbolAddress((void**)&WgT,   g_WgT);
    float* WoT;   cudaGetSymbolAddress((void**)&WoT,   g_WoT);

    cudaFuncSetAttribute(mma_gemm<0>,
                         cudaFuncAttributeMaxDynamicSharedMemorySize, GSM_BYTES);
    cudaFuncSetAttribute(mma_gemm<1>,
                         cudaFuncAttributeMaxDynamicSharedMemorySize, GSM_BYTES);
    cudaFuncSetAttribute(kv_outer_mma,
                         cudaFuncAttributeMaxDynamicSharedMemorySize, 2 * TILE_B);
    cudaFuncSetAttribute(attn_chunk_mma,
                         cudaFuncAttributeMaxDynamicSharedMemorySize, 3 * TILE_B);

    // 0. prep: round x to tf32; transpose+round weights to [N,K]
    tf32_round_kernel<<<(T_TOK * (long)HID) / 1024, 256>>>(x, xr);
    transpose_round_kernel<<<dim3(QKV_W / 32, HID / 32), dim3(32, 8)>>>(Wqkv, WqkvT, HID, QKV_W);
    transpose_round_kernel<<<dim3(INNER / 32, HID / 32), dim3(32, 8)>>>(Wg, WgT, HID, INNER);
    transpose_round_kernel<<<dim3(HID / 32, INNER / 32), dim3(32, 8)>>>(Wo, WoT, INNER, HID);

    // 1. qkv = silu(x @ Wqkv)
    mma_gemm<1><<<dim3(T_TOK / BM, QKV_W / BN), 256, GSM_BYTES>>>(xr, WqkvT, qkv, T_TOK, QKV_W);
    // 2. gate = x @ Wg
    mma_gemm<0><<<dim3(T_TOK / BM, INNER / BN), 256, GSM_BYTES>>>(xr, WgT, gate, T_TOK, INNER);
    // 3. per-head rmsnorm + rope (+ q scale), in place, tf32-rounded
    qk_rope_kernel<<<dim3(T_TOK, NH), 64>>>(qkv, pos, qw, kw);
    // 4. per-chunk KVt outer products (tensor cores)
    kv_outer_mma<<<dim3(NCHUNK, NH), 256, 2 * TILE_B>>>(qkv, kvp);
    // 5. exclusive prefix over chunks -> per-chunk state St
    prefix_kernel<<<(NH * HD * HD) / 256, 256>>>(kvp, S);
    // 6. intra-chunk masked attention + inter-chunk q@S (tensor cores)
    attn_chunk_mma<<<dim3(NCHUNK, NH), 256, 3 * TILE_B>>>(qkv, S, o);
    // 7. g-norm + sigmoid gating (in place, tf32-rounded output)
    gate_norm_kernel<<<T_TOK, 256>>>(o, gate, gw);
    // 8. out = gated @ Wo
    mma_gemm<0><<<dim3(T_TOK / BM, HID / BN), 256, GSM_BYTES>>>(gate, WoT, out, T_TOK, HID);
}

// round 17
// speedup vs baseline: 6.0446x; 1.8068x over previous
#include <cuda_runtime.h>
#include <cuda_fp16.h>
#include <cstdint>
#include <math.h>

// ---------------------------------------------------------------------------
// Problem constants
// ---------------------------------------------------------------------------
#define T_TOK   8192
#define HID     2048
#define NH      16
#define HD      128
#define INNER   2048          // NH*HD
#define QKV_W   6144          // 3*INNER
#define NCHUNK  64            // T/128
#define CHUNK   128
#define EPS     1e-5f
#define QSCALE  0.08838834764831845f   // 128^-0.5

// ---------------------------------------------------------------------------
// Device scratch (static globals: allocation-free rule)
// ---------------------------------------------------------------------------
__device__ float  g_qkv [T_TOK * QKV_W];           // fp32 silu(x@Wqkv)
__device__ float  g_gate[T_TOK * INNER];           // fp32 x@Wg
__device__ float  g_o   [T_TOK * INNER];           // fp32 attention output
__device__ float  g_kvp [NCHUNK * NH * HD * HD];   // fp32 per-chunk KVt [e][d]
__device__ __half g_S   [NCHUNK * NH * HD * HD];   // fp16 exclusive prefix St [e][d]
__device__ __half g_xh    [T_TOK * HID];           // fp16 x
__device__ __half g_gh    [T_TOK * INNER];         // fp16 gated value (A of final GEMM)
__device__ __half g_WqkvTh[QKV_W * HID];           // fp16 transposed weights [N,K]
__device__ __half g_WgTh  [INNER * HID];
__device__ __half g_WoTh  [HID * INNER];
__device__ __half g_qh [NH * T_TOK * HD];          // fp16 q, layout [h][t][d]
__device__ __half g_kh [NH * T_TOK * HD];
__device__ __half g_vh [NH * T_TOK * HD];

// ---------------------------------------------------------------------------
// PTX helpers (sm_75+/sm_80+, no arch-specific gating)
// ---------------------------------------------------------------------------
__device__ __forceinline__ uint32_t smem_u32(const void* p) {
    uint32_t a;
    asm("{ .reg .u64 t; cvta.to.shared.u64 t, %1; cvt.u32.u64 %0, t; }" : "=r"(a) : "l"(p));
    return a;
}
#define CP_ASYNC16(sdst, gsrc) \
    asm volatile("cp.async.cg.shared.global [%0], [%1], 16;" :: "r"(sdst), "l"(gsrc) : "memory")
#define CP_COMMIT() asm volatile("cp.async.commit_group;" ::: "memory")
#define CP_WAIT2()  asm volatile("cp.async.wait_group 2;" ::: "memory")
#define CP_WAIT0()  asm volatile("cp.async.wait_group 0;" ::: "memory")

__device__ __forceinline__ void ldsm4(uint32_t* d, uint32_t addr) {
    asm volatile("ldmatrix.sync.aligned.m8n8.x4.shared.b16 {%0,%1,%2,%3}, [%4];"
                 : "=r"(d[0]), "=r"(d[1]), "=r"(d[2]), "=r"(d[3]) : "r"(addr));
}
__device__ __forceinline__ void ldsm4t(uint32_t* d, uint32_t addr) {
    asm volatile("ldmatrix.sync.aligned.m8n8.x4.trans.shared.b16 {%0,%1,%2,%3}, [%4];"
                 : "=r"(d[0]), "=r"(d[1]), "=r"(d[2]), "=r"(d[3]) : "r"(addr));
}
__device__ __forceinline__ void mma_f16(float* c, const uint32_t* a, const uint32_t* b) {
    asm volatile(
        "mma.sync.aligned.m16n8k16.row.col.f32.f16.f16.f32 "
        "{%0,%1,%2,%3}, {%4,%5,%6,%7}, {%8,%9}, {%0,%1,%2,%3};"
        : "+f"(c[0]), "+f"(c[1]), "+f"(c[2]), "+f"(c[3])
        : "r"(a[0]), "r"(a[1]), "r"(a[2]), "r"(a[3]), "r"(b[0]), "r"(b[1]));
}

// ---------------------------------------------------------------------------
// Prep: x -> fp16 ; weights -> transposed fp16 [N,K]
// ---------------------------------------------------------------------------
__global__ __launch_bounds__(256)
void f2h_kernel(const float* __restrict__ in, __half* __restrict__ out)
{
    const long i = ((long)blockIdx.x * 256 + threadIdx.x) * 4;
    float4 v = *(const float4*)(in + i);
    __half2 lo = __floats2half2_rn(v.x, v.y);
    __half2 hi = __floats2half2_rn(v.z, v.w);
    *(__half2*)(out + i)     = lo;
    *(__half2*)(out + i + 2) = hi;
}

__global__ void transpose_h_kernel(const float* __restrict__ W, __half* __restrict__ Wt,
                                   int K, int N)
{
    __shared__ float tile[32][33];
    const int bx = blockIdx.x * 32;   // n
    const int by = blockIdx.y * 32;   // k
    const int x = threadIdx.x, y = threadIdx.y;   // (32, 8)
    #pragma unroll
    for (int i = 0; i < 32; i += 8)
        tile[y + i][x] = W[(long)(by + y + i) * N + bx + x];
    __syncthreads();
    #pragma unroll
    for (int i = 0; i < 32; i += 8)
        Wt[(long)(bx + y + i) * K + by + x] = __float2half_rn(tile[x][y + i]);
}

// ---------------------------------------------------------------------------
// FP16 GEMM via mma.m16n8k16 + ldmatrix (swizzled smem).
// C[M,N]fp32 = act(A[M,K]h @ Bt[N,K]h^T).  K = 2048.
// 128x256 tile, BK=64, 256 threads (8 warps 2x4), warp tile 64x64.
// 4-stage cp.async, one barrier per k-step. ACT: 0=none, 1=silu
// Tile rows = 64 half = 128B = 8 chunks of 16B; chunk' = ch ^ (row&7)
// ---------------------------------------------------------------------------
#define BM 128
#define BN 256
#define BK 64
#define STAGE_A_B 16384               // 128 rows * 128 B
#define STAGE_B_B 32768               // 256 rows * 128 B
#define OFF_SA(s) ((s) * STAGE_A_B)
#define OFF_SB(s) (4 * STAGE_A_B + (s) * STAGE_B_B)
#define GSM_BYTES (4 * STAGE_A_B + 4 * STAGE_B_B)   // 196608
#define CS_LDM 264

__device__ __forceinline__ void g_load_stage(uint32_t sbase, int slot, int tid,
                                             const __half* __restrict__ ag,
                                             const __half* __restrict__ bg)
{
    uint32_t sa = sbase + OFF_SA(slot);
    #pragma unroll
    for (int r = 0; r < 4; r++) {
        int idx = r * 256 + tid;
        int row = idx >> 3, ch = idx & 7;
        CP_ASYNC16(sa + (uint32_t)(row * 128 + ((ch ^ (row & 7)) << 4)),
                   ag + (long)row * HID + ch * 8);
    }
    uint32_t sb = sbase + OFF_SB(slot);
    #pragma unroll
    for (int r = 0; r < 8; r++) {
        int idx = r * 256 + tid;
        int row = idx >> 3, ch = idx & 7;
        CP_ASYNC16(sb + (uint32_t)(row * 128 + ((ch ^ (row & 7)) << 4)),
                   bg + (long)row * HID + ch * 8);
    }
}

template<int ACT>
__global__ __launch_bounds__(256, 1)
void mma_gemm(const __half* __restrict__ A, const __half* __restrict__ Bt,
              float* __restrict__ C, int M, int N)
{
    extern __shared__ float sm[];
    const uint32_t sbase = smem_u32(sm);
    const int tid  = threadIdx.x;
    const int wid  = tid >> 5, lane = tid & 31;
    const int wr   = wid >> 2;        // 0..1: 64-row block
    const int wc   = wid & 3;         // 0..3: 64-col block
    const long bm = (long)blockIdx.x * BM;
    const long bn = (long)blockIdx.y * BN;

    const __half* Ab = A  + bm * HID;
    const __half* Bb = Bt + bn * HID;

    const int r  = lane & 7;
    const int tl = lane >> 3;
    const int rowA = wr * 64 + ((tl & 1) << 3) + r;   // + mi*16
    const int cA   = tl >> 1;                          // + kk*2
    const int rowB = wc * 64 + ((tl >> 1) << 3) + r;  // + nb*16
    const int cB   = tl & 1;                           // + kk*2

    float acc[4][8][4];
    #pragma unroll
    for (int i = 0; i < 4; i++)
        #pragma unroll
        for (int j = 0; j < 8; j++)
            #pragma unroll
            for (int e = 0; e < 4; e++) acc[i][j][e] = 0.f;

    g_load_stage(sbase, 0, tid, Ab, Bb);                   CP_COMMIT();
    g_load_stage(sbase, 1, tid, Ab + BK, Bb + BK);         CP_COMMIT();
    g_load_stage(sbase, 2, tid, Ab + 2 * BK, Bb + 2 * BK); CP_COMMIT();

    const int nk = HID / BK;          // 32
    for (int ks = 0; ks < nk; ks++) {
        const int slot = ks & 3;
        CP_WAIT2();
        __syncthreads();
        if (ks + 3 < nk)
            g_load_stage(sbase, (ks + 3) & 3, tid, Ab + (long)(ks + 3) * BK,
                         Bb + (long)(ks + 3) * BK);
        CP_COMMIT();

        const uint32_t sa = sbase + OFF_SA(slot);
        const uint32_t sb = sbase + OFF_SB(slot);

        #pragma unroll
        for (int kk = 0; kk < 4; kk++) {          // k16 steps within BK=64
            uint32_t af[4][4], bf[4][4];
            #pragma unroll
            for (int mi = 0; mi < 4; mi++) {
                int row = rowA + mi * 16;
                ldsm4(af[mi], sa + (uint32_t)(row * 128
                                  + (((kk * 2 + cA) ^ (row & 7)) << 4)));
            }
            #pragma unroll
            for (int nb = 0; nb < 4; nb++) {
                int row = rowB + nb * 16;
                ldsm4(bf[nb], sb + (uint32_t)(row * 128
                                  + (((kk * 2 + cB) ^ (row & 7)) << 4)));
            }
            #pragma unroll
            for (int mi = 0; mi < 4; mi++)
                #pragma unroll
                for (int nj = 0; nj < 8; nj++)
                    mma_f16(acc[mi][nj], af[mi], &bf[nj >> 1][(nj & 1) * 2]);
        }
    }

    // epilogue: acc -> smem -> act -> coalesced global float4
    __syncthreads();
    const int er = lane >> 2, ec = (lane & 3) * 2;
    #pragma unroll
    for (int mi = 0; mi < 4; mi++)
        #pragma unroll
        for (int nj = 0; nj < 8; nj++) {
            int row0 = wr * 64 + mi * 16 + er;
            int col0 = wc * 64 + nj * 8 + ec;
            sm[row0 * CS_LDM + col0]       = acc[mi][nj][0];
            sm[row0 * CS_LDM + col0 + 1]   = acc[mi][nj][1];
            sm[(row0 + 8) * CS_LDM + col0]     = acc[mi][nj][2];
            sm[(row0 + 8) * CS_LDM + col0 + 1] = acc[mi][nj][3];
        }
    __syncthreads();

    #pragma unroll
    for (int p = 0; p < 32; p++) {
        int fid = p * 256 + tid;
        int row = fid >> 6;
        int col = (fid & 63) << 2;
        float4 v = *(const float4*)&sm[row * CS_LDM + col];
        if (ACT == 1) {
            v.x = v.x / (1.f + expf(-v.x));
            v.y = v.y / (1.f + expf(-v.y));
            v.z = v.z / (1.f + expf(-v.z));
            v.w = v.w / (1.f + expf(-v.w));
        }
        *(float4*)(C + (bm + row) * N + bn + col) = v;
    }
}

// ---------------------------------------------------------------------------
// Per-(token, head) RMSNorm + RoPE (+ q scale); reads fp32 qkv,
// writes fp16 q/k/v into per-head packed layout [h][t][d].
// ---------------------------------------------------------------------------
__global__ void qk_rope_kernel(const float* __restrict__ qkv,
                               const int* __restrict__ pos,
                               const float* __restrict__ qw,
                               const float* __restrict__ kw,
                               __half* __restrict__ qh, __half* __restrict__ kh,
                               __half* __restrict__ vh)
{
    const int t = blockIdx.x, h = blockIdx.y;
    const int j = threadIdx.x;              // 0..63
    const float* qp = qkv + (long)t * QKV_W + h * HD;
    const float* kp = qp + INNER;
    const float* vp = kp + INNER;
    const long ob = ((long)h * T_TOK + t) * HD;

    float q1 = qp[j], q2 = qp[j + 64];
    float k1 = kp[j], k2 = kp[j + 64];

    float sq = q1*q1 + q2*q2;
    float sk = k1*k1 + k2*k2;
    #pragma unroll
    for (int o = 16; o; o >>= 1) {
        sq += __shfl_xor_sync(0xffffffffu, sq, o);
        sk += __shfl_xor_sync(0xffffffffu, sk, o);
    }
    __shared__ float red[4];
    const int w = j >> 5, lane = j & 31;
    if (lane == 0) { red[w] = sq; red[2 + w] = sk; }
    __syncthreads();
    const float rq = rsqrtf((red[0] + red[1]) * (1.f / 128.f) + EPS);
    const float rk = rsqrtf((red[2] + red[3]) * (1.f / 128.f) + EPS);

    q1 = q1 * rq * qw[j]; q2 = q2 * rq * qw[j + 64];
    k1 = k1 * rk * kw[j]; k2 = k2 * rk * kw[j + 64];

    const float inv = powf(600000.0f, -(float)j * (1.0f / 64.0f));
    const float ang = (float)pos[t] * inv;
    float s, c;
    sincosf(ang, &s, &c);

    qh[ob + j]      = __float2half_rn((q1 * c - q2 * s) * QSCALE);
    qh[ob + j + 64] = __float2half_rn((q2 * c + q1 * s) * QSCALE);
    kh[ob + j]      = __float2half_rn(k1 * c - k2 * s);
    kh[ob + j + 64] = __float2half_rn(k2 * c + k1 * s);
    vh[ob + j]      = __float2half_rn(vp[j]);
    vh[ob + j + 64] = __float2half_rn(vp[j + 64]);
}

// ---------------------------------------------------------------------------
// fp16 tile smem addressing: rows 128 half = 256B = 16 chunks of 16B
// sw: chunk' = (ch & 8) | ((ch ^ row) & 7)
// ---------------------------------------------------------------------------
__device__ __forceinline__ uint32_t sw16(int row, int ch) {
    return (uint32_t)(row * 256 + (((ch & 8) | ((ch ^ row) & 7)) << 4));
}
#define TILE_HB 32768   // 128*128*2

__device__ __forceinline__ void load_tile_h(uint32_t sdst, int tid,
                                            const __half* __restrict__ g)
{
    #pragma unroll
    for (int it = 0; it < 8; it++) {
        int idx = it * 256 + tid;          // 0..2047
        int row = idx >> 4, ch = idx & 15;
        CP_ASYNC16(sdst + sw16(row, ch), g + row * HD + ch * 8);
    }
}

// ---------------------------------------------------------------------------
// Tensor-core per-(chunk,head) KV outer product (fp16 operands, fp32 out):
//   KVt[e][d] = sum_j v[j][e] * k[j][d]   (A = v^T via trans, B = k^T via trans)
// 8 warps (4x2): wr = e 32-block, wc = d 64-block.
// ---------------------------------------------------------------------------
__global__ __launch_bounds__(256, 1)
void kv_outer_mma(const __half* __restrict__ kh, const __half* __restrict__ vh,
                  float* __restrict__ KVt)
{
    extern __shared__ char smc[];
    const uint32_t sbase = smem_u32(smc);
    const uint32_t sV = sbase, sK = sbase + TILE_HB;

    const int c = blockIdx.x, h = blockIdx.y;
    const int t0 = c * CHUNK;
    const int tid = threadIdx.x, wid = tid >> 5, lane = tid & 31;
    const int wr = wid >> 1, wc = wid & 1;
    const int r = lane & 7, tl = lane >> 3;
    const int er = lane >> 2, ec = (lane & 3) * 2;

    const __half* kg = kh + ((long)h * T_TOK + t0) * HD;
    const __half* vg = vh + ((long)h * T_TOK + t0) * HD;
    load_tile_h(sV, tid, vg);
    load_tile_h(sK, tid, kg);
    CP_COMMIT(); CP_WAIT0();
    __syncthreads();

    float acc[2][8][4];
    #pragma unroll
    for (int i = 0; i < 2; i++)
        #pragma unroll
        for (int j = 0; j < 8; j++)
            #pragma unroll
            for (int e = 0; e < 4; e++) acc[i][j][e] = 0.f;

    #pragma unroll
    for (int kk = 0; kk < 8; kk++) {          // k16 over j
        uint32_t af[2][4], bf[4][4];
        #pragma unroll
        for (int mi = 0; mi < 2; mi++) {
            // A = v^T : trans load; rows j, chunk = e block
            int row = kk * 16 + ((tl >> 1) << 3) + r;
            int ch  = wr * 4 + mi * 2 + (tl & 1);
            ldsm4t(af[mi], sV + sw16(row, ch));
        }
        #pragma unroll
        for (int nb = 0; nb < 4; nb++) {
            // B = k^T : trans load; rows j, chunk = d block
            int row = kk * 16 + ((tl & 1) << 3) + r;
            int ch  = wc * 8 + nb * 2 + (tl >> 1);
            ldsm4t(bf[nb], sK + sw16(row, ch));
        }
        #pragma unroll
        for (int mi = 0; mi < 2; mi++)
            #pragma unroll
            for (int nj = 0; nj < 8; nj++)
                mma_f16(acc[mi][nj], af[mi], &bf[nj >> 1][(nj & 1) * 2]);
    }

    float* out = KVt + ((long)c * NH + h) * (HD * HD);
    #pragma unroll
    for (int mi = 0; mi < 2; mi++)
        #pragma unroll
        for (int nj = 0; nj < 8; nj++) {
            int e0 = wr * 32 + mi * 16 + er;
            int d0 = wc * 64 + nj * 8 + ec;
            *(float2*)(out + e0 * 128 + d0)       = make_float2(acc[mi][nj][0], acc[mi][nj][1]);
            *(float2*)(out + (e0 + 8) * 128 + d0) = make_float2(acc[mi][nj][2], acc[mi][nj][3]);
        }
}

// ---------------------------------------------------------------------------
// Exclusive prefix over chunks: fp32 accumulate, fp16 output
// ---------------------------------------------------------------------------
__global__ void prefix_kernel(const float* __restrict__ KV, __half* __restrict__ S)
{
    const int idx = blockIdx.x * 256 + threadIdx.x;
    float acc = 0.f;
    #pragma unroll 4
    for (int c = 0; c < NCHUNK; c++) {
        S[(long)c * (NH * HD * HD) + idx] = __float2half_rn(acc);
        acc += KV[(long)c * (NH * HD * HD) + idx];
    }
}

// ---------------------------------------------------------------------------
// Tensor-core per-(chunk,head) attention (fp16):
//   GEMM1: sc = q @ k^T (mask)    [A=q nat, B=k nat]
//   GEMM2: o  = sc @ v            [A=sc nat, B=v via trans]
//   GEMM3: o += q @ St^T          [A=q nat, B=St nat]
// smem: sQ | sK(->St) | sV | sC ; St load overlapped with GEMM2.
// 8 warps (4x2): wr = i 32-block, wc = j/e 64-block.
// ---------------------------------------------------------------------------
__global__ __launch_bounds__(256, 1)
void attn_chunk_mma(const __half* __restrict__ qh, const __half* __restrict__ kh,
                    const __half* __restrict__ vh, const __half* __restrict__ St,
                    float* __restrict__ O)
{
    extern __shared__ char smc[];
    const uint32_t sbase = smem_u32(smc);
    const uint32_t sQ = sbase, sK = sbase + TILE_HB,
                   sV = sbase + 2 * TILE_HB, sC = sbase + 3 * TILE_HB;

    const int c = blockIdx.x, h = blockIdx.y;
    const int t0 = c * CHUNK;
    const int tid = threadIdx.x, wid = tid >> 5, lane = tid & 31;
    const int wr = wid >> 1, wc = wid & 1;
    const int r = lane & 7, tl = lane >> 3;
    const int er = lane >> 2, ec = (lane & 3) * 2;

    load_tile_h(sQ, tid, qh + ((long)h * T_TOK + t0) * HD);
    load_tile_h(sK, tid, kh + ((long)h * T_TOK + t0) * HD);
    load_tile_h(sV, tid, vh + ((long)h * T_TOK + t0) * HD);
    CP_COMMIT(); CP_WAIT0();
    __syncthreads();

    // GEMM1: scores = q @ k^T
    float sc[2][8][4];
    #pragma unroll
    for (int i = 0; i < 2; i++)
        #pragma unroll
        for (int j = 0; j < 8; j++)
            #pragma unroll
            for (int e = 0; e < 4; e++) sc[i][j][e] = 0.f;

    #pragma unroll
    for (int kk = 0; kk < 8; kk++) {          // k16 over d
        uint32_t af[2][4], bf[4][4];
        #pragma unroll
        for (int mi = 0; mi < 2; mi++) {
            int row = wr * 32 + mi * 16 + ((tl & 1) << 3) + r;
            ldsm4(af[mi], sQ + sw16(row, kk * 2 + (tl >> 1)));
        }
        #pragma unroll
        for (int nb = 0; nb < 4; nb++) {
            int row = wc * 64 + nb * 16 + ((tl >> 1) << 3) + r;
            ldsm4(bf[nb], sK + sw16(row, kk * 2 + (tl & 1)));
        }
        #pragma unroll
        for (int mi = 0; mi < 2; mi++)
            #pragma unroll
            for (int nj = 0; nj < 8; nj++)
                mma_f16(sc[mi][nj], af[mi], &bf[nj >> 1][(nj & 1) * 2]);
    }
    __syncthreads();            // all warps done reading sK

    // overlap: start loading St into sK
    load_tile_h(sK, tid, St + ((long)c * NH + h) * (HD * HD));
    CP_COMMIT();

    // masked scores -> sC (half2 stores)
    #pragma unroll
    for (int mi = 0; mi < 2; mi++)
        #pragma unroll
        for (int nj = 0; nj < 8; nj++) {
            int i0 = wr * 32 + mi * 16 + er;
            int j0 = wc * 64 + nj * 8 + ec;
            float l0 = (i0     >= j0    ) ? sc[mi][nj][0] : 0.f;
            float l1 = (i0     >= j0 + 1) ? sc[mi][nj][1] : 0.f;
            float h0 = (i0 + 8 >= j0    ) ? sc[mi][nj][2] : 0.f;
            float h1 = (i0 + 8 >= j0 + 1) ? sc[mi][nj][3] : 0.f;
            *(__half2*)(smc + 3 * TILE_HB + sw16(i0, j0 >> 3) + (j0 & 7) * 2)
                = __floats2half2_rn(l0, l1);
            *(__half2*)(smc + 3 * TILE_HB + sw16(i0 + 8, j0 >> 3) + (j0 & 7) * 2)
                = __floats2half2_rn(h0, h1);
        }
    __syncthreads();

    // GEMM2: o = scores @ v   (B = v[j][e] via trans)
    float o[2][8][4];
    #pragma unroll
    for (int i = 0; i < 2; i++)
        #pragma unroll
        for (int j = 0; j < 8; j++)
            #pragma unroll
            for (int e = 0; e < 4; e++) o[i][j][e] = 0.f;

    #pragma unroll
    for (int kk = 0; kk < 8; kk++) {          // k16 over j
        uint32_t af[2][4], bf[4][4];
        #pragma unroll
        for (int mi = 0; mi < 2; mi++) {
            int row = wr * 32 + mi * 16 + ((tl & 1) << 3) + r;
            ldsm4(af[mi], sC + sw16(row, kk * 2 + (tl >> 1)));
        }
        #pragma unroll
        for (int nb = 0; nb < 4; nb++) {
            int row = kk * 16 + ((tl & 1) << 3) + r;
            int ch  = wc * 8 + nb * 2 + (tl >> 1);
            ldsm4t(bf[nb], sV + sw16(row, ch));
        }
        #pragma unroll
        for (int mi = 0; mi < 2; mi++)
            #pragma unroll
            for (int nj = 0; nj < 8; nj++)
                mma_f16(o[mi][nj], af[mi], &bf[nj >> 1][(nj & 1) * 2]);
    }
    CP_WAIT0();
    __syncthreads();            // St resident in sK

    // GEMM3: o += q @ St^T   (B = St[e][d] nat.)
    #pragma unroll
    for (int kk = 0; kk < 8; kk++) {          // k16 over d
        uint32_t af[2][4], bf[4][4];
        #pragma unroll
        for (int mi = 0; mi < 2; mi++) {
            int row = wr * 32 + mi * 16 + ((tl & 1) << 3) + r;
            ldsm4(af[mi], sQ + sw16(row, kk * 2 + (tl >> 1)));
        }
        #pragma unroll
        for (int nb = 0; nb < 4; nb++) {
            int row = wc * 64 + nb * 16 + ((tl >> 1) << 3) + r;
            ldsm4(bf[nb], sK + sw16(row, kk * 2 + (tl & 1)));
        }
        #pragma unroll
        for (int mi = 0; mi < 2; mi++)
            #pragma unroll
            for (int nj = 0; nj < 8; nj++)
                mma_f16(o[mi][nj], af[mi], &bf[nj >> 1][(nj & 1) * 2]);
    }

    // write O[t][h*128 + e] (fp32)
    #pragma unroll
    for (int mi = 0; mi < 2; mi++)
        #pragma unroll
        for (int nj = 0; nj < 8; nj++) {
            int i0 = wr * 32 + mi * 16 + er;
            int j0 = wc * 64 + nj * 8 + ec;
            *(float2*)(O + (long)(t0 + i0) * INNER + h * HD + j0)
                = make_float2(o[mi][nj][0], o[mi][nj][1]);
            *(float2*)(O + (long)(t0 + i0 + 8) * INNER + h * HD + j0)
                = make_float2(o[mi][nj][2], o[mi][nj][3]);
        }
}

// ---------------------------------------------------------------------------
// Per-token g-norm + sigmoid gate: writes fp16 A-operand of the final GEMM.
// ---------------------------------------------------------------------------
__global__ __launch_bounds__(256)
void gate_norm_kernel(const float* __restrict__ O, const float* __restrict__ G,
                      const float* __restrict__ gw, __half* __restrict__ GH)
{
    const int t = blockIdx.x;
    const int tid = threadIdx.x;
    const float* orow = O + (long)t * INNER;
    const float* grow = G + (long)t * INNER;
    __half* gh = GH + (long)t * INNER;

    float4 o0 = *(const float4*)(orow + tid * 4);
    float4 o1 = *(const float4*)(orow + 1024 + tid * 4);

    float s = o0.x*o0.x + o0.y*o0.y + o0.z*o0.z + o0.w*o0.w
            + o1.x*o1.x + o1.y*o1.y + o1.z*o1.z + o1.w*o1.w;
    #pragma unroll
    for (int o = 16; o; o >>= 1) s += __shfl_xor_sync(0xffffffffu, s, o);
    __shared__ float red[8];
    if ((tid & 31) == 0) red[tid >> 5] = s;
    __syncthreads();
    float tot = 0.f;
    #pragma unroll
    for (int w = 0; w < 8; w++) tot += red[w];
    const float rs = rsqrtf(tot * (1.f / 2048.f) + EPS);

    float4 g0 = *(const float4*)(grow + tid * 4);
    float4 g1 = *(const float4*)(grow + 1024 + tid * 4);
    float4 w0 = *(const float4*)(gw + tid * 4);
    float4 w1 = *(const float4*)(gw + 1024 + tid * 4);

    __half2 a = __floats2half2_rn((1.f / (1.f + expf(-g0.x))) * o0.x * rs * w0.x,
                                  (1.f / (1.f + expf(-g0.y))) * o0.y * rs * w0.y);
    __half2 b = __floats2half2_rn((1.f / (1.f + expf(-g0.z))) * o0.z * rs * w0.z,
                                  (1.f / (1.f + expf(-g0.w))) * o0.w * rs * w0.w);
    __half2 cc = __floats2half2_rn((1.f / (1.f + expf(-g1.x))) * o1.x * rs * w1.x,
                                   (1.f / (1.f + expf(-g1.y))) * o1.y * rs * w1.y);
    __half2 d = __floats2half2_rn((1.f / (1.f + expf(-g1.z))) * o1.z * rs * w1.z,
                                  (1.f / (1.f + expf(-g1.w))) * o1.w * rs * w1.w);
    *(__half2*)(gh + tid * 4)            = a;
    *(__half2*)(gh + tid * 4 + 2)        = b;
    *(__half2*)(gh + 1024 + tid * 4)     = cc;
    *(__half2*)(gh + 1024 + tid * 4 + 2) = d;
}

// ---------------------------------------------------------------------------
// Launch
// ---------------------------------------------------------------------------
extern "C" void kernel_launch(void* const* d_in, const int* in_sizes, int n_in,
                              void* d_out, int out_size)
{
    const float* x    = (const float*)d_in[0];   // [8192, 2048]
    const int*   pos  = (const int*)  d_in[1];   // [8192]
    const float* Wqkv = (const float*)d_in[2];   // [2048, 6144]
    const float* qw   = (const float*)d_in[3];   // [128]
    const float* kw   = (const float*)d_in[4];   // [128]
    const float* Wg   = (const float*)d_in[5];   // [2048, 2048]
    const float* gw   = (const float*)d_in[6];   // [2048]
    const float* Wo   = (const float*)d_in[7];   // [2048, 2048]
    float* out = (float*)d_out;                  // [8192, 2048]

    float*  qkv;  cudaGetSymbolAddress((void**)&qkv,  g_qkv);
    float*  gate; cudaGetSymbolAddress((void**)&gate, g_gate);
    float*  o;    cudaGetSymbolAddress((void**)&o,    g_o);
    float*  kvp;  cudaGetSymbolAddress((void**)&kvp,  g_kvp);
    __half* S;    cudaGetSymbolAddress((void**)&S,    g_S);
    __half* xh;    cudaGetSymbolAddress((void**)&xh,    g_xh);
    __half* gh;    cudaGetSymbolAddress((void**)&gh,    g_gh);
    __half* WqkvTh; cudaGetSymbolAddress((void**)&WqkvTh, g_WqkvTh);
    __half* WgTh;   cudaGetSymbolAddress((void**)&WgTh,   g_WgTh);
    __half* WoTh;   cudaGetSymbolAddress((void**)&WoTh,   g_WoTh);
    __half* qh;   cudaGetSymbolAddress((void**)&qh,   g_qh);
    __half* kh;   cudaGetSymbolAddress((void**)&kh,   g_kh);
    __half* vh;   cudaGetSymbolAddress((void**)&vh,   g_vh);

    cudaFuncSetAttribute(mma_gemm<0>,
                         cudaFuncAttributeMaxDynamicSharedMemorySize, GSM_BYTES);
    cudaFuncSetAttribute(mma_gemm<1>,
                         cudaFuncAttributeMaxDynamicSharedMemorySize, GSM_BYTES);
    cudaFuncSetAttribute(kv_outer_mma,
                         cudaFuncAttributeMaxDynamicSharedMemorySize, 2 * TILE_HB);
    cudaFuncSetAttribute(attn_chunk_mma,
                         cudaFuncAttributeMaxDynamicSharedMemorySize, 4 * TILE_HB);

    // 0. prep: x -> fp16; weights -> transposed fp16 [N,K]
    f2h_kernel<<<(T_TOK * (long)HID) / 1024, 256>>>(x, xh);
    transpose_h_kernel<<<dim3(QKV_W / 32, HID / 32), dim3(32, 8)>>>(Wqkv, WqkvTh, HID, QKV_W);
    transpose_h_kernel<<<dim3(INNER / 32, HID / 32), dim3(32, 8)>>>(Wg, WgTh, HID, INNER);
    transpose_h_kernel<<<dim3(HID / 32, INNER / 32), dim3(32, 8)>>>(Wo, WoTh, INNER, HID);

    // 1. qkv = silu(x @ Wqkv)
    mma_gemm<1><<<dim3(T_TOK / BM, QKV_W / BN), 256, GSM_BYTES>>>(xh, WqkvTh, qkv, T_TOK, QKV_W);
    // 2. gate = x @ Wg
    mma_gemm<0><<<dim3(T_TOK / BM, INNER / BN), 256, GSM_BYTES>>>(xh, WgTh, gate, T_TOK, INNER);
    // 3. per-head rmsnorm + rope (+ q scale) -> fp16 per-head q/k/v
    qk_rope_kernel<<<dim3(T_TOK, NH), 64>>>(qkv, pos, qw, kw, qh, kh, vh);
    // 4. per-chunk KVt outer products (fp16 tensor cores)
    kv_outer_mma<<<dim3(NCHUNK, NH), 256, 2 * TILE_HB>>>(kh, vh, kvp);
    // 5. exclusive prefix over chunks -> fp16 state St
    prefix_kernel<<<(NH * HD * HD) / 256, 256>>>(kvp, S);
    // 6. intra-chunk masked attention + inter-chunk q@S (fp16 tensor cores)
    attn_chunk_mma<<<dim3(NCHUNK, NH), 256, 4 * TILE_HB>>>(qh, kh, vh, S, o);
    // 7. g-norm + sigmoid gating -> fp16 gated value
    gate_norm_kernel<<<T_TOK, 256>>>(o, gate, gw, gh);
    // 8. out = gated @ Wo
    mma_gemm<0><<<dim3(T_TOK / BM, HID / BN), 256, GSM_BYTES>>>(gh, WoTh, out, T_TOK, HID);
}